// round 1
// baseline (speedup 1.0000x reference)
#include <cuda_runtime.h>
#include <math.h>

#define BATCH 2048
#define CTRLN 512
#define MEMN  1024
#define VDIM  64

// ---------------- scratch (device globals: allocation-free) ----------------
__device__ float g_inp[BATCH * 128];        // [x | read_prev]
__device__ float g_gates[BATCH * 2048];
__device__ float g_h[BATCH * CTRLN];
__device__ float g_logr[BATCH * MEMN];
__device__ float g_logw[BATCH * MEMN];
__device__ float g_readw[BATCH * MEMN];
__device__ float g_rw[BATCH * MEMN];        // read_w * write_w
__device__ float g_s[BATCH];                // sum_m read_w*write_w
__device__ float g_erase[BATCH * VDIM];
__device__ float g_add[BATCH * VDIM];
__device__ float g_readnew[BATCH * VDIM];

// ---------------- big NT GEMM: C[M,N] = A@W^T (+bias1+bias2), 2 K-phases ----
// BM=128, BN=128, BK=16, 256 threads, 8x8 per thread
__global__ __launch_bounds__(256) void gemm_nt_big(
    const float* __restrict__ A1, int lda1, int K1,
    const float* __restrict__ A2, int lda2, int K2,
    const float* __restrict__ W1, int ldw1,
    const float* __restrict__ W2, int ldw2,
    const float* __restrict__ bias1, const float* __restrict__ bias2,
    float* __restrict__ C, int ldc)
{
    __shared__ float As[16][128];
    __shared__ float Ws[16][128];
    const int bm = blockIdx.y * 128;
    const int bn = blockIdx.x * 128;
    const int tid = threadIdx.x;
    const int ty = tid >> 4, tx = tid & 15;
    float acc[8][8] = {};

    #pragma unroll 1
    for (int ph = 0; ph < 2; ph++) {
        const float* A = ph ? A2 : A1;
        const float* W = ph ? W2 : W1;
        const int lda = ph ? lda2 : lda1;
        const int ldw = ph ? ldw2 : ldw1;
        const int K   = ph ? K2   : K1;
        if (A == nullptr || K == 0) continue;
        for (int k0 = 0; k0 < K; k0 += 16) {
            #pragma unroll
            for (int l = 0; l < 2; l++) {
                int idx = tid + l * 256;          // 0..511 float4 slots
                int row = idx >> 2;
                int kc  = (idx & 3) * 4;
                float4 v = *(const float4*)&A[(size_t)(bm + row) * lda + k0 + kc];
                As[kc + 0][row] = v.x; As[kc + 1][row] = v.y;
                As[kc + 2][row] = v.z; As[kc + 3][row] = v.w;
            }
            #pragma unroll
            for (int l = 0; l < 2; l++) {
                int idx = tid + l * 256;
                int row = idx >> 2;
                int kc  = (idx & 3) * 4;
                float4 v = *(const float4*)&W[(size_t)(bn + row) * ldw + k0 + kc];
                Ws[kc + 0][row] = v.x; Ws[kc + 1][row] = v.y;
                Ws[kc + 2][row] = v.z; Ws[kc + 3][row] = v.w;
            }
            __syncthreads();
            #pragma unroll
            for (int kk = 0; kk < 16; kk++) {
                float a[8], b[8];
                *(float4*)&a[0] = *(const float4*)&As[kk][ty * 8];
                *(float4*)&a[4] = *(const float4*)&As[kk][ty * 8 + 4];
                *(float4*)&b[0] = *(const float4*)&Ws[kk][tx * 8];
                *(float4*)&b[4] = *(const float4*)&Ws[kk][tx * 8 + 4];
                #pragma unroll
                for (int i = 0; i < 8; i++)
                    #pragma unroll
                    for (int j = 0; j < 8; j++)
                        acc[i][j] += a[i] * b[j];
            }
            __syncthreads();
        }
    }
    #pragma unroll
    for (int i = 0; i < 8; i++) {
        int r = bm + ty * 8 + i;
        #pragma unroll
        for (int j = 0; j < 8; j++) {
            int c = bn + tx * 8 + j;
            float v = acc[i][j];
            if (bias1) v += bias1[c];
            if (bias2) v += bias2[c];
            C[(size_t)r * ldc + c] = v;
        }
    }
}

// ---------------- small NT GEMM: N=64 fixed, BM=32, BK=32, 256 threads -----
// act: 0=none 1=sigmoid 2=tanh
__global__ __launch_bounds__(256) void gemm_nt_small(
    const float* __restrict__ A1, int lda1, int K1,
    const float* __restrict__ A2, int lda2, int K2,
    const float* __restrict__ W1, int ldw1,
    const float* __restrict__ W2, int ldw2,
    const float* __restrict__ bias, int act,
    float* __restrict__ C, int ldc)
{
    __shared__ float As[32][33];
    __shared__ float Ws[32][65];
    const int bm = blockIdx.x * 32;
    const int tid = threadIdx.x;
    const int ty = tid >> 4, tx = tid & 15;
    float acc[2][4] = {};

    #pragma unroll 1
    for (int ph = 0; ph < 2; ph++) {
        const float* A = ph ? A2 : A1;
        const float* W = ph ? W2 : W1;
        const int lda = ph ? lda2 : lda1;
        const int ldw = ph ? ldw2 : ldw1;
        const int K   = ph ? K2   : K1;
        if (A == nullptr || K == 0) continue;
        for (int k0 = 0; k0 < K; k0 += 32) {
            {   // A tile 32x32
                int row = tid >> 3;
                int kc  = (tid & 7) * 4;
                float4 v = *(const float4*)&A[(size_t)(bm + row) * lda + k0 + kc];
                As[kc + 0][row] = v.x; As[kc + 1][row] = v.y;
                As[kc + 2][row] = v.z; As[kc + 3][row] = v.w;
            }
            #pragma unroll
            for (int l = 0; l < 2; l++) {  // W tile 64x32
                int idx = tid + l * 256;
                int row = idx >> 3;
                int kc  = (idx & 7) * 4;
                float4 v = *(const float4*)&W[(size_t)row * ldw + k0 + kc];
                Ws[kc + 0][row] = v.x; Ws[kc + 1][row] = v.y;
                Ws[kc + 2][row] = v.z; Ws[kc + 3][row] = v.w;
            }
            __syncthreads();
            #pragma unroll
            for (int kk = 0; kk < 32; kk++) {
                float a0 = As[kk][ty * 2], a1 = As[kk][ty * 2 + 1];
                float b0 = Ws[kk][tx * 4], b1 = Ws[kk][tx * 4 + 1];
                float b2 = Ws[kk][tx * 4 + 2], b3 = Ws[kk][tx * 4 + 3];
                acc[0][0] += a0 * b0; acc[0][1] += a0 * b1;
                acc[0][2] += a0 * b2; acc[0][3] += a0 * b3;
                acc[1][0] += a1 * b0; acc[1][1] += a1 * b1;
                acc[1][2] += a1 * b2; acc[1][3] += a1 * b3;
            }
            __syncthreads();
        }
    }
    #pragma unroll
    for (int i = 0; i < 2; i++) {
        int r = bm + ty * 2 + i;
        #pragma unroll
        for (int j = 0; j < 4; j++) {
            int c = tx * 4 + j;
            float v = acc[i][j];
            if (bias) v += bias[c];
            if (act == 1) v = 1.0f / (1.0f + expf(-v));
            else if (act == 2) v = tanhf(v);
            C[(size_t)r * ldc + c] = v;
        }
    }
}

// ---------------- NN GEMM vs memory [1024,64], dual-A, fused readnew -------
// BM=32, N=64, BK=32, 256 threads. lda hardcoded to 1024.
// mode 0: C[(bm+r)*ldc + coloff + c] = acc1
// mode 1: readnew = acc1 - erase*acc2 + add*s
__global__ __launch_bounds__(256) void gemm_nn_dual(
    const float* __restrict__ A1, const float* __restrict__ A2,
    const float* __restrict__ Bm,
    float* __restrict__ C, int ldc, int coloff,
    const float* __restrict__ erase, const float* __restrict__ addv,
    const float* __restrict__ svec, int mode)
{
    __shared__ float As1[32][33];
    __shared__ float As2[32][33];
    __shared__ float Bs[32][65];
    const int bm = blockIdx.x * 32;
    const int tid = threadIdx.x;
    const int ty = tid >> 4, tx = tid & 15;
    const bool dual = (A2 != nullptr);
    float acc1[2][4] = {};
    float acc2[2][4] = {};

    for (int k0 = 0; k0 < MEMN; k0 += 32) {
        {   int row = tid >> 3;
            int kc  = (tid & 7) * 4;
            float4 v = *(const float4*)&A1[(size_t)(bm + row) * MEMN + k0 + kc];
            As1[kc + 0][row] = v.x; As1[kc + 1][row] = v.y;
            As1[kc + 2][row] = v.z; As1[kc + 3][row] = v.w;
            if (dual) {
                float4 u = *(const float4*)&A2[(size_t)(bm + row) * MEMN + k0 + kc];
                As2[kc + 0][row] = u.x; As2[kc + 1][row] = u.y;
                As2[kc + 2][row] = u.z; As2[kc + 3][row] = u.w;
            }
        }
        #pragma unroll
        for (int l = 0; l < 2; l++) {   // memory tile: [32 k][64 v]
            int idx = tid + l * 256;
            int row = idx >> 4;
            int col = (idx & 15) * 4;
            float4 v = *(const float4*)&Bm[(size_t)(k0 + row) * 64 + col];
            Bs[row][col + 0] = v.x; Bs[row][col + 1] = v.y;
            Bs[row][col + 2] = v.z; Bs[row][col + 3] = v.w;
        }
        __syncthreads();
        #pragma unroll
        for (int kk = 0; kk < 32; kk++) {
            float b0 = Bs[kk][tx * 4], b1 = Bs[kk][tx * 4 + 1];
            float b2 = Bs[kk][tx * 4 + 2], b3 = Bs[kk][tx * 4 + 3];
            float a0 = As1[kk][ty * 2], a1 = As1[kk][ty * 2 + 1];
            acc1[0][0] += a0 * b0; acc1[0][1] += a0 * b1;
            acc1[0][2] += a0 * b2; acc1[0][3] += a0 * b3;
            acc1[1][0] += a1 * b0; acc1[1][1] += a1 * b1;
            acc1[1][2] += a1 * b2; acc1[1][3] += a1 * b3;
            if (dual) {
                float c0 = As2[kk][ty * 2], c1 = As2[kk][ty * 2 + 1];
                acc2[0][0] += c0 * b0; acc2[0][1] += c0 * b1;
                acc2[0][2] += c0 * b2; acc2[0][3] += c0 * b3;
                acc2[1][0] += c1 * b0; acc2[1][1] += c1 * b1;
                acc2[1][2] += c1 * b2; acc2[1][3] += c1 * b3;
            }
        }
        __syncthreads();
    }
    #pragma unroll
    for (int i = 0; i < 2; i++) {
        int r = bm + ty * 2 + i;
        #pragma unroll
        for (int j = 0; j < 4; j++) {
            int c = tx * 4 + j;
            if (mode == 0) {
                C[(size_t)r * ldc + coloff + c] = acc1[i][j];
            } else {
                float rn = acc1[i][j]
                         - erase[(size_t)r * 64 + c] * acc2[i][j]
                         + addv[(size_t)r * 64 + c] * svec[r];
                C[(size_t)r * 64 + c] = rn;
            }
        }
    }
}

// ---------------- elementwise / softmax ------------------------------------
__global__ void pack_x_kernel(const float* __restrict__ x, float* __restrict__ inp)
{
    int idx = blockIdx.x * blockDim.x + threadIdx.x;   // BATCH*64
    int b = idx >> 6, v = idx & 63;
    inp[(size_t)b * 128 + v] = x[idx];
}

__global__ void lstm_kernel(const float* __restrict__ gates,
                            const float* __restrict__ c_prev,
                            float* __restrict__ h)
{
    int idx = blockIdx.x * blockDim.x + threadIdx.x;   // BATCH*512
    int b = idx >> 9, j = idx & 511;
    const float* g = gates + (size_t)b * 2048;
    float gi = g[j], gf = g[512 + j], gg = g[1024 + j], go = g[1536 + j];
    float i = 1.0f / (1.0f + expf(-gi));
    float f = 1.0f / (1.0f + expf(-gf));
    float gv = tanhf(gg);
    float o = 1.0f / (1.0f + expf(-go));
    float c = f * c_prev[idx] + i * gv;
    h[idx] = o * tanhf(c);
}

__device__ __forceinline__ float reduce256(float v, float* sh, bool mx)
{
    int t = threadIdx.x;
    sh[t] = v;
    __syncthreads();
    #pragma unroll
    for (int s = 128; s > 0; s >>= 1) {
        if (t < s) sh[t] = mx ? fmaxf(sh[t], sh[t + s]) : (sh[t] + sh[t + s]);
        __syncthreads();
    }
    float r = sh[0];
    __syncthreads();
    return r;
}

__global__ void softmax_fuse_kernel(const float* __restrict__ lr,
                                    const float* __restrict__ lw,
                                    float* __restrict__ readw,
                                    float* __restrict__ rwprod,
                                    float* __restrict__ svec)
{
    __shared__ float sh[256];
    int b = blockIdx.x;
    int t = threadIdx.x;
    const float* r = lr + (size_t)b * MEMN;
    const float* w = lw + (size_t)b * MEMN;
    float vr[4], vw[4];
    float mr = -1e30f, mw = -1e30f;
    #pragma unroll
    for (int i = 0; i < 4; i++) {
        vr[i] = r[t + i * 256]; vw[i] = w[t + i * 256];
        mr = fmaxf(mr, vr[i]);  mw = fmaxf(mw, vw[i]);
    }
    mr = reduce256(mr, sh, true);
    mw = reduce256(mw, sh, true);
    float er[4], ew[4], sr = 0.f, sw = 0.f;
    #pragma unroll
    for (int i = 0; i < 4; i++) {
        er[i] = expf(vr[i] - mr); sr += er[i];
        ew[i] = expf(vw[i] - mw); sw += ew[i];
    }
    sr = reduce256(sr, sh, false);
    sw = reduce256(sw, sh, false);
    float inv_sr = 1.0f / sr, inv_sw = 1.0f / sw;
    float srw = 0.f;
    #pragma unroll
    for (int i = 0; i < 4; i++) {
        float a = er[i] * inv_sr;
        float p = a * (ew[i] * inv_sw);
        readw[(size_t)b * MEMN + t + i * 256] = a;
        rwprod[(size_t)b * MEMN + t + i * 256] = p;
        srw += p;
    }
    srw = reduce256(srw, sh, false);
    if (t == 0) svec[b] = srw;
}

// ---------------- launch ----------------------------------------------------
extern "C" void kernel_launch(void* const* d_in, const int* in_sizes, int n_in,
                              void* d_out, int out_size)
{
    const float* x       = (const float*)d_in[0];
    const float* h_prev  = (const float*)d_in[1];
    const float* c_prev  = (const float*)d_in[2];
    const float* rwp     = (const float*)d_in[3];
    const float* memory  = (const float*)d_in[4];
    const float* W_ih    = (const float*)d_in[5];
    const float* b_ih    = (const float*)d_in[6];
    const float* W_hh    = (const float*)d_in[7];
    const float* b_hh    = (const float*)d_in[8];
    const float* W_read  = (const float*)d_in[9];
    const float* b_read  = (const float*)d_in[10];
    const float* W_write = (const float*)d_in[11];
    const float* b_write = (const float*)d_in[12];
    const float* W_erase = (const float*)d_in[13];
    const float* b_erase = (const float*)d_in[14];
    const float* W_add   = (const float*)d_in[15];
    const float* b_add   = (const float*)d_in[16];
    const float* W_out   = (const float*)d_in[17];
    const float* b_out   = (const float*)d_in[18];
    float* out = (float*)d_out;

    float *inp, *gates, *h, *logr, *logw, *readw, *rw, *svec, *er, *ad, *rn;
    cudaGetSymbolAddress((void**)&inp,   g_inp);
    cudaGetSymbolAddress((void**)&gates, g_gates);
    cudaGetSymbolAddress((void**)&h,     g_h);
    cudaGetSymbolAddress((void**)&logr,  g_logr);
    cudaGetSymbolAddress((void**)&logw,  g_logw);
    cudaGetSymbolAddress((void**)&readw, g_readw);
    cudaGetSymbolAddress((void**)&rw,    g_rw);
    cudaGetSymbolAddress((void**)&svec,  g_s);
    cudaGetSymbolAddress((void**)&er,    g_erase);
    cudaGetSymbolAddress((void**)&ad,    g_add);
    cudaGetSymbolAddress((void**)&rn,    g_readnew);

    // 1) read_prev = read_weights_prev @ memory  -> inp[:, 64:128]
    gemm_nn_dual<<<BATCH / 32, 256>>>(rwp, nullptr, memory,
                                      inp, 128, 64,
                                      nullptr, nullptr, nullptr, 0);
    // 2) inp[:, 0:64] = x
    pack_x_kernel<<<(BATCH * 64) / 256, 256>>>(x, inp);

    // 3) gates = inp@W_ih^T + h_prev@W_hh^T + b_ih + b_hh   [B,2048]
    gemm_nt_big<<<dim3(2048 / 128, BATCH / 128), 256>>>(
        inp, 128, 128, h_prev, CTRLN, CTRLN,
        W_ih, 128, W_hh, CTRLN,
        b_ih, b_hh, gates, 2048);

    // 4) LSTM cell -> h
    lstm_kernel<<<(BATCH * CTRLN) / 256, 256>>>(gates, c_prev, h);

    // 5) read / write logits  [B,1024] each
    gemm_nt_big<<<dim3(MEMN / 128, BATCH / 128), 256>>>(
        h, CTRLN, CTRLN, nullptr, 0, 0,
        W_read, CTRLN, nullptr, 0,
        b_read, nullptr, logr, MEMN);
    gemm_nt_big<<<dim3(MEMN / 128, BATCH / 128), 256>>>(
        h, CTRLN, CTRLN, nullptr, 0, 0,
        W_write, CTRLN, nullptr, 0,
        b_write, nullptr, logw, MEMN);

    // 6) softmaxes + read_w*write_w + row sums
    softmax_fuse_kernel<<<BATCH, 256>>>(logr, logw, readw, rw, svec);

    // 7) erase = sigmoid(h@W_erase^T+b), add = tanh(h@W_add^T+b)
    gemm_nt_small<<<BATCH / 32, 256>>>(h, CTRLN, CTRLN, nullptr, 0, 0,
                                       W_erase, CTRLN, nullptr, 0,
                                       b_erase, 1, er, 64);
    gemm_nt_small<<<BATCH / 32, 256>>>(h, CTRLN, CTRLN, nullptr, 0, 0,
                                       W_add, CTRLN, nullptr, 0,
                                       b_add, 2, ad, 64);

    // 8) read_new = read_w@mem - erase*(rw@mem) + add*s   (fused einsum)
    gemm_nn_dual<<<BATCH / 32, 256>>>(readw, rw, memory,
                                      rn, 64, 0,
                                      er, ad, svec, 1);

    // 9) out = [h | read_new] @ W_out^T + b_out
    gemm_nt_small<<<BATCH / 32, 256>>>(h, CTRLN, CTRLN, rn, 64, 64,
                                       W_out, 576, W_out + 512, 576,
                                       b_out, 0, out, 64);
}

// round 3
// speedup vs baseline: 1.6004x; 1.6004x over previous
#include <cuda_runtime.h>
#include <math.h>
#include <stdint.h>

#define BATCH 2048
#define CTRLN 512
#define MEMN  1024
#define VDIM  64
#define KCAT  640   // 64 x + 64 read_prev + 512 h_prev

// ---------------- scratch (device globals: allocation-free) ----------------
__device__ float g_acat[BATCH * KCAT];      // tf32-rounded [x|read_prev|h_prev]
__device__ float g_wcat[2048 * KCAT];       // tf32-rounded [W_ih|W_hh]
__device__ float g_wrw[2048 * CTRLN];       // tf32-rounded [W_read;W_write]
__device__ float g_gates[BATCH * 2048];
__device__ float g_logits[BATCH * 2048];    // [read logits | write logits]
__device__ float g_h[BATCH * CTRLN];        // fp32 h
__device__ float g_ht32[BATCH * CTRLN];     // tf32-rounded h
__device__ float g_readw[BATCH * MEMN];
__device__ float g_rw[BATCH * MEMN];
__device__ float g_s[BATCH];
__device__ float g_erase[BATCH * VDIM];
__device__ float g_add[BATCH * VDIM];
__device__ float g_readnew[BATCH * VDIM];

// ---------------- helpers ----------------------------------------------------
__device__ __forceinline__ uint32_t smem_u32(const void* p) {
    uint32_t a;
    asm("{ .reg .u64 t; cvta.to.shared.u64 t, %1; cvt.u32.u64 %0, t; }"
        : "=r"(a) : "l"(p));
    return a;
}
__device__ __forceinline__ float rna_tf32(float x) {
    float r;
    asm("cvt.rna.tf32.f32 %0, %1;" : "=f"(r) : "f"(x));
    return r;
}

#define CP_ASYNC16(s, g) \
    asm volatile("cp.async.cg.shared.global [%0], [%1], 16;" \
                 :: "r"(s), "l"(g) : "memory")
#define CP_COMMIT() asm volatile("cp.async.commit_group;" ::: "memory")
#define CP_WAIT1()  asm volatile("cp.async.wait_group 1;" ::: "memory")

#define LDMX4(r0, r1, r2, r3, a) \
    asm volatile("ldmatrix.sync.aligned.m8n8.x4.shared.b16 {%0,%1,%2,%3}, [%4];" \
                 : "=r"(r0), "=r"(r1), "=r"(r2), "=r"(r3) : "r"(a))

#define MMA8(d, a, b0, b1) \
    asm volatile("mma.sync.aligned.m16n8k8.row.col.f32.tf32.tf32.f32 " \
        "{%0,%1,%2,%3}, {%4,%5,%6,%7}, {%8,%9}, {%0,%1,%2,%3};" \
        : "+f"((d)[0]), "+f"((d)[1]), "+f"((d)[2]), "+f"((d)[3]) \
        : "r"((a)[0]), "r"((a)[1]), "r"((a)[2]), "r"((a)[3]), "r"(b0), "r"(b1))

// ---------------- tf32 mma.sync GEMM: C[2048,2048] = A@W^T + bias ----------
// CTA 128x128, BK=32, 3-stage cp.async pipeline, 8 warps of 64x32.
// A row-major [M][K], W row-major [N][K]; smem rows of 128B with 16B-chunk
// xor swizzle: chunk' = chunk ^ (row & 7).
#define STAGE_SZ 32768
#define SMEM_MMA (3 * STAGE_SZ)

__global__ __launch_bounds__(256, 2) void mma_gemm(
    const float* __restrict__ A, const float* __restrict__ W, int K,
    const float* __restrict__ bias_a, const float* __restrict__ bias_b,
    int bias_mode, float* __restrict__ C)
{
    extern __shared__ char smem[];
    const int tid  = threadIdx.x;
    const int lane = tid & 31, wid = tid >> 5;
    const int wm = wid >> 2, wn = wid & 3;
    const int bm = blockIdx.y, bn = blockIdx.x;
    const uint32_t sbase = smem_u32(smem);
    const int NT = K >> 5;

    float acc[4][4][4] = {};

    // loader mapping: thread t -> row t/2, chunks (t&1)*4 .. +3 (16B each)
    const int lrow = tid >> 1;
    const int lc0  = (tid & 1) * 4;
    const float* Ag = A + (size_t)(bm * 128 + lrow) * K;
    const float* Wg = W + (size_t)(bn * 128 + lrow) * K;
    uint32_t sw[4];
    #pragma unroll
    for (int i = 0; i < 4; i++)
        sw[i] = (uint32_t)lrow * 128 + (((lc0 + i) ^ (lrow & 7)) * 16);

    // prologue: stages 0,1
    #pragma unroll
    for (int s = 0; s < 2; s++) {
        uint32_t sA = sbase + s * STAGE_SZ;
        uint32_t sB = sA + 16384;
        int k0 = s * 32;
        #pragma unroll
        for (int i = 0; i < 4; i++) {
            CP_ASYNC16(sA + sw[i], Ag + k0 + (lc0 + i) * 4);
            CP_ASYNC16(sB + sw[i], Wg + k0 + (lc0 + i) * 4);
        }
        CP_COMMIT();
    }

    // ldmatrix per-lane address offsets
    const int arow = (lane & 15);            // + msub
    const int acol = (lane >> 4);            // + 2*ks
    const int brow = (lane & 7) + ((lane >> 4) << 3);  // + nbase
    const int bcol = (lane >> 3) & 1;        // + 2*ks

    for (int kt = 0; kt < NT; kt++) {
        CP_WAIT1();
        __syncthreads();
        if (kt + 2 < NT) {
            int st = (kt + 2) % 3;
            uint32_t sA = sbase + st * STAGE_SZ;
            uint32_t sB = sA + 16384;
            int k0 = (kt + 2) * 32;
            #pragma unroll
            for (int i = 0; i < 4; i++) {
                CP_ASYNC16(sA + sw[i], Ag + k0 + (lc0 + i) * 4);
                CP_ASYNC16(sB + sw[i], Wg + k0 + (lc0 + i) * 4);
            }
            CP_COMMIT();
        }
        uint32_t sA = sbase + (kt % 3) * STAGE_SZ;
        uint32_t sB = sA + 16384;
        #pragma unroll
        for (int ks = 0; ks < 4; ks++) {
            uint32_t af[4][4], bf[2][4];
            #pragma unroll
            for (int mi = 0; mi < 4; mi++) {
                int r = wm * 64 + mi * 16 + arow;
                int c = 2 * ks + acol;
                uint32_t addr = sA + r * 128 + ((c ^ (r & 7)) * 16);
                LDMX4(af[mi][0], af[mi][1], af[mi][2], af[mi][3], addr);
            }
            #pragma unroll
            for (int bi = 0; bi < 2; bi++) {
                int r = wn * 32 + bi * 16 + brow;
                int c = 2 * ks + bcol;
                uint32_t addr = sB + r * 128 + ((c ^ (r & 7)) * 16);
                LDMX4(bf[bi][0], bf[bi][1], bf[bi][2], bf[bi][3], addr);
            }
            #pragma unroll
            for (int mi = 0; mi < 4; mi++) {
                #pragma unroll
                for (int j = 0; j < 4; j++)
                    MMA8(acc[mi][j], af[mi], bf[j >> 1][(j & 1) * 2],
                         bf[j >> 1][(j & 1) * 2 + 1]);
            }
        }
    }

    // epilogue
    #pragma unroll
    for (int mi = 0; mi < 4; mi++) {
        #pragma unroll
        for (int j = 0; j < 4; j++) {
            int row = bm * 128 + wm * 64 + mi * 16 + (lane >> 2);
            int col = bn * 128 + wn * 32 + j * 8 + (lane & 3) * 2;
            float bv0, bv1;
            if (bias_mode == 0) {
                bv0 = bias_a[col] + bias_b[col];
                bv1 = bias_a[col + 1] + bias_b[col + 1];
            } else {
                bv0 = (col < 1024) ? bias_a[col] : bias_b[col - 1024];
                bv1 = (col + 1 < 1024) ? bias_a[col + 1] : bias_b[col + 1 - 1024];
            }
            float2 v0 = {acc[mi][j][0] + bv0, acc[mi][j][1] + bv1};
            float2 v1 = {acc[mi][j][2] + bv0, acc[mi][j][3] + bv1};
            *(float2*)&C[(size_t)row * 2048 + col] = v0;
            *(float2*)&C[(size_t)(row + 8) * 2048 + col] = v1;
        }
    }
}

// ---------------- small NT GEMM (fp32): N=64 fixed, BM=32, BK=32 -----------
__global__ __launch_bounds__(256) void gemm_nt_small(
    const float* __restrict__ A1, int lda1, int K1,
    const float* __restrict__ A2, int lda2, int K2,
    const float* __restrict__ W1, int ldw1,
    const float* __restrict__ W2, int ldw2,
    const float* __restrict__ bias, int act,
    float* __restrict__ C, int ldc)
{
    __shared__ float As[32][33];
    __shared__ float Ws[32][65];
    const int bm = blockIdx.x * 32;
    const int tid = threadIdx.x;
    const int ty = tid >> 4, tx = tid & 15;
    float acc[2][4] = {};

    #pragma unroll 1
    for (int ph = 0; ph < 2; ph++) {
        const float* A = ph ? A2 : A1;
        const float* W = ph ? W2 : W1;
        const int lda = ph ? lda2 : lda1;
        const int ldw = ph ? ldw2 : ldw1;
        const int K   = ph ? K2   : K1;
        if (A == nullptr || K == 0) continue;
        for (int k0 = 0; k0 < K; k0 += 32) {
            {
                int row = tid >> 3;
                int kc  = (tid & 7) * 4;
                float4 v = *(const float4*)&A[(size_t)(bm + row) * lda + k0 + kc];
                As[kc + 0][row] = v.x; As[kc + 1][row] = v.y;
                As[kc + 2][row] = v.z; As[kc + 3][row] = v.w;
            }
            #pragma unroll
            for (int l = 0; l < 2; l++) {
                int idx = tid + l * 256;
                int row = idx >> 3;
                int kc  = (idx & 7) * 4;
                float4 v = *(const float4*)&W[(size_t)row * ldw + k0 + kc];
                Ws[kc + 0][row] = v.x; Ws[kc + 1][row] = v.y;
                Ws[kc + 2][row] = v.z; Ws[kc + 3][row] = v.w;
            }
            __syncthreads();
            #pragma unroll
            for (int kk = 0; kk < 32; kk++) {
                float a0 = As[kk][ty * 2], a1 = As[kk][ty * 2 + 1];
                float b0 = Ws[kk][tx * 4], b1 = Ws[kk][tx * 4 + 1];
                float b2 = Ws[kk][tx * 4 + 2], b3 = Ws[kk][tx * 4 + 3];
                acc[0][0] += a0 * b0; acc[0][1] += a0 * b1;
                acc[0][2] += a0 * b2; acc[0][3] += a0 * b3;
                acc[1][0] += a1 * b0; acc[1][1] += a1 * b1;
                acc[1][2] += a1 * b2; acc[1][3] += a1 * b3;
            }
            __syncthreads();
        }
    }
    #pragma unroll
    for (int i = 0; i < 2; i++) {
        int r = bm + ty * 2 + i;
        #pragma unroll
        for (int j = 0; j < 4; j++) {
            int c = tx * 4 + j;
            float v = acc[i][j];
            if (bias) v += bias[c];
            if (act == 1) v = 1.0f / (1.0f + expf(-v));
            else if (act == 2) v = tanhf(v);
            C[(size_t)r * ldc + c] = v;
        }
    }
}

// ---------------- NN GEMM vs memory [1024,64], dual-A, fused readnew -------
__global__ __launch_bounds__(256) void gemm_nn_dual(
    const float* __restrict__ A1, const float* __restrict__ A2,
    const float* __restrict__ Bm,
    float* __restrict__ C, int ldc, int coloff,
    const float* __restrict__ erase, const float* __restrict__ addv,
    const float* __restrict__ svec, int mode)
{
    __shared__ float As1[32][33];
    __shared__ float As2[32][33];
    __shared__ float Bs[32][65];
    const int bm = blockIdx.x * 32;
    const int tid = threadIdx.x;
    const int ty = tid >> 4, tx = tid & 15;
    const bool dual = (A2 != nullptr);
    float acc1[2][4] = {};
    float acc2[2][4] = {};

    for (int k0 = 0; k0 < MEMN; k0 += 32) {
        {
            int row = tid >> 3;
            int kc  = (tid & 7) * 4;
            float4 v = *(const float4*)&A1[(size_t)(bm + row) * MEMN + k0 + kc];
            As1[kc + 0][row] = v.x; As1[kc + 1][row] = v.y;
            As1[kc + 2][row] = v.z; As1[kc + 3][row] = v.w;
            if (dual) {
                float4 u = *(const float4*)&A2[(size_t)(bm + row) * MEMN + k0 + kc];
                As2[kc + 0][row] = u.x; As2[kc + 1][row] = u.y;
                As2[kc + 2][row] = u.z; As2[kc + 3][row] = u.w;
            }
        }
        #pragma unroll
        for (int l = 0; l < 2; l++) {
            int idx = tid + l * 256;
            int row = idx >> 4;
            int col = (idx & 15) * 4;
            float4 v = *(const float4*)&Bm[(size_t)(k0 + row) * 64 + col];
            Bs[row][col + 0] = v.x; Bs[row][col + 1] = v.y;
            Bs[row][col + 2] = v.z; Bs[row][col + 3] = v.w;
        }
        __syncthreads();
        #pragma unroll
        for (int kk = 0; kk < 32; kk++) {
            float b0 = Bs[kk][tx * 4], b1 = Bs[kk][tx * 4 + 1];
            float b2 = Bs[kk][tx * 4 + 2], b3 = Bs[kk][tx * 4 + 3];
            float a0 = As1[kk][ty * 2], a1 = As1[kk][ty * 2 + 1];
            acc1[0][0] += a0 * b0; acc1[0][1] += a0 * b1;
            acc1[0][2] += a0 * b2; acc1[0][3] += a0 * b3;
            acc1[1][0] += a1 * b0; acc1[1][1] += a1 * b1;
            acc1[1][2] += a1 * b2; acc1[1][3] += a1 * b3;
            if (dual) {
                float c0 = As2[kk][ty * 2], c1 = As2[kk][ty * 2 + 1];
                acc2[0][0] += c0 * b0; acc2[0][1] += c0 * b1;
                acc2[0][2] += c0 * b2; acc2[0][3] += c0 * b3;
                acc2[1][0] += c1 * b0; acc2[1][1] += c1 * b1;
                acc2[1][2] += c1 * b2; acc2[1][3] += c1 * b3;
            }
        }
        __syncthreads();
    }
    #pragma unroll
    for (int i = 0; i < 2; i++) {
        int r = bm + ty * 2 + i;
        #pragma unroll
        for (int j = 0; j < 4; j++) {
            int c = tx * 4 + j;
            if (mode == 0) {
                C[(size_t)r * ldc + coloff + c] = rna_tf32(acc1[i][j]);
            } else {
                float rn = acc1[i][j]
                         - erase[(size_t)r * 64 + c] * acc2[i][j]
                         + addv[(size_t)r * 64 + c] * svec[r];
                C[(size_t)r * 64 + c] = rn;
            }
        }
    }
}

// ---------------- packs / elementwise / softmax -----------------------------
__global__ void pack_acat_kernel(const float* __restrict__ x,
                                 const float* __restrict__ h_prev,
                                 float* __restrict__ acat)
{
    int idx = blockIdx.x * blockDim.x + threadIdx.x;   // BATCH*576
    int b = idx / 576, c = idx % 576;
    float v = (c < 64) ? x[(size_t)b * 64 + c] : h_prev[(size_t)b * 512 + (c - 64)];
    int col = (c < 64) ? c : c + 64;
    acat[(size_t)b * KCAT + col] = rna_tf32(v);
}

__global__ void pack_wcat_kernel(const float* __restrict__ W_ih,
                                 const float* __restrict__ W_hh,
                                 float* __restrict__ wcat)
{
    int idx = blockIdx.x * blockDim.x + threadIdx.x;   // 2048*640
    int n = idx / KCAT, c = idx % KCAT;
    float v = (c < 128) ? W_ih[(size_t)n * 128 + c] : W_hh[(size_t)n * 512 + (c - 128)];
    wcat[idx] = rna_tf32(v);
}

__global__ void pack_wrw_kernel(const float* __restrict__ W_read,
                                const float* __restrict__ W_write,
                                float* __restrict__ wrw)
{
    int idx = blockIdx.x * blockDim.x + threadIdx.x;   // 2048*512
    int n = idx >> 9;
    float v = (n < 1024) ? W_read[idx] : W_write[idx - 1024 * 512];
    wrw[idx] = rna_tf32(v);
}

__global__ void lstm_kernel(const float* __restrict__ gates,
                            const float* __restrict__ c_prev,
                            float* __restrict__ h,
                            float* __restrict__ ht32)
{
    int idx = blockIdx.x * blockDim.x + threadIdx.x;   // BATCH*512
    int b = idx >> 9, j = idx & 511;
    const float* g = gates + (size_t)b * 2048;
    float gi = g[j], gf = g[512 + j], gg = g[1024 + j], go = g[1536 + j];
    float i = 1.0f / (1.0f + expf(-gi));
    float f = 1.0f / (1.0f + expf(-gf));
    float gv = tanhf(gg);
    float o = 1.0f / (1.0f + expf(-go));
    float c = f * c_prev[idx] + i * gv;
    float hv = o * tanhf(c);
    h[idx] = hv;
    ht32[idx] = rna_tf32(hv);
}

__device__ __forceinline__ float reduce256(float v, float* sh, bool mx)
{
    int t = threadIdx.x;
    sh[t] = v;
    __syncthreads();
    #pragma unroll
    for (int s = 128; s > 0; s >>= 1) {
        if (t < s) sh[t] = mx ? fmaxf(sh[t], sh[t + s]) : (sh[t] + sh[t + s]);
        __syncthreads();
    }
    float r = sh[0];
    __syncthreads();
    return r;
}

__global__ void softmax_fuse_kernel(const float* __restrict__ logits,
                                    float* __restrict__ readw,
                                    float* __restrict__ rwprod,
                                    float* __restrict__ svec)
{
    __shared__ float sh[256];
    int b = blockIdx.x;
    int t = threadIdx.x;
    const float* r = logits + (size_t)b * 2048;
    const float* w = r + 1024;
    float vr[4], vw[4];
    float mr = -1e30f, mw = -1e30f;
    #pragma unroll
    for (int i = 0; i < 4; i++) {
        vr[i] = r[t + i * 256]; vw[i] = w[t + i * 256];
        mr = fmaxf(mr, vr[i]);  mw = fmaxf(mw, vw[i]);
    }
    mr = reduce256(mr, sh, true);
    mw = reduce256(mw, sh, true);
    float er[4], ew[4], sr = 0.f, sw = 0.f;
    #pragma unroll
    for (int i = 0; i < 4; i++) {
        er[i] = expf(vr[i] - mr); sr += er[i];
        ew[i] = expf(vw[i] - mw); sw += ew[i];
    }
    sr = reduce256(sr, sh, false);
    sw = reduce256(sw, sh, false);
    float inv_sr = 1.0f / sr, inv_sw = 1.0f / sw;
    float srw = 0.f;
    #pragma unroll
    for (int i = 0; i < 4; i++) {
        float a = er[i] * inv_sr;
        float p = a * (ew[i] * inv_sw);
        readw[(size_t)b * MEMN + t + i * 256] = a;
        rwprod[(size_t)b * MEMN + t + i * 256] = p;
        srw += p;
    }
    srw = reduce256(srw, sh, false);
    if (t == 0) svec[b] = srw;
}

// ---------------- launch ----------------------------------------------------
extern "C" void kernel_launch(void* const* d_in, const int* in_sizes, int n_in,
                              void* d_out, int out_size)
{
    const float* x       = (const float*)d_in[0];
    const float* h_prev  = (const float*)d_in[1];
    const float* c_prev  = (const float*)d_in[2];
    const float* rwp     = (const float*)d_in[3];
    const float* memory  = (const float*)d_in[4];
    const float* W_ih    = (const float*)d_in[5];
    const float* b_ih    = (const float*)d_in[6];
    const float* W_hh    = (const float*)d_in[7];
    const float* b_hh    = (const float*)d_in[8];
    const float* W_read  = (const float*)d_in[9];
    const float* b_read  = (const float*)d_in[10];
    const float* W_write = (const float*)d_in[11];
    const float* b_write = (const float*)d_in[12];
    const float* W_erase = (const float*)d_in[13];
    const float* b_erase = (const float*)d_in[14];
    const float* W_add   = (const float*)d_in[15];
    const float* b_add   = (const float*)d_in[16];
    const float* W_out   = (const float*)d_in[17];
    const float* b_out   = (const float*)d_in[18];
    float* out = (float*)d_out;

    float *acat, *wcat, *wrw, *gates, *logits, *h, *ht32;
    float *readw, *rw, *svec, *er, *ad, *rn;
    cudaGetSymbolAddress((void**)&acat,   g_acat);
    cudaGetSymbolAddress((void**)&wcat,   g_wcat);
    cudaGetSymbolAddress((void**)&wrw,    g_wrw);
    cudaGetSymbolAddress((void**)&gates,  g_gates);
    cudaGetSymbolAddress((void**)&logits, g_logits);
    cudaGetSymbolAddress((void**)&h,      g_h);
    cudaGetSymbolAddress((void**)&ht32,   g_ht32);
    cudaGetSymbolAddress((void**)&readw,  g_readw);
    cudaGetSymbolAddress((void**)&rw,     g_rw);
    cudaGetSymbolAddress((void**)&svec,   g_s);
    cudaGetSymbolAddress((void**)&er,     g_erase);
    cudaGetSymbolAddress((void**)&ad,     g_add);
    cudaGetSymbolAddress((void**)&rn,     g_readnew);

    cudaFuncSetAttribute(mma_gemm, cudaFuncAttributeMaxDynamicSharedMemorySize,
                         SMEM_MMA);

    // 1) packs (tf32-round all MMA operands)
    pack_wcat_kernel<<<(2048 * KCAT) / 256, 256>>>(W_ih, W_hh, wcat);
    pack_wrw_kernel<<<(2048 * CTRLN) / 256, 256>>>(W_read, W_write, wrw);
    pack_acat_kernel<<<(BATCH * 576) / 256, 256>>>(x, h_prev, acat);

    // 2) read_prev = read_weights_prev @ memory -> acat[:, 64:128) (rounded)
    gemm_nn_dual<<<BATCH / 32, 256>>>(rwp, nullptr, memory,
                                      acat, KCAT, 64,
                                      nullptr, nullptr, nullptr, 0);

    // 3) gates = A_cat @ W_cat^T + b_ih + b_hh   [tf32 mma.sync]
    mma_gemm<<<dim3(16, 16), 256, SMEM_MMA>>>(
        acat, wcat, KCAT, b_ih, b_hh, 0, gates);

    // 4) LSTM cell -> h (fp32) + ht32 (rounded)
    lstm_kernel<<<(BATCH * CTRLN) / 256, 256>>>(gates, c_prev, h, ht32);

    // 5) logits = h @ [W_read;W_write]^T + biases   [tf32 mma.sync]
    mma_gemm<<<dim3(16, 16), 256, SMEM_MMA>>>(
        ht32, wrw, CTRLN, b_read, b_write, 1, logits);

    // 6) softmaxes + read_w*write_w + row sums
    softmax_fuse_kernel<<<BATCH, 256>>>(logits, readw, rw, svec);

    // 7) erase/add (fp32 small GEMMs)
    gemm_nt_small<<<BATCH / 32, 256>>>(h, CTRLN, CTRLN, nullptr, 0, 0,
                                       W_erase, CTRLN, nullptr, 0,
                                       b_erase, 1, er, 64);
    gemm_nt_small<<<BATCH / 32, 256>>>(h, CTRLN, CTRLN, nullptr, 0, 0,
                                       W_add, CTRLN, nullptr, 0,
                                       b_add, 2, ad, 64);

    // 8) read_new = read_w@mem - erase*(rw@mem) + add*s   (fused einsum)
    gemm_nn_dual<<<BATCH / 32, 256>>>(readw, rw, memory,
                                      rn, 64, 0,
                                      er, ad, svec, 1);

    // 9) out = [h | read_new] @ W_out^T + b_out
    gemm_nt_small<<<BATCH / 32, 256>>>(h, CTRLN, CTRLN, rn, 64, 64,
                                       W_out, 576, W_out + 512, 576,
                                       b_out, 0, out, 64);
}

// round 4
// speedup vs baseline: 2.9665x; 1.8536x over previous
#include <cuda_runtime.h>
#include <math.h>
#include <stdint.h>

#define BATCH 2048
#define CTRLN 512
#define MEMN  1024
#define VDIM  64
#define KCAT  640   // 64 x + 64 read_prev + 512 h_prev
#define SPLITK 8

// ---------------- scratch (device globals: allocation-free) ----------------
__device__ float g_acat[BATCH * KCAT];      // tf32-rounded [x|read_prev|h_prev]
__device__ float g_wcat[2048 * KCAT];       // tf32-rounded [W_ih|W_hh]
__device__ float g_wrw[2048 * CTRLN];       // tf32-rounded [W_read;W_write]
__device__ float g_gates[BATCH * 2048];
__device__ float g_logits[BATCH * 2048];    // [read logits | write logits]
__device__ float g_h[BATCH * CTRLN];        // fp32 h
__device__ float g_ht32[BATCH * CTRLN];     // tf32-rounded h
__device__ float g_readw[BATCH * MEMN];
__device__ float g_rw[BATCH * MEMN];
__device__ float g_s[BATCH];
__device__ float g_erase[BATCH * VDIM];
__device__ float g_add[BATCH * VDIM];
__device__ float g_readnew[BATCH * VDIM];
__device__ float g_p1[SPLITK * BATCH * VDIM];   // split-K partials
__device__ float g_p2[SPLITK * BATCH * VDIM];

// ---------------- helpers ----------------------------------------------------
__device__ __forceinline__ uint32_t smem_u32(const void* p) {
    uint32_t a;
    asm("{ .reg .u64 t; cvta.to.shared.u64 t, %1; cvt.u32.u64 %0, t; }"
        : "=r"(a) : "l"(p));
    return a;
}
__device__ __forceinline__ float rna_tf32(float x) {
    float r;
    asm("cvt.rna.tf32.f32 %0, %1;" : "=f"(r) : "f"(x));
    return r;
}

#define CP_ASYNC16(s, g) \
    asm volatile("cp.async.cg.shared.global [%0], [%1], 16;" \
                 :: "r"(s), "l"(g) : "memory")
#define CP_COMMIT() asm volatile("cp.async.commit_group;" ::: "memory")
#define CP_WAIT1()  asm volatile("cp.async.wait_group 1;" ::: "memory")

#define LDMX4(r0, r1, r2, r3, a) \
    asm volatile("ldmatrix.sync.aligned.m8n8.x4.shared.b16 {%0,%1,%2,%3}, [%4];" \
                 : "=r"(r0), "=r"(r1), "=r"(r2), "=r"(r3) : "r"(a))

#define MMA8(d, a, b0, b1) \
    asm volatile("mma.sync.aligned.m16n8k8.row.col.f32.tf32.tf32.f32 " \
        "{%0,%1,%2,%3}, {%4,%5,%6,%7}, {%8,%9}, {%0,%1,%2,%3};" \
        : "+f"((d)[0]), "+f"((d)[1]), "+f"((d)[2]), "+f"((d)[3]) \
        : "r"((a)[0]), "r"((a)[1]), "r"((a)[2]), "r"((a)[3]), "r"(b0), "r"(b1))

// ---------------- tf32 mma.sync GEMM: C[2048,2048] = A@W^T + bias ----------
#define STAGE_SZ 32768
#define SMEM_MMA (3 * STAGE_SZ)

__global__ __launch_bounds__(256, 2) void mma_gemm(
    const float* __restrict__ A, const float* __restrict__ W, int K,
    const float* __restrict__ bias_a, const float* __restrict__ bias_b,
    int bias_mode, float* __restrict__ C)
{
    extern __shared__ char smem[];
    const int tid  = threadIdx.x;
    const int lane = tid & 31, wid = tid >> 5;
    const int wm = wid >> 2, wn = wid & 3;
    const int bm = blockIdx.y, bn = blockIdx.x;
    const uint32_t sbase = smem_u32(smem);
    const int NT = K >> 5;

    float acc[4][4][4] = {};

    const int lrow = tid >> 1;
    const int lc0  = (tid & 1) * 4;
    const float* Ag = A + (size_t)(bm * 128 + lrow) * K;
    const float* Wg = W + (size_t)(bn * 128 + lrow) * K;
    uint32_t sw[4];
    #pragma unroll
    for (int i = 0; i < 4; i++)
        sw[i] = (uint32_t)lrow * 128 + (((lc0 + i) ^ (lrow & 7)) * 16);

    #pragma unroll
    for (int s = 0; s < 2; s++) {
        uint32_t sA = sbase + s * STAGE_SZ;
        uint32_t sB = sA + 16384;
        int k0 = s * 32;
        #pragma unroll
        for (int i = 0; i < 4; i++) {
            CP_ASYNC16(sA + sw[i], Ag + k0 + (lc0 + i) * 4);
            CP_ASYNC16(sB + sw[i], Wg + k0 + (lc0 + i) * 4);
        }
        CP_COMMIT();
    }

    const int arow = (lane & 15);
    const int acol = (lane >> 4);
    const int brow = (lane & 7) + ((lane >> 4) << 3);
    const int bcol = (lane >> 3) & 1;

    for (int kt = 0; kt < NT; kt++) {
        CP_WAIT1();
        __syncthreads();
        if (kt + 2 < NT) {
            int st = (kt + 2) % 3;
            uint32_t sA = sbase + st * STAGE_SZ;
            uint32_t sB = sA + 16384;
            int k0 = (kt + 2) * 32;
            #pragma unroll
            for (int i = 0; i < 4; i++) {
                CP_ASYNC16(sA + sw[i], Ag + k0 + (lc0 + i) * 4);
                CP_ASYNC16(sB + sw[i], Wg + k0 + (lc0 + i) * 4);
            }
            CP_COMMIT();
        }
        uint32_t sA = sbase + (kt % 3) * STAGE_SZ;
        uint32_t sB = sA + 16384;
        #pragma unroll
        for (int ks = 0; ks < 4; ks++) {
            uint32_t af[4][4], bf[2][4];
            #pragma unroll
            for (int mi = 0; mi < 4; mi++) {
                int r = wm * 64 + mi * 16 + arow;
                int c = 2 * ks + acol;
                uint32_t addr = sA + r * 128 + ((c ^ (r & 7)) * 16);
                LDMX4(af[mi][0], af[mi][1], af[mi][2], af[mi][3], addr);
            }
            #pragma unroll
            for (int bi = 0; bi < 2; bi++) {
                int r = wn * 32 + bi * 16 + brow;
                int c = 2 * ks + bcol;
                uint32_t addr = sB + r * 128 + ((c ^ (r & 7)) * 16);
                LDMX4(bf[bi][0], bf[bi][1], bf[bi][2], bf[bi][3], addr);
            }
            #pragma unroll
            for (int mi = 0; mi < 4; mi++) {
                #pragma unroll
                for (int j = 0; j < 4; j++)
                    MMA8(acc[mi][j], af[mi], bf[j >> 1][(j & 1) * 2],
                         bf[j >> 1][(j & 1) * 2 + 1]);
            }
        }
    }

    #pragma unroll
    for (int mi = 0; mi < 4; mi++) {
        #pragma unroll
        for (int j = 0; j < 4; j++) {
            int row = bm * 128 + wm * 64 + mi * 16 + (lane >> 2);
            int col = bn * 128 + wn * 32 + j * 8 + (lane & 3) * 2;
            float bv0, bv1;
            if (bias_mode == 0) {
                bv0 = bias_a[col] + bias_b[col];
                bv1 = bias_a[col + 1] + bias_b[col + 1];
            } else {
                bv0 = (col < 1024) ? bias_a[col] : bias_b[col - 1024];
                bv1 = (col + 1 < 1024) ? bias_a[col + 1] : bias_b[col + 1 - 1024];
            }
            float2 v0 = {acc[mi][j][0] + bv0, acc[mi][j][1] + bv1};
            float2 v1 = {acc[mi][j][2] + bv0, acc[mi][j][3] + bv1};
            *(float2*)&C[(size_t)row * 2048 + col] = v0;
            *(float2*)&C[(size_t)(row + 8) * 2048 + col] = v1;
        }
    }
}

// ---------------- split-K skinny GEMM: P[s][M][64] partials -----------------
// Block tile 64(M) x 64(N), BK=32, 256 threads (16x16, 4x4 each).
// Supports: NT (B = W[64][ldw], n-major rows), NN (B = memory[K][64]),
// concat-A second phase (A2,K2), and dual-A (same B, two accumulators).
template <int DUAL>
__global__ __launch_bounds__(256) void gemm_skinny(
    const float* __restrict__ A1, const float* __restrict__ A1d,
    int lda1, int K1,
    const float* __restrict__ A2, int lda2, int K2,
    const float* __restrict__ Bw, int ldw, int bmode,
    float* __restrict__ P1, float* __restrict__ P2)
{
    __shared__ float As[64][36];
    __shared__ float Adm[DUAL ? 64 : 1][36];
    __shared__ float Bs[32][68];

    const int tid = threadIdx.x;
    const int bm  = blockIdx.x * 64;
    const int ty  = tid >> 4, tx = tid & 15;

    const int total_tiles = (K1 + K2) >> 5;
    const int per = (total_tiles + SPLITK - 1) / SPLITK;
    const int t0 = blockIdx.y * per;
    int t1 = t0 + per; if (t1 > total_tiles) t1 = total_tiles;
    const int nt1 = K1 >> 5;

    float acc[4][4] = {};
    float accd[DUAL ? 4 : 1][4] = {};

    for (int t = t0; t < t1; t++) {
        const float* Ag; int lda, k0;
        if (t < nt1) { Ag = A1; lda = lda1; k0 = t << 5; }
        else         { Ag = A2; lda = lda2; k0 = (t - nt1) << 5; }

        // A tile [64 rows][32 k]
        {
            int row = tid >> 3;
            int c   = (tid & 7) * 4;
            #pragma unroll
            for (int rr = 0; rr < 64; rr += 32) {
                float4 v = *(const float4*)&Ag[(size_t)(bm + row + rr) * lda + k0 + c];
                *(float4*)&As[row + rr][c] = v;
                if (DUAL) {
                    float4 u = *(const float4*)&A1d[(size_t)(bm + row + rr) * lda + k0 + c];
                    *(float4*)&Adm[row + rr][c] = u;
                }
            }
        }
        // B tile -> Bs[k][n]
        if (bmode == 1) {   // NN: memory[K][64]
            int idx = tid;
            #pragma unroll
            for (int it = 0; it < 2; it++, idx += 256) {
                int kr = idx >> 4, nc = (idx & 15) * 4;
                float4 v = *(const float4*)&Bw[(size_t)((t << 5) + kr) * 64 + nc];
                *(float4*)&Bs[kr][nc] = v;
            }
        } else {            // NT: W[64][ldw], col offset = t*32
            int n = tid >> 3, c = (tid & 7) * 4;
            #pragma unroll
            for (int nn = 0; nn < 64; nn += 32) {
                float4 v = *(const float4*)&Bw[(size_t)(n + nn) * ldw + (t << 5) + c];
                Bs[c + 0][n + nn] = v.x; Bs[c + 1][n + nn] = v.y;
                Bs[c + 2][n + nn] = v.z; Bs[c + 3][n + nn] = v.w;
            }
        }
        __syncthreads();
        #pragma unroll
        for (int kk = 0; kk < 32; kk++) {
            float b[4];
            *(float4*)b = *(const float4*)&Bs[kk][tx * 4];
            float a[4];
            #pragma unroll
            for (int i = 0; i < 4; i++) a[i] = As[ty * 4 + i][kk];
            #pragma unroll
            for (int i = 0; i < 4; i++)
                #pragma unroll
                for (int j = 0; j < 4; j++)
                    acc[i][j] += a[i] * b[j];
            if (DUAL) {
                float ad[4];
                #pragma unroll
                for (int i = 0; i < 4; i++) ad[i] = Adm[ty * 4 + i][kk];
                #pragma unroll
                for (int i = 0; i < 4; i++)
                    #pragma unroll
                    for (int j = 0; j < 4; j++)
                        accd[i][j] += ad[i] * b[j];
            }
        }
        __syncthreads();
    }

    const size_t pbase = ((size_t)blockIdx.y * BATCH + bm) * 64;
    #pragma unroll
    for (int i = 0; i < 4; i++) {
        *(float4*)&P1[pbase + (size_t)(ty * 4 + i) * 64 + tx * 4] = *(float4*)acc[i];
        if (DUAL)
            *(float4*)&P2[pbase + (size_t)(ty * 4 + i) * 64 + tx * 4] = *(float4*)accd[i];
    }
}

// ---------------- reduces ----------------------------------------------------
// act: 0=none 1=sigmoid 2=tanh ; tf32r: round output to tf32
__global__ void reduce_act(const float* __restrict__ P,
                           const float* __restrict__ bias,
                           int act, int tf32r,
                           float* __restrict__ out, int ldc, int coloff)
{
    int idx = blockIdx.x * blockDim.x + threadIdx.x;   // BATCH*16
    int r = idx >> 4, c = (idx & 15) * 4;
    float4 s = {0.f, 0.f, 0.f, 0.f};
    #pragma unroll
    for (int k = 0; k < SPLITK; k++) {
        float4 v = *(const float4*)&P[((size_t)k * BATCH + r) * 64 + c];
        s.x += v.x; s.y += v.y; s.z += v.z; s.w += v.w;
    }
    float vv[4] = {s.x, s.y, s.z, s.w};
    #pragma unroll
    for (int q = 0; q < 4; q++) {
        float v = vv[q];
        if (bias) v += bias[c + q];
        if (act == 1) v = 1.0f / (1.0f + expf(-v));
        else if (act == 2) v = tanhf(v);
        if (tf32r) v = rna_tf32(v);
        vv[q] = v;
    }
    *(float4*)&out[(size_t)r * ldc + coloff + c] =
        make_float4(vv[0], vv[1], vv[2], vv[3]);
}

__global__ void reduce_readnew(const float* __restrict__ PA,
                               const float* __restrict__ PB,
                               const float* __restrict__ erase,
                               const float* __restrict__ addv,
                               const float* __restrict__ svec,
                               float* __restrict__ rn)
{
    int idx = blockIdx.x * blockDim.x + threadIdx.x;   // BATCH*16
    int r = idx >> 4, c = (idx & 15) * 4;
    float4 s1 = {0.f, 0.f, 0.f, 0.f}, s2 = {0.f, 0.f, 0.f, 0.f};
    #pragma unroll
    for (int k = 0; k < SPLITK; k++) {
        float4 v = *(const float4*)&PA[((size_t)k * BATCH + r) * 64 + c];
        float4 u = *(const float4*)&PB[((size_t)k * BATCH + r) * 64 + c];
        s1.x += v.x; s1.y += v.y; s1.z += v.z; s1.w += v.w;
        s2.x += u.x; s2.y += u.y; s2.z += u.z; s2.w += u.w;
    }
    float sv = svec[r];
    float4 e = *(const float4*)&erase[(size_t)r * 64 + c];
    float4 a = *(const float4*)&addv[(size_t)r * 64 + c];
    float4 o;
    o.x = s1.x - e.x * s2.x + a.x * sv;
    o.y = s1.y - e.y * s2.y + a.y * sv;
    o.z = s1.z - e.z * s2.z + a.z * sv;
    o.w = s1.w - e.w * s2.w + a.w * sv;
    *(float4*)&rn[(size_t)r * 64 + c] = o;
}

// ---------------- packs / elementwise / softmax -----------------------------
__global__ void pack_acat_kernel(const float* __restrict__ x,
                                 const float* __restrict__ h_prev,
                                 float* __restrict__ acat)
{
    int idx = blockIdx.x * blockDim.x + threadIdx.x;   // BATCH*576
    int b = idx / 576, c = idx % 576;
    float v = (c < 64) ? x[(size_t)b * 64 + c] : h_prev[(size_t)b * 512 + (c - 64)];
    int col = (c < 64) ? c : c + 64;
    acat[(size_t)b * KCAT + col] = rna_tf32(v);
}

__global__ void pack_wcat_kernel(const float* __restrict__ W_ih,
                                 const float* __restrict__ W_hh,
                                 float* __restrict__ wcat)
{
    int idx = blockIdx.x * blockDim.x + threadIdx.x;   // 2048*640
    int n = idx / KCAT, c = idx % KCAT;
    float v = (c < 128) ? W_ih[(size_t)n * 128 + c] : W_hh[(size_t)n * 512 + (c - 128)];
    wcat[idx] = rna_tf32(v);
}

__global__ void pack_wrw_kernel(const float* __restrict__ W_read,
                                const float* __restrict__ W_write,
                                float* __restrict__ wrw)
{
    int idx = blockIdx.x * blockDim.x + threadIdx.x;   // 2048*512
    int n = idx >> 9;
    float v = (n < 1024) ? W_read[idx] : W_write[idx - 1024 * 512];
    wrw[idx] = rna_tf32(v);
}

__global__ void lstm_kernel(const float* __restrict__ gates,
                            const float* __restrict__ c_prev,
                            float* __restrict__ h,
                            float* __restrict__ ht32)
{
    int idx = blockIdx.x * blockDim.x + threadIdx.x;   // BATCH*128
    int b = idx >> 7, j = (idx & 127) * 4;
    const float* g = gates + (size_t)b * 2048;
    float4 gi = *(const float4*)&g[j];
    float4 gf = *(const float4*)&g[512 + j];
    float4 gg = *(const float4*)&g[1024 + j];
    float4 go = *(const float4*)&g[1536 + j];
    float4 cp = *(const float4*)&c_prev[(size_t)b * 512 + j];
    float hi[4];
    float I[4] = {gi.x, gi.y, gi.z, gi.w};
    float F[4] = {gf.x, gf.y, gf.z, gf.w};
    float G[4] = {gg.x, gg.y, gg.z, gg.w};
    float O[4] = {go.x, go.y, go.z, go.w};
    float C[4] = {cp.x, cp.y, cp.z, cp.w};
    #pragma unroll
    for (int q = 0; q < 4; q++) {
        float i = 1.0f / (1.0f + expf(-I[q]));
        float f = 1.0f / (1.0f + expf(-F[q]));
        float gv = tanhf(G[q]);
        float o = 1.0f / (1.0f + expf(-O[q]));
        float c = f * C[q] + i * gv;
        hi[q] = o * tanhf(c);
    }
    *(float4*)&h[(size_t)b * 512 + j] = make_float4(hi[0], hi[1], hi[2], hi[3]);
    *(float4*)&ht32[(size_t)b * 512 + j] =
        make_float4(rna_tf32(hi[0]), rna_tf32(hi[1]), rna_tf32(hi[2]), rna_tf32(hi[3]));
}

__device__ __forceinline__ float blk_reduce(float v, bool mx, float* sh)
{
    int lane = threadIdx.x & 31, wid = threadIdx.x >> 5;
    #pragma unroll
    for (int o = 16; o > 0; o >>= 1) {
        float t = __shfl_xor_sync(0xFFFFFFFFu, v, o);
        v = mx ? fmaxf(v, t) : (v + t);
    }
    if (lane == 0) sh[wid] = v;
    __syncthreads();
    if (wid == 0) {
        float r = (lane < 8) ? sh[lane] : (mx ? -1e30f : 0.f);
        #pragma unroll
        for (int o = 4; o > 0; o >>= 1) {
            float t = __shfl_xor_sync(0xFFFFFFFFu, r, o);
            r = mx ? fmaxf(r, t) : (r + t);
        }
        if (lane == 0) sh[0] = r;
    }
    __syncthreads();
    float r = sh[0];
    __syncthreads();
    return r;
}

__global__ void softmax_fuse_kernel(const float* __restrict__ logits,
                                    float* __restrict__ readw,
                                    float* __restrict__ rwprod,
                                    float* __restrict__ svec)
{
    __shared__ float sh[8];
    int b = blockIdx.x;
    int t = threadIdx.x;
    const float* r = logits + (size_t)b * 2048;
    const float* w = r + 1024;
    float vr[4], vw[4];
    float mr = -1e30f, mw = -1e30f;
    #pragma unroll
    for (int i = 0; i < 4; i++) {
        vr[i] = r[t + i * 256]; vw[i] = w[t + i * 256];
        mr = fmaxf(mr, vr[i]);  mw = fmaxf(mw, vw[i]);
    }
    mr = blk_reduce(mr, true, sh);
    mw = blk_reduce(mw, true, sh);
    float er[4], ew[4], sr = 0.f, sw = 0.f;
    #pragma unroll
    for (int i = 0; i < 4; i++) {
        er[i] = expf(vr[i] - mr); sr += er[i];
        ew[i] = expf(vw[i] - mw); sw += ew[i];
    }
    sr = blk_reduce(sr, false, sh);
    sw = blk_reduce(sw, false, sh);
    float inv_sr = 1.0f / sr, inv_sw = 1.0f / sw;
    float srw = 0.f;
    #pragma unroll
    for (int i = 0; i < 4; i++) {
        float a = er[i] * inv_sr;
        float p = a * (ew[i] * inv_sw);
        readw[(size_t)b * MEMN + t + i * 256] = a;
        rwprod[(size_t)b * MEMN + t + i * 256] = p;
        srw += p;
    }
    srw = blk_reduce(srw, false, sh);
    if (t == 0) svec[b] = srw;
}

// ---------------- launch ----------------------------------------------------
extern "C" void kernel_launch(void* const* d_in, const int* in_sizes, int n_in,
                              void* d_out, int out_size)
{
    const float* x       = (const float*)d_in[0];
    const float* h_prev  = (const float*)d_in[1];
    const float* c_prev  = (const float*)d_in[2];
    const float* rwp     = (const float*)d_in[3];
    const float* memory  = (const float*)d_in[4];
    const float* W_ih    = (const float*)d_in[5];
    const float* b_ih    = (const float*)d_in[6];
    const float* W_hh    = (const float*)d_in[7];
    const float* b_hh    = (const float*)d_in[8];
    const float* W_read  = (const float*)d_in[9];
    const float* b_read  = (const float*)d_in[10];
    const float* W_write = (const float*)d_in[11];
    const float* b_write = (const float*)d_in[12];
    const float* W_erase = (const float*)d_in[13];
    const float* b_erase = (const float*)d_in[14];
    const float* W_add   = (const float*)d_in[15];
    const float* b_add   = (const float*)d_in[16];
    const float* W_out   = (const float*)d_in[17];
    const float* b_out   = (const float*)d_in[18];
    float* out = (float*)d_out;

    float *acat, *wcat, *wrw, *gates, *logits, *h, *ht32;
    float *readw, *rw, *svec, *er, *ad, *rn, *p1, *p2;
    cudaGetSymbolAddress((void**)&acat,   g_acat);
    cudaGetSymbolAddress((void**)&wcat,   g_wcat);
    cudaGetSymbolAddress((void**)&wrw,    g_wrw);
    cudaGetSymbolAddress((void**)&gates,  g_gates);
    cudaGetSymbolAddress((void**)&logits, g_logits);
    cudaGetSymbolAddress((void**)&h,      g_h);
    cudaGetSymbolAddress((void**)&ht32,   g_ht32);
    cudaGetSymbolAddress((void**)&readw,  g_readw);
    cudaGetSymbolAddress((void**)&rw,     g_rw);
    cudaGetSymbolAddress((void**)&svec,   g_s);
    cudaGetSymbolAddress((void**)&er,     g_erase);
    cudaGetSymbolAddress((void**)&ad,     g_add);
    cudaGetSymbolAddress((void**)&rn,     g_readnew);
    cudaGetSymbolAddress((void**)&p1,     g_p1);
    cudaGetSymbolAddress((void**)&p2,     g_p2);

    cudaFuncSetAttribute(mma_gemm, cudaFuncAttributeMaxDynamicSharedMemorySize,
                         SMEM_MMA);

    const dim3 skg(BATCH / 64, SPLITK);
    const int rgrid = (BATCH * 16) / 256;

    // 1) packs (tf32-round all MMA operands)
    pack_wcat_kernel<<<(2048 * KCAT) / 256, 256>>>(W_ih, W_hh, wcat);
    pack_wrw_kernel<<<(2048 * CTRLN) / 256, 256>>>(W_read, W_write, wrw);
    pack_acat_kernel<<<(BATCH * 576) / 256, 256>>>(x, h_prev, acat);

    // 2) read_prev = read_weights_prev @ memory -> acat[:, 64:128) (rounded)
    gemm_skinny<0><<<skg, 256>>>(rwp, nullptr, MEMN, MEMN,
                                 nullptr, 0, 0, memory, 0, 1, p1, nullptr);
    reduce_act<<<rgrid, 256>>>(p1, nullptr, 0, 1, acat, KCAT, 64);

    // 3) gates = A_cat @ W_cat^T + b_ih + b_hh   [tf32 mma.sync]
    mma_gemm<<<dim3(16, 16), 256, SMEM_MMA>>>(
        acat, wcat, KCAT, b_ih, b_hh, 0, gates);

    // 4) LSTM cell -> h (fp32) + ht32 (rounded)
    lstm_kernel<<<(BATCH * 128) / 256, 256>>>(gates, c_prev, h, ht32);

    // 5) logits = h @ [W_read;W_write]^T + biases   [tf32 mma.sync]
    mma_gemm<<<dim3(16, 16), 256, SMEM_MMA>>>(
        ht32, wrw, CTRLN, b_read, b_write, 1, logits);

    // 6) softmaxes + read_w*write_w + row sums
    softmax_fuse_kernel<<<BATCH, 256>>>(logits, readw, rw, svec);

    // 7) erase = sigmoid(h@W_erase^T+b), add = tanh(h@W_add^T+b)
    gemm_skinny<0><<<skg, 256>>>(h, nullptr, CTRLN, CTRLN,
                                 nullptr, 0, 0, W_erase, CTRLN, 0, p1, nullptr);
    gemm_skinny<0><<<skg, 256>>>(h, nullptr, CTRLN, CTRLN,
                                 nullptr, 0, 0, W_add, CTRLN, 0, p2, nullptr);
    reduce_act<<<rgrid, 256>>>(p1, b_erase, 1, 0, er, 64, 0);
    reduce_act<<<rgrid, 256>>>(p2, b_add, 2, 0, ad, 64, 0);

    // 8) read_new = read_w@mem - erase*(rw@mem) + add*s   (fused einsum)
    gemm_skinny<1><<<skg, 256>>>(readw, rw, MEMN, MEMN,
                                 nullptr, 0, 0, memory, 0, 1, p1, p2);
    reduce_readnew<<<rgrid, 256>>>(p1, p2, er, ad, svec, rn);

    // 9) out = [h | read_new] @ W_out^T + b_out
    gemm_skinny<0><<<skg, 256>>>(h, nullptr, CTRLN, CTRLN,
                                 rn, VDIM, VDIM, W_out, CTRLN + VDIM, 0,
                                 p1, nullptr);
    reduce_act<<<rgrid, 256>>>(p1, b_out, 0, 0, out, 64, 0);
}

// round 5
// speedup vs baseline: 3.0265x; 1.0202x over previous
#include <cuda_runtime.h>
#include <math.h>
#include <stdint.h>

#define BATCH 2048
#define CTRLN 512
#define MEMN  1024
#define VDIM  64
#define KCAT  640   // 64 x + 64 read_prev + 512 h_prev
#define SPLITK 16

// ---------------- scratch (device globals: allocation-free) ----------------
__device__ float g_acat[BATCH * KCAT];      // tf32-rounded [x|read_prev|h_prev]
__device__ float g_wcat[2048 * KCAT];       // tf32-rounded [W_ih|W_hh]
__device__ float g_wrw[2048 * CTRLN];       // tf32-rounded [W_read;W_write]
__device__ float g_wea[128 * CTRLN];        // [W_erase;W_add] packed
__device__ float g_gates[BATCH * 2048];
__device__ float g_logits[BATCH * 2048];    // [read logits | write logits]
__device__ float g_h[BATCH * CTRLN];        // fp32 h
__device__ float g_ht32[BATCH * CTRLN];     // tf32-rounded h
__device__ float g_readw[BATCH * MEMN];
__device__ float g_rw[BATCH * MEMN];
__device__ float g_s[BATCH];
__device__ float g_readnew[BATCH * VDIM];
__device__ float g_p1[SPLITK * BATCH * VDIM];    // split-K partials (64-wide)
__device__ float g_p2[SPLITK * BATCH * VDIM];
__device__ float g_p3[SPLITK * BATCH * 128];     // erase|add partials (128-wide)

// ---------------- helpers ----------------------------------------------------
__device__ __forceinline__ uint32_t smem_u32(const void* p) {
    uint32_t a;
    asm("{ .reg .u64 t; cvta.to.shared.u64 t, %1; cvt.u32.u64 %0, t; }"
        : "=r"(a) : "l"(p));
    return a;
}
__device__ __forceinline__ float rna_tf32(float x) {
    float r;
    asm("cvt.rna.tf32.f32 %0, %1;" : "=f"(r) : "f"(x));
    return r;
}

#define CP_ASYNC16(s, g) \
    asm volatile("cp.async.cg.shared.global [%0], [%1], 16;" \
                 :: "r"(s), "l"(g) : "memory")
#define CP_COMMIT() asm volatile("cp.async.commit_group;" ::: "memory")
#define CP_WAIT1()  asm volatile("cp.async.wait_group 1;" ::: "memory")

#define LDMX4(r0, r1, r2, r3, a) \
    asm volatile("ldmatrix.sync.aligned.m8n8.x4.shared.b16 {%0,%1,%2,%3}, [%4];" \
                 : "=r"(r0), "=r"(r1), "=r"(r2), "=r"(r3) : "r"(a))

#define MMA8(d, a, b0, b1) \
    asm volatile("mma.sync.aligned.m16n8k8.row.col.f32.tf32.tf32.f32 " \
        "{%0,%1,%2,%3}, {%4,%5,%6,%7}, {%8,%9}, {%0,%1,%2,%3};" \
        : "+f"((d)[0]), "+f"((d)[1]), "+f"((d)[2]), "+f"((d)[3]) \
        : "r"((a)[0]), "r"((a)[1]), "r"((a)[2]), "r"((a)[3]), "r"(b0), "r"(b1))

// ---------------- tf32 mma.sync GEMM: C[2048,2048] = A@W^T + bias ----------
#define STAGE_SZ 32768
#define SMEM_MMA (3 * STAGE_SZ)

__global__ __launch_bounds__(256, 2) void mma_gemm(
    const float* __restrict__ A, const float* __restrict__ W, int K,
    const float* __restrict__ bias_a, const float* __restrict__ bias_b,
    int bias_mode, float* __restrict__ C)
{
    extern __shared__ char smem[];
    const int tid  = threadIdx.x;
    const int lane = tid & 31, wid = tid >> 5;
    const int wm = wid >> 2, wn = wid & 3;
    const int bm = blockIdx.y, bn = blockIdx.x;
    const uint32_t sbase = smem_u32(smem);
    const int NT = K >> 5;

    float acc[4][4][4] = {};

    const int lrow = tid >> 1;
    const int lc0  = (tid & 1) * 4;
    const float* Ag = A + (size_t)(bm * 128 + lrow) * K;
    const float* Wg = W + (size_t)(bn * 128 + lrow) * K;
    uint32_t sw[4];
    #pragma unroll
    for (int i = 0; i < 4; i++)
        sw[i] = (uint32_t)lrow * 128 + (((lc0 + i) ^ (lrow & 7)) * 16);

    #pragma unroll
    for (int s = 0; s < 2; s++) {
        uint32_t sA = sbase + s * STAGE_SZ;
        uint32_t sB = sA + 16384;
        int k0 = s * 32;
        #pragma unroll
        for (int i = 0; i < 4; i++) {
            CP_ASYNC16(sA + sw[i], Ag + k0 + (lc0 + i) * 4);
            CP_ASYNC16(sB + sw[i], Wg + k0 + (lc0 + i) * 4);
        }
        CP_COMMIT();
    }

    const int arow = (lane & 15);
    const int acol = (lane >> 4);
    const int brow = (lane & 7) + ((lane >> 4) << 3);
    const int bcol = (lane >> 3) & 1;

    for (int kt = 0; kt < NT; kt++) {
        CP_WAIT1();
        __syncthreads();
        if (kt + 2 < NT) {
            int st = (kt + 2) % 3;
            uint32_t sA = sbase + st * STAGE_SZ;
            uint32_t sB = sA + 16384;
            int k0 = (kt + 2) * 32;
            #pragma unroll
            for (int i = 0; i < 4; i++) {
                CP_ASYNC16(sA + sw[i], Ag + k0 + (lc0 + i) * 4);
                CP_ASYNC16(sB + sw[i], Wg + k0 + (lc0 + i) * 4);
            }
            CP_COMMIT();
        }
        uint32_t sA = sbase + (kt % 3) * STAGE_SZ;
        uint32_t sB = sA + 16384;
        #pragma unroll
        for (int ks = 0; ks < 4; ks++) {
            uint32_t af[4][4], bf[2][4];
            #pragma unroll
            for (int mi = 0; mi < 4; mi++) {
                int r = wm * 64 + mi * 16 + arow;
                int c = 2 * ks + acol;
                uint32_t addr = sA + r * 128 + ((c ^ (r & 7)) * 16);
                LDMX4(af[mi][0], af[mi][1], af[mi][2], af[mi][3], addr);
            }
            #pragma unroll
            for (int bi = 0; bi < 2; bi++) {
                int r = wn * 32 + bi * 16 + brow;
                int c = 2 * ks + bcol;
                uint32_t addr = sB + r * 128 + ((c ^ (r & 7)) * 16);
                LDMX4(bf[bi][0], bf[bi][1], bf[bi][2], bf[bi][3], addr);
            }
            #pragma unroll
            for (int mi = 0; mi < 4; mi++) {
                #pragma unroll
                for (int j = 0; j < 4; j++)
                    MMA8(acc[mi][j], af[mi], bf[j >> 1][(j & 1) * 2],
                         bf[j >> 1][(j & 1) * 2 + 1]);
            }
        }
    }

    #pragma unroll
    for (int mi = 0; mi < 4; mi++) {
        #pragma unroll
        for (int j = 0; j < 4; j++) {
            int row = bm * 128 + wm * 64 + mi * 16 + (lane >> 2);
            int col = bn * 128 + wn * 32 + j * 8 + (lane & 3) * 2;
            float bv0, bv1;
            if (bias_mode == 0) {
                bv0 = bias_a[col] + bias_b[col];
                bv1 = bias_a[col + 1] + bias_b[col + 1];
            } else {
                bv0 = (col < 1024) ? bias_a[col] : bias_b[col - 1024];
                bv1 = (col + 1 < 1024) ? bias_a[col + 1] : bias_b[col + 1 - 1024];
            }
            float2 v0 = {acc[mi][j][0] + bv0, acc[mi][j][1] + bv1};
            float2 v1 = {acc[mi][j][2] + bv0, acc[mi][j][3] + bv1};
            *(float2*)&C[(size_t)row * 2048 + col] = v0;
            *(float2*)&C[(size_t)(row + 8) * 2048 + col] = v1;
        }
    }
}

// ---------------- split-K skinny GEMM: P[s][M][64*NB] partials ---------------
// Block tile 64(M) x 64(N), BK=32, 256 threads (16x16, 4x4 each).
// NB = number of 64-col N blocks (grid.x = (M/64)*NB). bmode 1 = NN vs memory.
template <int DUAL>
__global__ __launch_bounds__(256) void gemm_skinny(
    const float* __restrict__ A1, const float* __restrict__ A1d,
    int lda1, int K1,
    const float* __restrict__ A2, int lda2, int K2,
    const float* __restrict__ Bw, int ldw, int bmode, int NB,
    float* __restrict__ P1, float* __restrict__ P2)
{
    __shared__ float As[64][36];
    __shared__ float Adm[DUAL ? 64 : 1][36];
    __shared__ float Bs[32][68];

    const int tid = threadIdx.x;
    const int bm  = (blockIdx.x / NB) * 64;
    const int bn  = (blockIdx.x % NB) * 64;
    const int ty  = tid >> 4, tx = tid & 15;

    const int total_tiles = (K1 + K2) >> 5;
    const int per = (total_tiles + SPLITK - 1) / SPLITK;
    const int t0 = blockIdx.y * per;
    int t1 = t0 + per; if (t1 > total_tiles) t1 = total_tiles;
    const int nt1 = K1 >> 5;

    float acc[4][4] = {};
    float accd[DUAL ? 4 : 1][4] = {};

    for (int t = t0; t < t1; t++) {
        const float* Ag; int lda, k0;
        if (t < nt1) { Ag = A1; lda = lda1; k0 = t << 5; }
        else         { Ag = A2; lda = lda2; k0 = (t - nt1) << 5; }

        {
            int row = tid >> 3;
            int c   = (tid & 7) * 4;
            #pragma unroll
            for (int rr = 0; rr < 64; rr += 32) {
                float4 v = *(const float4*)&Ag[(size_t)(bm + row + rr) * lda + k0 + c];
                *(float4*)&As[row + rr][c] = v;
                if (DUAL) {
                    float4 u = *(const float4*)&A1d[(size_t)(bm + row + rr) * lda + k0 + c];
                    *(float4*)&Adm[row + rr][c] = u;
                }
            }
        }
        if (bmode == 1) {   // NN: memory[K][64]
            int idx = tid;
            #pragma unroll
            for (int it = 0; it < 2; it++, idx += 256) {
                int kr = idx >> 4, nc = (idx & 15) * 4;
                float4 v = *(const float4*)&Bw[(size_t)((t << 5) + kr) * 64 + nc];
                *(float4*)&Bs[kr][nc] = v;
            }
        } else {            // NT: W[n][ldw], n block offset = bn
            int n = tid >> 3, c = (tid & 7) * 4;
            #pragma unroll
            for (int nn = 0; nn < 64; nn += 32) {
                float4 v = *(const float4*)&Bw[(size_t)(bn + n + nn) * ldw + (t << 5) + c];
                Bs[c + 0][n + nn] = v.x; Bs[c + 1][n + nn] = v.y;
                Bs[c + 2][n + nn] = v.z; Bs[c + 3][n + nn] = v.w;
            }
        }
        __syncthreads();
        #pragma unroll
        for (int kk = 0; kk < 32; kk++) {
            float b[4];
            *(float4*)b = *(const float4*)&Bs[kk][tx * 4];
            float a[4];
            #pragma unroll
            for (int i = 0; i < 4; i++) a[i] = As[ty * 4 + i][kk];
            #pragma unroll
            for (int i = 0; i < 4; i++)
                #pragma unroll
                for (int j = 0; j < 4; j++)
                    acc[i][j] += a[i] * b[j];
            if (DUAL) {
                float ad[4];
                #pragma unroll
                for (int i = 0; i < 4; i++) ad[i] = Adm[ty * 4 + i][kk];
                #pragma unroll
                for (int i = 0; i < 4; i++)
                    #pragma unroll
                    for (int j = 0; j < 4; j++)
                        accd[i][j] += ad[i] * b[j];
            }
        }
        __syncthreads();
    }

    const int pw = NB * 64;
    const size_t pbase = ((size_t)blockIdx.y * BATCH + bm) * pw + bn;
    #pragma unroll
    for (int i = 0; i < 4; i++) {
        *(float4*)&P1[pbase + (size_t)(ty * 4 + i) * pw + tx * 4] = *(float4*)acc[i];
        if (DUAL)
            *(float4*)&P2[pbase + (size_t)(ty * 4 + i) * pw + tx * 4] = *(float4*)accd[i];
    }
}

// ---------------- reduces ----------------------------------------------------
__global__ void reduce_act(const float* __restrict__ P,
                           const float* __restrict__ bias,
                           int act, int tf32r,
                           float* __restrict__ out, int ldc, int coloff)
{
    int idx = blockIdx.x * blockDim.x + threadIdx.x;   // BATCH*16
    int r = idx >> 4, c = (idx & 15) * 4;
    float4 s = {0.f, 0.f, 0.f, 0.f};
    #pragma unroll
    for (int k = 0; k < SPLITK; k++) {
        float4 v = *(const float4*)&P[((size_t)k * BATCH + r) * 64 + c];
        s.x += v.x; s.y += v.y; s.z += v.z; s.w += v.w;
    }
    float vv[4] = {s.x, s.y, s.z, s.w};
    #pragma unroll
    for (int q = 0; q < 4; q++) {
        float v = vv[q];
        if (bias) v += bias[c + q];
        if (act == 1) v = 1.0f / (1.0f + expf(-v));
        else if (act == 2) v = tanhf(v);
        if (tf32r) v = rna_tf32(v);
        vv[q] = v;
    }
    *(float4*)&out[(size_t)r * ldc + coloff + c] =
        make_float4(vv[0], vv[1], vv[2], vv[3]);
}

// Fused: erase=sigmoid(ΣPE[:, :64]+b_e), add=tanh(ΣPE[:, 64:]+b_a),
//        rn = ΣPA - erase*ΣPB + add*svec
__global__ void reduce_readnew(const float* __restrict__ PA,
                               const float* __restrict__ PB,
                               const float* __restrict__ PE,
                               const float* __restrict__ b_erase,
                               const float* __restrict__ b_add,
                               const float* __restrict__ svec,
                               float* __restrict__ rn)
{
    int idx = blockIdx.x * blockDim.x + threadIdx.x;   // BATCH*16
    int r = idx >> 4, c = (idx & 15) * 4;
    float4 s1 = {0.f, 0.f, 0.f, 0.f}, s2 = {0.f, 0.f, 0.f, 0.f};
    float4 se = {0.f, 0.f, 0.f, 0.f}, sa = {0.f, 0.f, 0.f, 0.f};
    #pragma unroll
    for (int k = 0; k < SPLITK; k++) {
        float4 v = *(const float4*)&PA[((size_t)k * BATCH + r) * 64 + c];
        float4 u = *(const float4*)&PB[((size_t)k * BATCH + r) * 64 + c];
        float4 e = *(const float4*)&PE[((size_t)k * BATCH + r) * 128 + c];
        float4 a = *(const float4*)&PE[((size_t)k * BATCH + r) * 128 + 64 + c];
        s1.x += v.x; s1.y += v.y; s1.z += v.z; s1.w += v.w;
        s2.x += u.x; s2.y += u.y; s2.z += u.z; s2.w += u.w;
        se.x += e.x; se.y += e.y; se.z += e.z; se.w += e.w;
        sa.x += a.x; sa.y += a.y; sa.z += a.z; sa.w += a.w;
    }
    float sv = svec[r];
    float ev[4] = {se.x, se.y, se.z, se.w};
    float av[4] = {sa.x, sa.y, sa.z, sa.w};
    float v1[4] = {s1.x, s1.y, s1.z, s1.w};
    float v2[4] = {s2.x, s2.y, s2.z, s2.w};
    float o[4];
    #pragma unroll
    for (int q = 0; q < 4; q++) {
        float e = 1.0f / (1.0f + expf(-(ev[q] + b_erase[c + q])));
        float a = tanhf(av[q] + b_add[c + q]);
        o[q] = v1[q] - e * v2[q] + a * sv;
    }
    *(float4*)&rn[(size_t)r * 64 + c] = make_float4(o[0], o[1], o[2], o[3]);
}

// ---------------- packs / elementwise / softmax -----------------------------
__global__ void pack_acat_kernel(const float* __restrict__ x,
                                 const float* __restrict__ h_prev,
                                 float* __restrict__ acat)
{
    int idx = blockIdx.x * blockDim.x + threadIdx.x;   // BATCH*576
    int b = idx / 576, c = idx % 576;
    float v = (c < 64) ? x[(size_t)b * 64 + c] : h_prev[(size_t)b * 512 + (c - 64)];
    int col = (c < 64) ? c : c + 64;
    acat[(size_t)b * KCAT + col] = rna_tf32(v);
}

__global__ void pack_wcat_kernel(const float* __restrict__ W_ih,
                                 const float* __restrict__ W_hh,
                                 float* __restrict__ wcat)
{
    int idx = blockIdx.x * blockDim.x + threadIdx.x;   // 2048*640
    int n = idx / KCAT, c = idx % KCAT;
    float v = (c < 128) ? W_ih[(size_t)n * 128 + c] : W_hh[(size_t)n * 512 + (c - 128)];
    wcat[idx] = rna_tf32(v);
}

__global__ void pack_wrw_kernel(const float* __restrict__ W_read,
                                const float* __restrict__ W_write,
                                float* __restrict__ wrw)
{
    int idx = blockIdx.x * blockDim.x + threadIdx.x;   // 2048*512
    int n = idx >> 9;
    float v = (n < 1024) ? W_read[idx] : W_write[idx - 1024 * 512];
    wrw[idx] = rna_tf32(v);
}

__global__ void pack_wea_kernel(const float* __restrict__ W_erase,
                                const float* __restrict__ W_add,
                                float* __restrict__ wea)
{
    int idx = blockIdx.x * blockDim.x + threadIdx.x;   // 128*512
    int n = idx >> 9;
    wea[idx] = (n < 64) ? W_erase[idx] : W_add[idx - 64 * 512];
}

__global__ void lstm_kernel(const float* __restrict__ gates,
                            const float* __restrict__ c_prev,
                            float* __restrict__ h,
                            float* __restrict__ ht32)
{
    int idx = blockIdx.x * blockDim.x + threadIdx.x;   // BATCH*128
    int b = idx >> 7, j = (idx & 127) * 4;
    const float* g = gates + (size_t)b * 2048;
    float4 gi = *(const float4*)&g[j];
    float4 gf = *(const float4*)&g[512 + j];
    float4 gg = *(const float4*)&g[1024 + j];
    float4 go = *(const float4*)&g[1536 + j];
    float4 cp = *(const float4*)&c_prev[(size_t)b * 512 + j];
    float hi[4];
    float I[4] = {gi.x, gi.y, gi.z, gi.w};
    float F[4] = {gf.x, gf.y, gf.z, gf.w};
    float G[4] = {gg.x, gg.y, gg.z, gg.w};
    float O[4] = {go.x, go.y, go.z, go.w};
    float C[4] = {cp.x, cp.y, cp.z, cp.w};
    #pragma unroll
    for (int q = 0; q < 4; q++) {
        float i = 1.0f / (1.0f + expf(-I[q]));
        float f = 1.0f / (1.0f + expf(-F[q]));
        float gv = tanhf(G[q]);
        float o = 1.0f / (1.0f + expf(-O[q]));
        float c = f * C[q] + i * gv;
        hi[q] = o * tanhf(c);
    }
    *(float4*)&h[(size_t)b * 512 + j] = make_float4(hi[0], hi[1], hi[2], hi[3]);
    *(float4*)&ht32[(size_t)b * 512 + j] =
        make_float4(rna_tf32(hi[0]), rna_tf32(hi[1]), rna_tf32(hi[2]), rna_tf32(hi[3]));
}

__device__ __forceinline__ float blk_reduce(float v, bool mx, float* sh)
{
    int lane = threadIdx.x & 31, wid = threadIdx.x >> 5;
    #pragma unroll
    for (int o = 16; o > 0; o >>= 1) {
        float t = __shfl_xor_sync(0xFFFFFFFFu, v, o);
        v = mx ? fmaxf(v, t) : (v + t);
    }
    if (lane == 0) sh[wid] = v;
    __syncthreads();
    if (wid == 0) {
        float r = (lane < 8) ? sh[lane] : (mx ? -1e30f : 0.f);
        #pragma unroll
        for (int o = 4; o > 0; o >>= 1) {
            float t = __shfl_xor_sync(0xFFFFFFFFu, r, o);
            r = mx ? fmaxf(r, t) : (r + t);
        }
        if (lane == 0) sh[0] = r;
    }
    __syncthreads();
    float r = sh[0];
    __syncthreads();
    return r;
}

__global__ void softmax_fuse_kernel(const float* __restrict__ logits,
                                    float* __restrict__ readw,
                                    float* __restrict__ rwprod,
                                    float* __restrict__ svec)
{
    __shared__ float sh[8];
    int b = blockIdx.x;
    int t = threadIdx.x;
    const float* r = logits + (size_t)b * 2048;
    const float* w = r + 1024;
    float vr[4], vw[4];
    float mr = -1e30f, mw = -1e30f;
    #pragma unroll
    for (int i = 0; i < 4; i++) {
        vr[i] = r[t + i * 256]; vw[i] = w[t + i * 256];
        mr = fmaxf(mr, vr[i]);  mw = fmaxf(mw, vw[i]);
    }
    mr = blk_reduce(mr, true, sh);
    mw = blk_reduce(mw, true, sh);
    float er[4], ew[4], sr = 0.f, sw = 0.f;
    #pragma unroll
    for (int i = 0; i < 4; i++) {
        er[i] = expf(vr[i] - mr); sr += er[i];
        ew[i] = expf(vw[i] - mw); sw += ew[i];
    }
    sr = blk_reduce(sr, false, sh);
    sw = blk_reduce(sw, false, sh);
    float inv_sr = 1.0f / sr, inv_sw = 1.0f / sw;
    float srw = 0.f;
    #pragma unroll
    for (int i = 0; i < 4; i++) {
        float a = er[i] * inv_sr;
        float p = a * (ew[i] * inv_sw);
        readw[(size_t)b * MEMN + t + i * 256] = a;
        rwprod[(size_t)b * MEMN + t + i * 256] = p;
        srw += p;
    }
    srw = blk_reduce(srw, false, sh);
    if (t == 0) svec[b] = srw;
}

// ---------------- launch ----------------------------------------------------
extern "C" void kernel_launch(void* const* d_in, const int* in_sizes, int n_in,
                              void* d_out, int out_size)
{
    const float* x       = (const float*)d_in[0];
    const float* h_prev  = (const float*)d_in[1];
    const float* c_prev  = (const float*)d_in[2];
    const float* rwp     = (const float*)d_in[3];
    const float* memory  = (const float*)d_in[4];
    const float* W_ih    = (const float*)d_in[5];
    const float* b_ih    = (const float*)d_in[6];
    const float* W_hh    = (const float*)d_in[7];
    const float* b_hh    = (const float*)d_in[8];
    const float* W_read  = (const float*)d_in[9];
    const float* b_read  = (const float*)d_in[10];
    const float* W_write = (const float*)d_in[11];
    const float* b_write = (const float*)d_in[12];
    const float* W_erase = (const float*)d_in[13];
    const float* b_erase = (const float*)d_in[14];
    const float* W_add   = (const float*)d_in[15];
    const float* b_add   = (const float*)d_in[16];
    const float* W_out   = (const float*)d_in[17];
    const float* b_out   = (const float*)d_in[18];
    float* out = (float*)d_out;

    float *acat, *wcat, *wrw, *wea, *gates, *logits, *h, *ht32;
    float *readw, *rw, *svec, *rn, *p1, *p2, *p3;
    cudaGetSymbolAddress((void**)&acat,   g_acat);
    cudaGetSymbolAddress((void**)&wcat,   g_wcat);
    cudaGetSymbolAddress((void**)&wrw,    g_wrw);
    cudaGetSymbolAddress((void**)&wea,    g_wea);
    cudaGetSymbolAddress((void**)&gates,  g_gates);
    cudaGetSymbolAddress((void**)&logits, g_logits);
    cudaGetSymbolAddress((void**)&h,      g_h);
    cudaGetSymbolAddress((void**)&ht32,   g_ht32);
    cudaGetSymbolAddress((void**)&readw,  g_readw);
    cudaGetSymbolAddress((void**)&rw,     g_rw);
    cudaGetSymbolAddress((void**)&svec,   g_s);
    cudaGetSymbolAddress((void**)&rn,     g_readnew);
    cudaGetSymbolAddress((void**)&p1,     g_p1);
    cudaGetSymbolAddress((void**)&p2,     g_p2);
    cudaGetSymbolAddress((void**)&p3,     g_p3);

    cudaFuncSetAttribute(mma_gemm, cudaFuncAttributeMaxDynamicSharedMemorySize,
                         SMEM_MMA);

    const dim3 skg1(BATCH / 64, SPLITK);        // N=64 grids
    const dim3 skg2((BATCH / 64) * 2, SPLITK);  // N=128 grid (erase|add)
    const int rgrid = (BATCH * 16) / 256;

    // 1) packs (tf32-round MMA operands; wea stays fp32)
    pack_wcat_kernel<<<(2048 * KCAT) / 256, 256>>>(W_ih, W_hh, wcat);
    pack_wrw_kernel<<<(2048 * CTRLN) / 256, 256>>>(W_read, W_write, wrw);
    pack_wea_kernel<<<(128 * CTRLN) / 256, 256>>>(W_erase, W_add, wea);
    pack_acat_kernel<<<(BATCH * 576) / 256, 256>>>(x, h_prev, acat);

    // 2) read_prev = read_weights_prev @ memory -> acat[:, 64:128) (rounded)
    gemm_skinny<0><<<skg1, 256>>>(rwp, nullptr, MEMN, MEMN,
                                  nullptr, 0, 0, memory, 0, 1, 1, p1, nullptr);
    reduce_act<<<rgrid, 256>>>(p1, nullptr, 0, 1, acat, KCAT, 64);

    // 3) gates = A_cat @ W_cat^T + b_ih + b_hh   [tf32 mma.sync]
    mma_gemm<<<dim3(16, 16), 256, SMEM_MMA>>>(
        acat, wcat, KCAT, b_ih, b_hh, 0, gates);

    // 4) LSTM cell -> h (fp32) + ht32 (rounded)
    lstm_kernel<<<(BATCH * 128) / 256, 256>>>(gates, c_prev, h, ht32);

    // 5) logits = h @ [W_read;W_write]^T + biases   [tf32 mma.sync]
    mma_gemm<<<dim3(16, 16), 256, SMEM_MMA>>>(
        ht32, wrw, CTRLN, b_read, b_write, 1, logits);

    // 6) softmaxes + read_w*write_w + row sums
    softmax_fuse_kernel<<<BATCH, 256>>>(logits, readw, rw, svec);

    // 7) erase|add partials = h @ [W_erase;W_add]^T  (fused N=128 GEMM)
    gemm_skinny<0><<<skg2, 256>>>(h, nullptr, CTRLN, CTRLN,
                                  nullptr, 0, 0, wea, CTRLN, 0, 2, p3, nullptr);

    // 8) dual partials: read_w@mem , (read_w*write_w)@mem
    gemm_skinny<1><<<skg1, 256>>>(readw, rw, MEMN, MEMN,
                                  nullptr, 0, 0, memory, 0, 1, 1, p1, p2);

    // 9) fused reduce: erase/add activation + readnew combine
    reduce_readnew<<<rgrid, 256>>>(p1, p2, p3, b_erase, b_add, svec, rn);

    // 10) out = [h | read_new] @ W_out^T + b_out
    gemm_skinny<0><<<skg1, 256>>>(h, nullptr, CTRLN, CTRLN,
                                  rn, VDIM, VDIM, W_out, CTRLN + VDIM, 0, 1,
                                  p1, nullptr);
    reduce_act<<<rgrid, 256>>>(p1, b_out, 0, 0, out, 64, 0);
}

// round 7
// speedup vs baseline: 3.6739x; 1.2139x over previous
#include <cuda_runtime.h>
#include <math.h>
#include <stdint.h>

#define BATCH 2048
#define CTRLN 512
#define MEMN  1024
#define VDIM  64
#define KCAT  640   // 64 x + 64 read_prev + 512 h_prev
#define SPLITK 8

// ---------------- scratch (device globals: allocation-free) ----------------
__device__ float g_acat[BATCH * KCAT];      // tf32-rounded [x|read_prev|h_prev]
__device__ float g_wcat[2048 * KCAT];       // tf32-rounded [W_ih|W_hh]
__device__ float g_wrw[2048 * CTRLN];       // tf32-rounded [W_read;W_write]
__device__ float g_wea[128 * CTRLN];        // tf32-rounded [W_erase;W_add]
__device__ float g_wout[64 * (CTRLN + 64)]; // tf32-rounded W_out
__device__ float g_memT[64 * MEMN];         // tf32-rounded memory^T  [v][m]
__device__ float g_gates[BATCH * 2048];
__device__ float g_logits[BATCH * 2048];
__device__ float g_h[BATCH * CTRLN];
__device__ float g_ht32[BATCH * CTRLN];     // tf32-rounded h
__device__ float g_readw[BATCH * MEMN];     // tf32-rounded
__device__ float g_rw[BATCH * MEMN];        // tf32-rounded
__device__ float g_s[BATCH];
__device__ float g_readnew[BATCH * VDIM];   // tf32-rounded
__device__ float g_p1[SPLITK * BATCH * VDIM];
__device__ float g_p2[SPLITK * BATCH * VDIM];
__device__ float g_p3[SPLITK * BATCH * 128];

// ---------------- helpers ----------------------------------------------------
__device__ __forceinline__ uint32_t smem_u32(const void* p) {
    uint32_t a;
    asm("{ .reg .u64 t; cvta.to.shared.u64 t, %1; cvt.u32.u64 %0, t; }"
        : "=r"(a) : "l"(p));
    return a;
}
__device__ __forceinline__ float rna_tf32(float x) {
    float r;
    asm("cvt.rna.tf32.f32 %0, %1;" : "=f"(r) : "f"(x));
    return r;
}
__device__ __forceinline__ float4 rna4(float4 v) {
    return make_float4(rna_tf32(v.x), rna_tf32(v.y), rna_tf32(v.z), rna_tf32(v.w));
}

#define CP_ASYNC16(s, g) \
    asm volatile("cp.async.cg.shared.global [%0], [%1], 16;" \
                 :: "r"(s), "l"(g) : "memory")
#define CP_COMMIT() asm volatile("cp.async.commit_group;" ::: "memory")
#define CP_WAIT1()  asm volatile("cp.async.wait_group 1;" ::: "memory")
#define CP_WAIT0()  asm volatile("cp.async.wait_group 0;" ::: "memory")

#define LDMX4(r0, r1, r2, r3, a) \
    asm volatile("ldmatrix.sync.aligned.m8n8.x4.shared.b16 {%0,%1,%2,%3}, [%4];" \
                 : "=r"(r0), "=r"(r1), "=r"(r2), "=r"(r3) : "r"(a))

#define MMA8(d, a, b0, b1) \
    asm volatile("mma.sync.aligned.m16n8k8.row.col.f32.tf32.tf32.f32 " \
        "{%0,%1,%2,%3}, {%4,%5,%6,%7}, {%8,%9}, {%0,%1,%2,%3};" \
        : "+f"((d)[0]), "+f"((d)[1]), "+f"((d)[2]), "+f"((d)[3]) \
        : "r"((a)[0]), "r"((a)[1]), "r"((a)[2]), "r"((a)[3]), "r"(b0), "r"(b1))

// ---------------- tf32 mma.sync GEMM: C[2048,2048] = A@W^T + bias ----------
#define STAGE_SZ 32768
#define SMEM_MMA (3 * STAGE_SZ)

__global__ __launch_bounds__(256, 2) void mma_gemm(
    const float* __restrict__ A, const float* __restrict__ W, int K,
    const float* __restrict__ bias_a, const float* __restrict__ bias_b,
    int bias_mode, float* __restrict__ C)
{
    extern __shared__ char smem[];
    const int tid  = threadIdx.x;
    const int lane = tid & 31, wid = tid >> 5;
    const int wm = wid >> 2, wn = wid & 3;
    const int bm = blockIdx.y, bn = blockIdx.x;
    const uint32_t sbase = smem_u32(smem);
    const int NT = K >> 5;

    float acc[4][4][4] = {};

    const int lrow = tid >> 1;
    const int lc0  = (tid & 1) * 4;
    const float* Ag = A + (size_t)(bm * 128 + lrow) * K;
    const float* Wg = W + (size_t)(bn * 128 + lrow) * K;
    uint32_t sw[4];
    #pragma unroll
    for (int i = 0; i < 4; i++)
        sw[i] = (uint32_t)lrow * 128 + (((lc0 + i) ^ (lrow & 7)) * 16);

    #pragma unroll
    for (int s = 0; s < 2; s++) {
        uint32_t sA = sbase + s * STAGE_SZ;
        uint32_t sB = sA + 16384;
        int k0 = s * 32;
        #pragma unroll
        for (int i = 0; i < 4; i++) {
            CP_ASYNC16(sA + sw[i], Ag + k0 + (lc0 + i) * 4);
            CP_ASYNC16(sB + sw[i], Wg + k0 + (lc0 + i) * 4);
        }
        CP_COMMIT();
    }

    const int arow = (lane & 15);
    const int acol = (lane >> 4);
    const int brow = (lane & 7) + ((lane >> 4) << 3);
    const int bcol = (lane >> 3) & 1;

    for (int kt = 0; kt < NT; kt++) {
        CP_WAIT1();
        __syncthreads();
        if (kt + 2 < NT) {
            int st = (kt + 2) % 3;
            uint32_t sA = sbase + st * STAGE_SZ;
            uint32_t sB = sA + 16384;
            int k0 = (kt + 2) * 32;
            #pragma unroll
            for (int i = 0; i < 4; i++) {
                CP_ASYNC16(sA + sw[i], Ag + k0 + (lc0 + i) * 4);
                CP_ASYNC16(sB + sw[i], Wg + k0 + (lc0 + i) * 4);
            }
            CP_COMMIT();
        }
        uint32_t sA = sbase + (kt % 3) * STAGE_SZ;
        uint32_t sB = sA + 16384;
        #pragma unroll
        for (int ks = 0; ks < 4; ks++) {
            uint32_t af[4][4], bf[2][4];
            #pragma unroll
            for (int mi = 0; mi < 4; mi++) {
                int r = wm * 64 + mi * 16 + arow;
                int c = 2 * ks + acol;
                uint32_t addr = sA + r * 128 + ((c ^ (r & 7)) * 16);
                LDMX4(af[mi][0], af[mi][1], af[mi][2], af[mi][3], addr);
            }
            #pragma unroll
            for (int bi = 0; bi < 2; bi++) {
                int r = wn * 32 + bi * 16 + brow;
                int c = 2 * ks + bcol;
                uint32_t addr = sB + r * 128 + ((c ^ (r & 7)) * 16);
                LDMX4(bf[bi][0], bf[bi][1], bf[bi][2], bf[bi][3], addr);
            }
            #pragma unroll
            for (int mi = 0; mi < 4; mi++) {
                #pragma unroll
                for (int j = 0; j < 4; j++)
                    MMA8(acc[mi][j], af[mi], bf[j >> 1][(j & 1) * 2],
                         bf[j >> 1][(j & 1) * 2 + 1]);
            }
        }
    }

    #pragma unroll
    for (int mi = 0; mi < 4; mi++) {
        #pragma unroll
        for (int j = 0; j < 4; j++) {
            int row = bm * 128 + wm * 64 + mi * 16 + (lane >> 2);
            int col = bn * 128 + wn * 32 + j * 8 + (lane & 3) * 2;
            float bv0, bv1;
            if (bias_mode == 0) {
                bv0 = bias_a[col] + bias_b[col];
                bv1 = bias_a[col + 1] + bias_b[col + 1];
            } else {
                bv0 = (col < 1024) ? bias_a[col] : bias_b[col - 1024];
                bv1 = (col + 1 < 1024) ? bias_a[col + 1] : bias_b[col + 1 - 1024];
            }
            float2 v0 = {acc[mi][j][0] + bv0, acc[mi][j][1] + bv1};
            float2 v1 = {acc[mi][j][2] + bv0, acc[mi][j][3] + bv1};
            *(float2*)&C[(size_t)row * 2048 + col] = v0;
            *(float2*)&C[(size_t)(row + 8) * 2048 + col] = v1;
        }
    }
}

// ---------------- tf32 mma skinny split-K: P[s][M][64*NB] partials ----------
// CTA tile 64(M) x 64(N), BK=32, 256 threads, 8 warps (4m x 2n, 16x32 each).
// A may be a row-concat of (A1,K1)+(A2,K2); B is one row-major [rows][K1+K2].
#define SKSTG(D) ((D) ? 24576 : 16384)

template <int DUAL>
__global__ __launch_bounds__(256) void mma_skinny(
    const float* __restrict__ A1, const float* __restrict__ A1d,
    int lda1, int K1,
    const float* __restrict__ A2, int lda2, int K2,
    const float* __restrict__ Bw, int ldw, int NB,
    float* __restrict__ P1, float* __restrict__ P2)
{
    extern __shared__ char smem[];
    const uint32_t sbase = smem_u32(smem);
    const int tid  = threadIdx.x;
    const int lane = tid & 31, wid = tid >> 5;
    const int wm = wid >> 1, wn = wid & 1;
    const int bmRow = (blockIdx.x / NB) * 64;
    const int bn    = (blockIdx.x % NB) * 64;

    const int total_tiles = (K1 + K2) >> 5;
    const int per = (total_tiles + SPLITK - 1) / SPLITK;
    const int t0 = blockIdx.y * per;
    int t1 = t0 + per; if (t1 > total_tiles) t1 = total_tiles;
    const int nt1 = K1 >> 5;

    float acc[4][4] = {};
    float accd[DUAL ? 4 : 1][4] = {};

    const int lrow = tid >> 2;           // 0..63
    const int lc0  = (tid & 3) * 2;      // chunks {0,2,4,6}
    uint32_t sw[2];
    #pragma unroll
    for (int i = 0; i < 2; i++)
        sw[i] = (uint32_t)lrow * 128 + (((lc0 + i) ^ (lrow & 7)) * 16);

    auto load_tile = [&](int t, int stg) {
        // A-phase offsets (k resets at the concat boundary)
        const float* Ag; const float* Agd = nullptr; int lda, kA;
        if (t < nt1) { Ag = A1; if (DUAL) Agd = A1d; lda = lda1; kA = t << 5; }
        else         { Ag = A2; lda = lda2; kA = (t - nt1) << 5; }
        const int kB = t << 5;   // B is continuous over the full K
        uint32_t sA  = sbase + stg * SKSTG(DUAL);
        uint32_t sAd = sA + 8192;
        uint32_t sB  = sA + (DUAL ? 16384 : 8192);
        const float* Arow = Ag + (size_t)(bmRow + lrow) * lda + kA;
        const float* Brow = Bw + (size_t)(bn + lrow) * ldw + kB;
        #pragma unroll
        for (int i = 0; i < 2; i++) {
            CP_ASYNC16(sA + sw[i], Arow + (lc0 + i) * 4);
            CP_ASYNC16(sB + sw[i], Brow + (lc0 + i) * 4);
            if (DUAL) {
                const float* Adrow = Agd + (size_t)(bmRow + lrow) * lda + kA;
                CP_ASYNC16(sAd + sw[i], Adrow + (lc0 + i) * 4);
            }
        }
        CP_COMMIT();
    };

    const int arow = (lane & 15);
    const int acol = (lane >> 4);
    const int brow = (lane & 7) + ((lane >> 4) << 3);
    const int bcol = (lane >> 3) & 1;

    if (t0 < t1) {
        load_tile(t0, t0 & 1);
        for (int t = t0; t < t1; t++) {
            if (t + 1 < t1) { load_tile(t + 1, (t + 1) & 1); CP_WAIT1(); }
            else            { CP_WAIT0(); }
            __syncthreads();
            uint32_t sA  = sbase + (t & 1) * SKSTG(DUAL);
            uint32_t sAd = sA + 8192;
            uint32_t sB  = sA + (DUAL ? 16384 : 8192);
            #pragma unroll
            for (int ks = 0; ks < 4; ks++) {
                uint32_t af[4], afd[4], bf[2][4];
                {
                    int r = wm * 16 + arow;
                    int c = 2 * ks + acol;
                    uint32_t addr = sA + r * 128 + ((c ^ (r & 7)) * 16);
                    LDMX4(af[0], af[1], af[2], af[3], addr);
                    if (DUAL) {
                        uint32_t addrd = sAd + r * 128 + ((c ^ (r & 7)) * 16);
                        LDMX4(afd[0], afd[1], afd[2], afd[3], addrd);
                    }
                }
                #pragma unroll
                for (int bi = 0; bi < 2; bi++) {
                    int r = wn * 32 + bi * 16 + brow;
                    int c = 2 * ks + bcol;
                    uint32_t addr = sB + r * 128 + ((c ^ (r & 7)) * 16);
                    LDMX4(bf[bi][0], bf[bi][1], bf[bi][2], bf[bi][3], addr);
                }
                #pragma unroll
                for (int j = 0; j < 4; j++) {
                    MMA8(acc[j], af, bf[j >> 1][(j & 1) * 2],
                         bf[j >> 1][(j & 1) * 2 + 1]);
                    if (DUAL)
                        MMA8(accd[j], afd, bf[j >> 1][(j & 1) * 2],
                             bf[j >> 1][(j & 1) * 2 + 1]);
                }
            }
            __syncthreads();
        }
    }

    const int pw = NB * 64;
    #pragma unroll
    for (int j = 0; j < 4; j++) {
        int row = bmRow + wm * 16 + (lane >> 2);
        int col = bn + wn * 32 + j * 8 + (lane & 3) * 2;
        size_t base = ((size_t)blockIdx.y * BATCH + row) * pw + col;
        *(float2*)&P1[base]          = make_float2(acc[j][0], acc[j][1]);
        *(float2*)&P1[base + 8 * pw] = make_float2(acc[j][2], acc[j][3]);
        if (DUAL) {
            *(float2*)&P2[base]          = make_float2(accd[j][0], accd[j][1]);
            *(float2*)&P2[base + 8 * pw] = make_float2(accd[j][2], accd[j][3]);
        }
    }
}

// ---------------- reduces ----------------------------------------------------
__global__ void reduce_act(const float* __restrict__ P,
                           const float* __restrict__ bias,
                           int act, int tf32r,
                           float* __restrict__ out, int ldc, int coloff)
{
    int idx = blockIdx.x * blockDim.x + threadIdx.x;   // BATCH*16
    int r = idx >> 4, c = (idx & 15) * 4;
    float4 s = {0.f, 0.f, 0.f, 0.f};
    #pragma unroll
    for (int k = 0; k < SPLITK; k++) {
        float4 v = *(const float4*)&P[((size_t)k * BATCH + r) * 64 + c];
        s.x += v.x; s.y += v.y; s.z += v.z; s.w += v.w;
    }
    float vv[4] = {s.x, s.y, s.z, s.w};
    #pragma unroll
    for (int q = 0; q < 4; q++) {
        float v = vv[q];
        if (bias) v += bias[c + q];
        if (act == 1) v = 1.0f / (1.0f + expf(-v));
        else if (act == 2) v = tanhf(v);
        if (tf32r) v = rna_tf32(v);
        vv[q] = v;
    }
    *(float4*)&out[(size_t)r * ldc + coloff + c] =
        make_float4(vv[0], vv[1], vv[2], vv[3]);
}

__global__ void reduce_readnew(const float* __restrict__ PA,
                               const float* __restrict__ PB,
                               const float* __restrict__ PE,
                               const float* __restrict__ b_erase,
                               const float* __restrict__ b_add,
                               const float* __restrict__ svec,
                               float* __restrict__ rn)
{
    int idx = blockIdx.x * blockDim.x + threadIdx.x;   // BATCH*16
    int r = idx >> 4, c = (idx & 15) * 4;
    float4 s1 = {0.f, 0.f, 0.f, 0.f}, s2 = {0.f, 0.f, 0.f, 0.f};
    float4 se = {0.f, 0.f, 0.f, 0.f}, sa = {0.f, 0.f, 0.f, 0.f};
    #pragma unroll
    for (int k = 0; k < SPLITK; k++) {
        float4 v = *(const float4*)&PA[((size_t)k * BATCH + r) * 64 + c];
        float4 u = *(const float4*)&PB[((size_t)k * BATCH + r) * 64 + c];
        float4 e = *(const float4*)&PE[((size_t)k * BATCH + r) * 128 + c];
        float4 a = *(const float4*)&PE[((size_t)k * BATCH + r) * 128 + 64 + c];
        s1.x += v.x; s1.y += v.y; s1.z += v.z; s1.w += v.w;
        s2.x += u.x; s2.y += u.y; s2.z += u.z; s2.w += u.w;
        se.x += e.x; se.y += e.y; se.z += e.z; se.w += e.w;
        sa.x += a.x; sa.y += a.y; sa.z += a.z; sa.w += a.w;
    }
    float sv = svec[r];
    float ev[4] = {se.x, se.y, se.z, se.w};
    float av[4] = {sa.x, sa.y, sa.z, sa.w};
    float v1[4] = {s1.x, s1.y, s1.z, s1.w};
    float v2[4] = {s2.x, s2.y, s2.z, s2.w};
    float o[4];
    #pragma unroll
    for (int q = 0; q < 4; q++) {
        float e = 1.0f / (1.0f + expf(-(ev[q] + b_erase[c + q])));
        float a = tanhf(av[q] + b_add[c + q]);
        o[q] = rna_tf32(v1[q] - e * v2[q] + a * sv);
    }
    *(float4*)&rn[(size_t)r * 64 + c] = make_float4(o[0], o[1], o[2], o[3]);
}

// ---------------- packs / elementwise / softmax -----------------------------
__global__ void pack_acat_kernel(const float* __restrict__ x,
                                 const float* __restrict__ h_prev,
                                 float* __restrict__ acat)
{
    int idx = blockIdx.x * blockDim.x + threadIdx.x;   // BATCH*144
    int b = idx / 144, q = idx % 144;
    float4 v;
    int col;
    if (q < 16) { v = *(const float4*)&x[(size_t)b * 64 + q * 4]; col = q * 4; }
    else { v = *(const float4*)&h_prev[(size_t)b * 512 + (q - 16) * 4];
           col = 128 + (q - 16) * 4; }
    *(float4*)&acat[(size_t)b * KCAT + col] = rna4(v);
}

__global__ void pack_wcat_kernel(const float* __restrict__ W_ih,
                                 const float* __restrict__ W_hh,
                                 float* __restrict__ wcat)
{
    int idx = blockIdx.x * blockDim.x + threadIdx.x;   // 2048*160
    int n = idx / 160, q = idx % 160;
    float4 v = (q < 32) ? *(const float4*)&W_ih[(size_t)n * 128 + q * 4]
                        : *(const float4*)&W_hh[(size_t)n * 512 + (q - 32) * 4];
    *(float4*)&wcat[(size_t)n * KCAT + q * 4] = rna4(v);
}

__global__ void pack_wrw_kernel(const float* __restrict__ W_read,
                                const float* __restrict__ W_write,
                                float* __restrict__ wrw)
{
    int idx = blockIdx.x * blockDim.x + threadIdx.x;   // 2048*128
    int n = idx >> 7, q = idx & 127;
    float4 v = (n < 1024)
        ? *(const float4*)&W_read[(size_t)n * 512 + q * 4]
        : *(const float4*)&W_write[(size_t)(n - 1024) * 512 + q * 4];
    *(float4*)&wrw[(size_t)n * 512 + q * 4] = rna4(v);
}

__global__ void pack_weao_kernel(const float* __restrict__ W_erase,
                                 const float* __restrict__ W_add,
                                 const float* __restrict__ W_out,
                                 float* __restrict__ wea,
                                 float* __restrict__ wout)
{
    int idx = blockIdx.x * blockDim.x + threadIdx.x;   // 25600 float4s
    if (idx < 16384) {
        int n = idx >> 7, q = idx & 127;
        float4 v = (n < 64)
            ? *(const float4*)&W_erase[(size_t)n * 512 + q * 4]
            : *(const float4*)&W_add[(size_t)(n - 64) * 512 + q * 4];
        *(float4*)&wea[(size_t)n * 512 + q * 4] = rna4(v);
    } else {
        int j = idx - 16384;              // 64*144
        if (j < 64 * 144) {
            float4 v = *(const float4*)&W_out[(size_t)j * 4];
            *(float4*)&wout[(size_t)j * 4] = rna4(v);
        }
    }
}

__global__ void memT_kernel(const float* __restrict__ mem,
                            float* __restrict__ memT)
{
    __shared__ float s[32][33];
    int k0 = blockIdx.x * 32, v0 = blockIdx.y * 32;
    int tx = threadIdx.x, ty = threadIdx.y;   // (32, 8)
    #pragma unroll
    for (int i = 0; i < 4; i++)
        s[ty + i * 8][tx] = mem[(size_t)(k0 + ty + i * 8) * 64 + v0 + tx];
    __syncthreads();
    #pragma unroll
    for (int i = 0; i < 4; i++)
        memT[(size_t)(v0 + ty + i * 8) * MEMN + k0 + tx] = rna_tf32(s[tx][ty + i * 8]);
}

__global__ void lstm_kernel(const float* __restrict__ gates,
                            const float* __restrict__ c_prev,
                            float* __restrict__ h,
                            float* __restrict__ ht32)
{
    int idx = blockIdx.x * blockDim.x + threadIdx.x;   // BATCH*128
    int b = idx >> 7, j = (idx & 127) * 4;
    const float* g = gates + (size_t)b * 2048;
    float4 gi = *(const float4*)&g[j];
    float4 gf = *(const float4*)&g[512 + j];
    float4 gg = *(const float4*)&g[1024 + j];
    float4 go = *(const float4*)&g[1536 + j];
    float4 cp = *(const float4*)&c_prev[(size_t)b * 512 + j];
    float hi[4];
    float I[4] = {gi.x, gi.y, gi.z, gi.w};
    float F[4] = {gf.x, gf.y, gf.z, gf.w};
    float G[4] = {gg.x, gg.y, gg.z, gg.w};
    float O[4] = {go.x, go.y, go.z, go.w};
    float C[4] = {cp.x, cp.y, cp.z, cp.w};
    #pragma unroll
    for (int q = 0; q < 4; q++) {
        float i = 1.0f / (1.0f + expf(-I[q]));
        float f = 1.0f / (1.0f + expf(-F[q]));
        float gv = tanhf(G[q]);
        float o = 1.0f / (1.0f + expf(-O[q]));
        float c = f * C[q] + i * gv;
        hi[q] = o * tanhf(c);
    }
    *(float4*)&h[(size_t)b * 512 + j] = make_float4(hi[0], hi[1], hi[2], hi[3]);
    *(float4*)&ht32[(size_t)b * 512 + j] =
        make_float4(rna_tf32(hi[0]), rna_tf32(hi[1]), rna_tf32(hi[2]), rna_tf32(hi[3]));
}

__device__ __forceinline__ float blk_reduce(float v, bool mx, float* sh)
{
    int lane = threadIdx.x & 31, wid = threadIdx.x >> 5;
    #pragma unroll
    for (int o = 16; o > 0; o >>= 1) {
        float t = __shfl_xor_sync(0xFFFFFFFFu, v, o);
        v = mx ? fmaxf(v, t) : (v + t);
    }
    if (lane == 0) sh[wid] = v;
    __syncthreads();
    if (wid == 0) {
        float r = (lane < 8) ? sh[lane] : (mx ? -1e30f : 0.f);
        #pragma unroll
        for (int o = 4; o > 0; o >>= 1) {
            float t = __shfl_xor_sync(0xFFFFFFFFu, r, o);
            r = mx ? fmaxf(r, t) : (r + t);
        }
        if (lane == 0) sh[0] = r;
    }
    __syncthreads();
    float r = sh[0];
    __syncthreads();
    return r;
}

__global__ void softmax_fuse_kernel(const float* __restrict__ logits,
                                    float* __restrict__ readw,
                                    float* __restrict__ rwprod,
                                    float* __restrict__ svec)
{
    __shared__ float sh[8];
    int b = blockIdx.x;
    int t = threadIdx.x;
    const float* r = logits + (size_t)b * 2048;
    const float* w = r + 1024;
    float vr[4], vw[4];
    float mr = -1e30f, mw = -1e30f;
    #pragma unroll
    for (int i = 0; i < 4; i++) {
        vr[i] = r[t + i * 256]; vw[i] = w[t + i * 256];
        mr = fmaxf(mr, vr[i]);  mw = fmaxf(mw, vw[i]);
    }
    mr = blk_reduce(mr, true, sh);
    mw = blk_reduce(mw, true, sh);
    float er[4], ew[4], sr = 0.f, sw = 0.f;
    #pragma unroll
    for (int i = 0; i < 4; i++) {
        er[i] = expf(vr[i] - mr); sr += er[i];
        ew[i] = expf(vw[i] - mw); sw += ew[i];
    }
    sr = blk_reduce(sr, false, sh);
    sw = blk_reduce(sw, false, sh);
    float inv_sr = 1.0f / sr, inv_sw = 1.0f / sw;
    float srw = 0.f;
    #pragma unroll
    for (int i = 0; i < 4; i++) {
        float a = er[i] * inv_sr;
        float p = a * (ew[i] * inv_sw);
        readw[(size_t)b * MEMN + t + i * 256] = rna_tf32(a);
        rwprod[(size_t)b * MEMN + t + i * 256] = rna_tf32(p);
        srw += p;
    }
    srw = blk_reduce(srw, false, sh);
    if (t == 0) svec[b] = srw;
}

// ---------------- launch ----------------------------------------------------
extern "C" void kernel_launch(void* const* d_in, const int* in_sizes, int n_in,
                              void* d_out, int out_size)
{
    const float* x       = (const float*)d_in[0];
    const float* h_prev  = (const float*)d_in[1];
    const float* c_prev  = (const float*)d_in[2];
    const float* rwp     = (const float*)d_in[3];
    const float* memory  = (const float*)d_in[4];
    const float* W_ih    = (const float*)d_in[5];
    const float* b_ih    = (const float*)d_in[6];
    const float* W_hh    = (const float*)d_in[7];
    const float* b_hh    = (const float*)d_in[8];
    const float* W_read  = (const float*)d_in[9];
    const float* b_read  = (const float*)d_in[10];
    const float* W_write = (const float*)d_in[11];
    const float* b_write = (const float*)d_in[12];
    const float* W_erase = (const float*)d_in[13];
    const float* b_erase = (const float*)d_in[14];
    const float* W_add   = (const float*)d_in[15];
    const float* b_add   = (const float*)d_in[16];
    const float* W_out   = (const float*)d_in[17];
    const float* b_out   = (const float*)d_in[18];
    float* out = (float*)d_out;

    float *acat, *wcat, *wrw, *wea, *wout, *memT, *gates, *logits, *h, *ht32;
    float *readw, *rw, *svec, *rn, *p1, *p2, *p3;
    cudaGetSymbolAddress((void**)&acat,   g_acat);
    cudaGetSymbolAddress((void**)&wcat,   g_wcat);
    cudaGetSymbolAddress((void**)&wrw,    g_wrw);
    cudaGetSymbolAddress((void**)&wea,    g_wea);
    cudaGetSymbolAddress((void**)&wout,   g_wout);
    cudaGetSymbolAddress((void**)&memT,   g_memT);
    cudaGetSymbolAddress((void**)&gates,  g_gates);
    cudaGetSymbolAddress((void**)&logits, g_logits);
    cudaGetSymbolAddress((void**)&h,      g_h);
    cudaGetSymbolAddress((void**)&ht32,   g_ht32);
    cudaGetSymbolAddress((void**)&readw,  g_readw);
    cudaGetSymbolAddress((void**)&rw,     g_rw);
    cudaGetSymbolAddress((void**)&svec,   g_s);
    cudaGetSymbolAddress((void**)&rn,     g_readnew);
    cudaGetSymbolAddress((void**)&p1,     g_p1);
    cudaGetSymbolAddress((void**)&p2,     g_p2);
    cudaGetSymbolAddress((void**)&p3,     g_p3);

    cudaFuncSetAttribute(mma_gemm, cudaFuncAttributeMaxDynamicSharedMemorySize,
                         SMEM_MMA);
    cudaFuncSetAttribute(mma_skinny<0>,
                         cudaFuncAttributeMaxDynamicSharedMemorySize, 2 * SKSTG(0));
    cudaFuncSetAttribute(mma_skinny<1>,
                         cudaFuncAttributeMaxDynamicSharedMemorySize, 2 * SKSTG(1));

    const int rgrid = (BATCH * 16) / 256;

    // 1) packs
    pack_wcat_kernel<<<(2048 * 160) / 256, 256>>>(W_ih, W_hh, wcat);
    pack_wrw_kernel<<<(2048 * 128) / 256, 256>>>(W_read, W_write, wrw);
    pack_weao_kernel<<<100, 256>>>(W_erase, W_add, W_out, wea, wout);
    memT_kernel<<<dim3(32, 2), dim3(32, 8)>>>(memory, memT);
    pack_acat_kernel<<<(BATCH * 144) / 256, 256>>>(x, h_prev, acat);

    // 2) read_prev = rwp @ memory = rwp @ memT^T  -> acat[:, 64:128)
    mma_skinny<0><<<dim3(BATCH / 64, SPLITK), 256, 2 * SKSTG(0)>>>(
        rwp, nullptr, MEMN, MEMN, nullptr, 0, 0, memT, MEMN, 1, p1, nullptr);
    reduce_act<<<rgrid, 256>>>(p1, nullptr, 0, 1, acat, KCAT, 64);

    // 3) gates = A_cat @ W_cat^T + b_ih + b_hh
    mma_gemm<<<dim3(16, 16), 256, SMEM_MMA>>>(
        acat, wcat, KCAT, b_ih, b_hh, 0, gates);

    // 4) LSTM cell
    lstm_kernel<<<(BATCH * 128) / 256, 256>>>(gates, c_prev, h, ht32);

    // 5) logits = h @ [W_read;W_write]^T
    mma_gemm<<<dim3(16, 16), 256, SMEM_MMA>>>(
        ht32, wrw, CTRLN, b_read, b_write, 1, logits);

    // 6) softmaxes (rounded outputs) + row sums
    softmax_fuse_kernel<<<BATCH, 256>>>(logits, readw, rw, svec);

    // 7) erase|add partials = h @ [W_erase;W_add]^T  (N=128)
    mma_skinny<0><<<dim3((BATCH / 64) * 2, SPLITK), 256, 2 * SKSTG(0)>>>(
        ht32, nullptr, CTRLN, CTRLN, nullptr, 0, 0, wea, CTRLN, 2, p3, nullptr);

    // 8) dual partials: readw@memT^T, rw@memT^T
    mma_skinny<1><<<dim3(BATCH / 64, SPLITK), 256, 2 * SKSTG(1)>>>(
        readw, rw, MEMN, MEMN, nullptr, 0, 0, memT, MEMN, 1, p1, p2);

    // 9) fused reduce -> rn (rounded)
    reduce_readnew<<<rgrid, 256>>>(p1, p2, p3, b_erase, b_add, svec, rn);

    // 10) out = [h | rn] @ W_out^T + b_out
    mma_skinny<0><<<dim3(BATCH / 64, SPLITK), 256, 2 * SKSTG(0)>>>(
        ht32, nullptr, CTRLN, CTRLN, rn, VDIM, VDIM, wout, CTRLN + VDIM, 1,
        p1, nullptr);
    reduce_act<<<rgrid, 256>>>(p1, b_out, 0, 0, out, 64, 0);
}

// round 8
// speedup vs baseline: 3.9202x; 1.0670x over previous
#include <cuda_runtime.h>
#include <math.h>
#include <stdint.h>

#define BATCH 2048
#define CTRLN 512
#define MEMN  1024
#define VDIM  64
#define KCAT  640   // 64 x + 64 read_prev + 512 h_prev
#define SPLITK 8

// ---------------- scratch (device globals: allocation-free) ----------------
__device__ float g_acat[BATCH * KCAT];      // tf32-rounded [x|read_prev|h_prev]
__device__ float g_wcat[2048 * KCAT];       // tf32-rounded, gate-interleaved [W_ih|W_hh]
__device__ float g_wrw[2048 * CTRLN];       // tf32-rounded [W_read;W_write]
__device__ float g_wea[128 * CTRLN];        // tf32-rounded [W_erase;W_add]
__device__ float g_wout[64 * (CTRLN + 64)]; // tf32-rounded W_out
__device__ float g_memT[64 * MEMN];         // tf32-rounded memory^T  [v][m]
__device__ float g_logits[BATCH * 2048];
__device__ float g_ht32[BATCH * CTRLN];     // tf32-rounded h
__device__ float g_readw[BATCH * MEMN];     // tf32-rounded
__device__ float g_rw[BATCH * MEMN];        // tf32-rounded
__device__ float g_s[BATCH];
__device__ float g_readnew[BATCH * VDIM];   // tf32-rounded
__device__ float g_p1[SPLITK * BATCH * VDIM];
__device__ float g_p2[SPLITK * BATCH * VDIM];
__device__ float g_p3[SPLITK * BATCH * 128];

// ---------------- helpers ----------------------------------------------------
__device__ __forceinline__ uint32_t smem_u32(const void* p) {
    uint32_t a;
    asm("{ .reg .u64 t; cvta.to.shared.u64 t, %1; cvt.u32.u64 %0, t; }"
        : "=r"(a) : "l"(p));
    return a;
}
__device__ __forceinline__ float rna_tf32(float x) {
    float r;
    asm("cvt.rna.tf32.f32 %0, %1;" : "=f"(r) : "f"(x));
    return r;
}
__device__ __forceinline__ float4 rna4(float4 v) {
    return make_float4(rna_tf32(v.x), rna_tf32(v.y), rna_tf32(v.z), rna_tf32(v.w));
}

#define CP_ASYNC16(s, g) \
    asm volatile("cp.async.cg.shared.global [%0], [%1], 16;" \
                 :: "r"(s), "l"(g) : "memory")
#define CP_COMMIT() asm volatile("cp.async.commit_group;" ::: "memory")
#define CP_WAIT1()  asm volatile("cp.async.wait_group 1;" ::: "memory")
#define CP_WAIT0()  asm volatile("cp.async.wait_group 0;" ::: "memory")

#define LDMX4(r0, r1, r2, r3, a) \
    asm volatile("ldmatrix.sync.aligned.m8n8.x4.shared.b16 {%0,%1,%2,%3}, [%4];" \
                 : "=r"(r0), "=r"(r1), "=r"(r2), "=r"(r3) : "r"(a))

#define MMA8(d, a, b0, b1) \
    asm volatile("mma.sync.aligned.m16n8k8.row.col.f32.tf32.tf32.f32 " \
        "{%0,%1,%2,%3}, {%4,%5,%6,%7}, {%8,%9}, {%0,%1,%2,%3};" \
        : "+f"((d)[0]), "+f"((d)[1]), "+f"((d)[2]), "+f"((d)[3]) \
        : "r"((a)[0]), "r"((a)[1]), "r"((a)[2]), "r"((a)[3]), "r"(b0), "r"(b1))

// ---------------- tf32 mma.sync GEMM core macros ----------------------------
#define STAGE_SZ 32768
#define SMEM_MMA (3 * STAGE_SZ)

// Shared mainloop for the two big GEMMs (128x128 CTA tile, BK=32, 3 stages).
// Defines acc[4][4][4] accumulated over K.
#define MMA_BIG_MAINLOOP(A, W, K)                                              \
    extern __shared__ char smem[];                                             \
    const int tid  = threadIdx.x;                                              \
    const int lane = tid & 31, wid = tid >> 5;                                 \
    const int wm = wid >> 2, wn = wid & 3;                                     \
    const int bm = blockIdx.y, bn = blockIdx.x;                                \
    const uint32_t sbase = smem_u32(smem);                                     \
    const int NT = (K) >> 5;                                                   \
    float acc[4][4][4] = {};                                                   \
    const int lrow = tid >> 1;                                                 \
    const int lc0  = (tid & 1) * 4;                                            \
    const float* Ag = (A) + (size_t)(bm * 128 + lrow) * (K);                   \
    const float* Wg = (W) + (size_t)(bn * 128 + lrow) * (K);                   \
    uint32_t sw[4];                                                            \
    _Pragma("unroll")                                                          \
    for (int i = 0; i < 4; i++)                                                \
        sw[i] = (uint32_t)lrow * 128 + (((lc0 + i) ^ (lrow & 7)) * 16);        \
    _Pragma("unroll")                                                          \
    for (int s = 0; s < 2; s++) {                                              \
        uint32_t sA = sbase + s * STAGE_SZ;                                    \
        uint32_t sB = sA + 16384;                                              \
        int k0 = s * 32;                                                       \
        _Pragma("unroll")                                                      \
        for (int i = 0; i < 4; i++) {                                          \
            CP_ASYNC16(sA + sw[i], Ag + k0 + (lc0 + i) * 4);                   \
            CP_ASYNC16(sB + sw[i], Wg + k0 + (lc0 + i) * 4);                   \
        }                                                                      \
        CP_COMMIT();                                                           \
    }                                                                          \
    const int arow = (lane & 15);                                              \
    const int acol = (lane >> 4);                                              \
    const int brow = (lane & 7) + ((lane >> 4) << 3);                          \
    const int bcol = (lane >> 3) & 1;                                          \
    for (int kt = 0; kt < NT; kt++) {                                          \
        CP_WAIT1();                                                            \
        __syncthreads();                                                       \
        if (kt + 2 < NT) {                                                     \
            int st = (kt + 2) % 3;                                             \
            uint32_t sA = sbase + st * STAGE_SZ;                               \
            uint32_t sB = sA + 16384;                                          \
            int k0 = (kt + 2) * 32;                                            \
            _Pragma("unroll")                                                  \
            for (int i = 0; i < 4; i++) {                                      \
                CP_ASYNC16(sA + sw[i], Ag + k0 + (lc0 + i) * 4);               \
                CP_ASYNC16(sB + sw[i], Wg + k0 + (lc0 + i) * 4);               \
            }                                                                  \
            CP_COMMIT();                                                       \
        }                                                                      \
        uint32_t sA = sbase + (kt % 3) * STAGE_SZ;                             \
        uint32_t sB = sA + 16384;                                              \
        _Pragma("unroll")                                                      \
        for (int ks = 0; ks < 4; ks++) {                                       \
            uint32_t af[4][4], bf[2][4];                                       \
            _Pragma("unroll")                                                  \
            for (int mi = 0; mi < 4; mi++) {                                   \
                int r = wm * 64 + mi * 16 + arow;                              \
                int c = 2 * ks + acol;                                         \
                uint32_t addr = sA + r * 128 + ((c ^ (r & 7)) * 16);           \
                LDMX4(af[mi][0], af[mi][1], af[mi][2], af[mi][3], addr);       \
            }                                                                  \
            _Pragma("unroll")                                                  \
            for (int bi = 0; bi < 2; bi++) {                                   \
                int r = wn * 32 + bi * 16 + brow;                              \
                int c = 2 * ks + bcol;                                         \
                uint32_t addr = sB + r * 128 + ((c ^ (r & 7)) * 16);           \
                LDMX4(bf[bi][0], bf[bi][1], bf[bi][2], bf[bi][3], addr);       \
            }                                                                  \
            _Pragma("unroll")                                                  \
            for (int mi = 0; mi < 4; mi++) {                                   \
                _Pragma("unroll")                                              \
                for (int j = 0; j < 4; j++)                                    \
                    MMA8(acc[mi][j], af[mi], bf[j >> 1][(j & 1) * 2],          \
                         bf[j >> 1][(j & 1) * 2 + 1]);                         \
            }                                                                  \
        }                                                                      \
    }

// ---------------- gates GEMM with fused LSTM epilogue ------------------------
// W rows gate-interleaved: packed row n -> orig ((n>>3)&3)*512 + (n>>5)*8 + (n&7)
// so each epilogue thread holds all 4 gates of its units. Writes ht32 directly.
__global__ __launch_bounds__(256, 2) void mma_gates(
    const float* __restrict__ A, const float* __restrict__ W, int K,
    const float* __restrict__ b_ih, const float* __restrict__ b_hh,
    const float* __restrict__ c_prev, float* __restrict__ ht)
{
    MMA_BIG_MAINLOOP(A, W, K)

    const int q = lane & 3;
    const int u0 = (bn * 4 + wn) * 8 + q * 2;
    float bsum[4][2];
    #pragma unroll
    for (int j = 0; j < 4; j++)
        #pragma unroll
        for (int uu = 0; uu < 2; uu++) {
            int orig = j * 512 + u0 + uu;
            bsum[j][uu] = b_ih[orig] + b_hh[orig];
        }
    #pragma unroll
    for (int mi = 0; mi < 4; mi++) {
        int r0 = bm * 128 + wm * 64 + mi * 16 + (lane >> 2);
        #pragma unroll
        for (int rr = 0; rr < 2; rr++) {
            int r = r0 + rr * 8;
            float2 cp = *(const float2*)&c_prev[(size_t)r * 512 + u0];
            float cc[2] = {cp.x, cp.y};
            float hv[2];
            #pragma unroll
            for (int uu = 0; uu < 2; uu++) {
                int k = rr * 2 + uu;
                float gi = acc[mi][0][k] + bsum[0][uu];
                float gf = acc[mi][1][k] + bsum[1][uu];
                float gg = acc[mi][2][k] + bsum[2][uu];
                float go = acc[mi][3][k] + bsum[3][uu];
                float iv = 1.0f / (1.0f + expf(-gi));
                float fv = 1.0f / (1.0f + expf(-gf));
                float gv = tanhf(gg);
                float ov = 1.0f / (1.0f + expf(-go));
                float c = fv * cc[uu] + iv * gv;
                hv[uu] = ov * tanhf(c);
            }
            *(float2*)&ht[(size_t)r * 512 + u0] =
                make_float2(rna_tf32(hv[0]), rna_tf32(hv[1]));
        }
    }
}

// ---------------- logits GEMM (plain epilogue, split bias) -------------------
__global__ __launch_bounds__(256, 2) void mma_logits(
    const float* __restrict__ A, const float* __restrict__ W, int K,
    const float* __restrict__ bias_a, const float* __restrict__ bias_b,
    float* __restrict__ C)
{
    MMA_BIG_MAINLOOP(A, W, K)

    #pragma unroll
    for (int mi = 0; mi < 4; mi++) {
        #pragma unroll
        for (int j = 0; j < 4; j++) {
            int row = bm * 128 + wm * 64 + mi * 16 + (lane >> 2);
            int col = bn * 128 + wn * 32 + j * 8 + (lane & 3) * 2;
            float bv0 = (col < 1024) ? bias_a[col] : bias_b[col - 1024];
            float bv1 = (col + 1 < 1024) ? bias_a[col + 1] : bias_b[col + 1 - 1024];
            float2 v0 = {acc[mi][j][0] + bv0, acc[mi][j][1] + bv1};
            float2 v1 = {acc[mi][j][2] + bv0, acc[mi][j][3] + bv1};
            *(float2*)&C[(size_t)row * 2048 + col] = v0;
            *(float2*)&C[(size_t)(row + 8) * 2048 + col] = v1;
        }
    }
}

// ---------------- tf32 mma skinny split-K (single/concat-A) -----------------
#define SKSTG0 16384

__global__ __launch_bounds__(256) void mma_skinny1(
    const float* __restrict__ A1, int lda1, int K1,
    const float* __restrict__ A2, int lda2, int K2,
    const float* __restrict__ Bw, int ldw, int NB,
    float* __restrict__ P1)
{
    extern __shared__ char smem[];
    const uint32_t sbase = smem_u32(smem);
    const int tid  = threadIdx.x;
    const int lane = tid & 31, wid = tid >> 5;
    const int wm = wid >> 1, wn = wid & 1;
    const int bmRow = (blockIdx.x / NB) * 64;
    const int bn    = (blockIdx.x % NB) * 64;

    const int total_tiles = (K1 + K2) >> 5;
    const int per = (total_tiles + SPLITK - 1) / SPLITK;
    const int t0 = blockIdx.y * per;
    int t1 = t0 + per; if (t1 > total_tiles) t1 = total_tiles;
    const int nt1 = K1 >> 5;

    float acc[4][4] = {};
    const int lrow = tid >> 2;
    const int lc0  = (tid & 3) * 2;
    uint32_t sw[2];
    #pragma unroll
    for (int i = 0; i < 2; i++)
        sw[i] = (uint32_t)lrow * 128 + (((lc0 + i) ^ (lrow & 7)) * 16);

    auto load_tile = [&](int t, int stg) {
        const float* Ag; int lda, kA;
        if (t < nt1) { Ag = A1; lda = lda1; kA = t << 5; }
        else         { Ag = A2; lda = lda2; kA = (t - nt1) << 5; }
        const int kB = t << 5;
        uint32_t sA = sbase + stg * SKSTG0;
        uint32_t sB = sA + 8192;
        const float* Arow = Ag + (size_t)(bmRow + lrow) * lda + kA;
        const float* Brow = Bw + (size_t)(bn + lrow) * ldw + kB;
        #pragma unroll
        for (int i = 0; i < 2; i++) {
            CP_ASYNC16(sA + sw[i], Arow + (lc0 + i) * 4);
            CP_ASYNC16(sB + sw[i], Brow + (lc0 + i) * 4);
        }
        CP_COMMIT();
    };

    const int arow = (lane & 15);
    const int acol = (lane >> 4);
    const int brow = (lane & 7) + ((lane >> 4) << 3);
    const int bcol = (lane >> 3) & 1;

    if (t0 < t1) {
        load_tile(t0, t0 & 1);
        for (int t = t0; t < t1; t++) {
            if (t + 1 < t1) { load_tile(t + 1, (t + 1) & 1); CP_WAIT1(); }
            else            { CP_WAIT0(); }
            __syncthreads();
            uint32_t sA = sbase + (t & 1) * SKSTG0;
            uint32_t sB = sA + 8192;
            #pragma unroll
            for (int ks = 0; ks < 4; ks++) {
                uint32_t af[4], bf[2][4];
                {
                    int r = wm * 16 + arow;
                    int c = 2 * ks + acol;
                    uint32_t addr = sA + r * 128 + ((c ^ (r & 7)) * 16);
                    LDMX4(af[0], af[1], af[2], af[3], addr);
                }
                #pragma unroll
                for (int bi = 0; bi < 2; bi++) {
                    int r = wn * 32 + bi * 16 + brow;
                    int c = 2 * ks + bcol;
                    uint32_t addr = sB + r * 128 + ((c ^ (r & 7)) * 16);
                    LDMX4(bf[bi][0], bf[bi][1], bf[bi][2], bf[bi][3], addr);
                }
                #pragma unroll
                for (int j = 0; j < 4; j++)
                    MMA8(acc[j], af, bf[j >> 1][(j & 1) * 2],
                         bf[j >> 1][(j & 1) * 2 + 1]);
            }
            __syncthreads();
        }
    }

    const int pw = NB * 64;
    #pragma unroll
    for (int j = 0; j < 4; j++) {
        int row = bmRow + wm * 16 + (lane >> 2);
        int col = bn + wn * 32 + j * 8 + (lane & 3) * 2;
        size_t base = ((size_t)blockIdx.y * BATCH + row) * pw + col;
        *(float2*)&P1[base]          = make_float2(acc[j][0], acc[j][1]);
        *(float2*)&P1[base + 8 * pw] = make_float2(acc[j][2], acc[j][3]);
    }
}

// ---------------- combined skinny: dual (readw,rw)@memT^T + ht32@wea^T ------
#define SKSTG1 24576

__global__ __launch_bounds__(256) void mma_skinny_comb(
    const float* __restrict__ readw, const float* __restrict__ rw,
    const float* __restrict__ memT,
    const float* __restrict__ ht32, const float* __restrict__ wea,
    float* __restrict__ P1, float* __restrict__ P2, float* __restrict__ P3)
{
    extern __shared__ char smem[];
    const uint32_t sbase = smem_u32(smem);
    const int tid  = threadIdx.x;
    const int lane = tid & 31, wid = tid >> 5;
    const int wm = wid >> 1, wn = wid & 1;

    const bool dualp = blockIdx.x < (BATCH / 64);
    const float *A1, *A1d = nullptr, *Bw;
    float *Pout1, *Pout2 = nullptr;
    int lda, K, ldw, NB, bxe;
    if (dualp) {
        A1 = readw; A1d = rw; lda = MEMN; K = MEMN;
        Bw = memT; ldw = MEMN; NB = 1; bxe = blockIdx.x;
        Pout1 = P1; Pout2 = P2;
    } else {
        A1 = ht32; lda = CTRLN; K = CTRLN;
        Bw = wea; ldw = CTRLN; NB = 2; bxe = blockIdx.x - BATCH / 64;
        Pout1 = P3;
    }
    const int bmRow = (bxe / NB) * 64;
    const int bn    = (bxe % NB) * 64;

    const int total_tiles = K >> 5;
    const int per = (total_tiles + SPLITK - 1) / SPLITK;
    const int t0 = blockIdx.y * per;
    int t1 = t0 + per; if (t1 > total_tiles) t1 = total_tiles;

    float acc[4][4] = {};
    float accd[4][4] = {};
    const int lrow = tid >> 2;
    const int lc0  = (tid & 3) * 2;
    uint32_t sw[2];
    #pragma unroll
    for (int i = 0; i < 2; i++)
        sw[i] = (uint32_t)lrow * 128 + (((lc0 + i) ^ (lrow & 7)) * 16);

    auto load_tile = [&](int t, int stg) {
        int k0 = t << 5;
        uint32_t sA  = sbase + stg * SKSTG1;
        uint32_t sAd = sA + 8192;
        uint32_t sB  = sA + 16384;
        const float* Arow = A1 + (size_t)(bmRow + lrow) * lda + k0;
        const float* Brow = Bw + (size_t)(bn + lrow) * ldw + k0;
        #pragma unroll
        for (int i = 0; i < 2; i++) {
            CP_ASYNC16(sA + sw[i], Arow + (lc0 + i) * 4);
            CP_ASYNC16(sB + sw[i], Brow + (lc0 + i) * 4);
            if (dualp) {
                const float* Adrow = A1d + (size_t)(bmRow + lrow) * lda + k0;
                CP_ASYNC16(sAd + sw[i], Adrow + (lc0 + i) * 4);
            }
        }
        CP_COMMIT();
    };

    const int arow = (lane & 15);
    const int acol = (lane >> 4);
    const int brow = (lane & 7) + ((lane >> 4) << 3);
    const int bcol = (lane >> 3) & 1;

    if (t0 < t1) {
        load_tile(t0, t0 & 1);
        for (int t = t0; t < t1; t++) {
            if (t + 1 < t1) { load_tile(t + 1, (t + 1) & 1); CP_WAIT1(); }
            else            { CP_WAIT0(); }
            __syncthreads();
            uint32_t sA  = sbase + (t & 1) * SKSTG1;
            uint32_t sAd = sA + 8192;
            uint32_t sB  = sA + 16384;
            #pragma unroll
            for (int ks = 0; ks < 4; ks++) {
                uint32_t af[4], afd[4], bf[2][4];
                {
                    int r = wm * 16 + arow;
                    int c = 2 * ks + acol;
                    uint32_t addr = sA + r * 128 + ((c ^ (r & 7)) * 16);
                    LDMX4(af[0], af[1], af[2], af[3], addr);
                    if (dualp) {
                        uint32_t addrd = sAd + r * 128 + ((c ^ (r & 7)) * 16);
                        LDMX4(afd[0], afd[1], afd[2], afd[3], addrd);
                    }
                }
                #pragma unroll
                for (int bi = 0; bi < 2; bi++) {
                    int r = wn * 32 + bi * 16 + brow;
                    int c = 2 * ks + bcol;
                    uint32_t addr = sB + r * 128 + ((c ^ (r & 7)) * 16);
                    LDMX4(bf[bi][0], bf[bi][1], bf[bi][2], bf[bi][3], addr);
                }
                #pragma unroll
                for (int j = 0; j < 4; j++) {
                    MMA8(acc[j], af, bf[j >> 1][(j & 1) * 2],
                         bf[j >> 1][(j & 1) * 2 + 1]);
                    if (dualp)
                        MMA8(accd[j], afd, bf[j >> 1][(j & 1) * 2],
                             bf[j >> 1][(j & 1) * 2 + 1]);
                }
            }
            __syncthreads();
        }
    }

    const int pw = NB * 64;
    #pragma unroll
    for (int j = 0; j < 4; j++) {
        int row = bmRow + wm * 16 + (lane >> 2);
        int col = bn + wn * 32 + j * 8 + (lane & 3) * 2;
        size_t base = ((size_t)blockIdx.y * BATCH + row) * pw + col;
        *(float2*)&Pout1[base]          = make_float2(acc[j][0], acc[j][1]);
        *(float2*)&Pout1[base + 8 * pw] = make_float2(acc[j][2], acc[j][3]);
        if (dualp) {
            *(float2*)&Pout2[base]          = make_float2(accd[j][0], accd[j][1]);
            *(float2*)&Pout2[base + 8 * pw] = make_float2(accd[j][2], accd[j][3]);
        }
    }
}

// ---------------- reduces ----------------------------------------------------
__global__ void reduce_act(const float* __restrict__ P,
                           const float* __restrict__ bias,
                           int act, int tf32r,
                           float* __restrict__ out, int ldc, int coloff)
{
    int idx = blockIdx.x * blockDim.x + threadIdx.x;   // BATCH*16
    int r = idx >> 4, c = (idx & 15) * 4;
    float4 s = {0.f, 0.f, 0.f, 0.f};
    #pragma unroll
    for (int k = 0; k < SPLITK; k++) {
        float4 v = *(const float4*)&P[((size_t)k * BATCH + r) * 64 + c];
        s.x += v.x; s.y += v.y; s.z += v.z; s.w += v.w;
    }
    float vv[4] = {s.x, s.y, s.z, s.w};
    #pragma unroll
    for (int q = 0; q < 4; q++) {
        float v = vv[q];
        if (bias) v += bias[c + q];
        if (act == 1) v = 1.0f / (1.0f + expf(-v));
        else if (act == 2) v = tanhf(v);
        if (tf32r) v = rna_tf32(v);
        vv[q] = v;
    }
    *(float4*)&out[(size_t)r * ldc + coloff + c] =
        make_float4(vv[0], vv[1], vv[2], vv[3]);
}

__global__ void reduce_readnew(const float* __restrict__ PA,
                               const float* __restrict__ PB,
                               const float* __restrict__ PE,
                               const float* __restrict__ b_erase,
                               const float* __restrict__ b_add,
                               const float* __restrict__ svec,
                               float* __restrict__ rn)
{
    int idx = blockIdx.x * blockDim.x + threadIdx.x;   // BATCH*16
    int r = idx >> 4, c = (idx & 15) * 4;
    float4 s1 = {0.f, 0.f, 0.f, 0.f}, s2 = {0.f, 0.f, 0.f, 0.f};
    float4 se = {0.f, 0.f, 0.f, 0.f}, sa = {0.f, 0.f, 0.f, 0.f};
    #pragma unroll
    for (int k = 0; k < SPLITK; k++) {
        float4 v = *(const float4*)&PA[((size_t)k * BATCH + r) * 64 + c];
        float4 u = *(const float4*)&PB[((size_t)k * BATCH + r) * 64 + c];
        float4 e = *(const float4*)&PE[((size_t)k * BATCH + r) * 128 + c];
        float4 a = *(const float4*)&PE[((size_t)k * BATCH + r) * 128 + 64 + c];
        s1.x += v.x; s1.y += v.y; s1.z += v.z; s1.w += v.w;
        s2.x += u.x; s2.y += u.y; s2.z += u.z; s2.w += u.w;
        se.x += e.x; se.y += e.y; se.z += e.z; se.w += e.w;
        sa.x += a.x; sa.y += a.y; sa.z += a.z; sa.w += a.w;
    }
    float sv = svec[r];
    float ev[4] = {se.x, se.y, se.z, se.w};
    float av[4] = {sa.x, sa.y, sa.z, sa.w};
    float v1[4] = {s1.x, s1.y, s1.z, s1.w};
    float v2[4] = {s2.x, s2.y, s2.z, s2.w};
    float o[4];
    #pragma unroll
    for (int q = 0; q < 4; q++) {
        float e = 1.0f / (1.0f + expf(-(ev[q] + b_erase[c + q])));
        float a = tanhf(av[q] + b_add[c + q]);
        o[q] = rna_tf32(v1[q] - e * v2[q] + a * sv);
    }
    *(float4*)&rn[(size_t)r * 64 + c] = make_float4(o[0], o[1], o[2], o[3]);
}

// ---------------- single merged pack kernel ----------------------------------
// seg0 wcat (gate-interleaved) | seg1 wrw | seg2 weao | seg3 acat | memT blocks
#define N_WCAT_F4  (2048 * 160)
#define N_WRW_F4   (2048 * 128)
#define N_WEAO_F4  25600
#define N_ACAT_F4  (BATCH * 144)
#define N_ELEM_BLK ((N_WCAT_F4 + N_WRW_F4 + N_WEAO_F4 + N_ACAT_F4) / 256)  // 3556
#define N_MEMT_BLK 64

__global__ void pack_all(const float* __restrict__ W_ih,
                         const float* __restrict__ W_hh,
                         const float* __restrict__ W_read,
                         const float* __restrict__ W_write,
                         const float* __restrict__ W_erase,
                         const float* __restrict__ W_add,
                         const float* __restrict__ W_out,
                         const float* __restrict__ x,
                         const float* __restrict__ h_prev,
                         const float* __restrict__ mem,
                         float* __restrict__ wcat, float* __restrict__ wrw,
                         float* __restrict__ wea, float* __restrict__ wout,
                         float* __restrict__ acat, float* __restrict__ memT)
{
    __shared__ float s[32][33];
    if (blockIdx.x >= N_ELEM_BLK) {     // memT transpose blocks
        int bxm = blockIdx.x - N_ELEM_BLK;
        int k0 = (bxm & 31) * 32, v0 = (bxm >> 5) * 32;
        int tx = threadIdx.x & 31, ty = threadIdx.x >> 5;   // 32 x 8
        #pragma unroll
        for (int i = 0; i < 4; i++)
            s[ty + i * 8][tx] = mem[(size_t)(k0 + ty + i * 8) * 64 + v0 + tx];
        __syncthreads();
        #pragma unroll
        for (int i = 0; i < 4; i++)
            memT[(size_t)(v0 + ty + i * 8) * MEMN + k0 + tx] =
                rna_tf32(s[tx][ty + i * 8]);
        return;
    }
    int idx = blockIdx.x * 256 + threadIdx.x;
    if (idx < N_WCAT_F4) {
        int n = idx / 160, q = idx % 160;
        int orig = ((n >> 3) & 3) * 512 + ((n >> 5) << 3) + (n & 7);
        float4 v = (q < 32)
            ? *(const float4*)&W_ih[(size_t)orig * 128 + q * 4]
            : *(const float4*)&W_hh[(size_t)orig * 512 + (q - 32) * 4];
        *(float4*)&wcat[(size_t)n * KCAT + q * 4] = rna4(v);
        return;
    }
    idx -= N_WCAT_F4;
    if (idx < N_WRW_F4) {
        int n = idx >> 7, q = idx & 127;
        float4 v = (n < 1024)
            ? *(const float4*)&W_read[(size_t)n * 512 + q * 4]
            : *(const float4*)&W_write[(size_t)(n - 1024) * 512 + q * 4];
        *(float4*)&wrw[(size_t)n * 512 + q * 4] = rna4(v);
        return;
    }
    idx -= N_WRW_F4;
    if (idx < N_WEAO_F4) {
        if (idx < 16384) {
            int n = idx >> 7, q = idx & 127;
            float4 v = (n < 64)
                ? *(const float4*)&W_erase[(size_t)n * 512 + q * 4]
                : *(const float4*)&W_add[(size_t)(n - 64) * 512 + q * 4];
            *(float4*)&wea[(size_t)n * 512 + q * 4] = rna4(v);
        } else {
            int j = idx - 16384;    // 64*144 = 9216
            float4 v = *(const float4*)&W_out[(size_t)j * 4];
            *(float4*)&wout[(size_t)j * 4] = rna4(v);
        }
        return;
    }
    idx -= N_WEAO_F4;
    {   // acat
        int b = idx / 144, q = idx % 144;
        float4 v; int col;
        if (q < 16) { v = *(const float4*)&x[(size_t)b * 64 + q * 4]; col = q * 4; }
        else { v = *(const float4*)&h_prev[(size_t)b * 512 + (q - 16) * 4];
               col = 128 + (q - 16) * 4; }
        *(float4*)&acat[(size_t)b * KCAT + col] = rna4(v);
    }
}

// ---------------- softmax -----------------------------------------------------
__device__ __forceinline__ float blk_reduce(float v, bool mx, float* sh)
{
    int lane = threadIdx.x & 31, wid = threadIdx.x >> 5;
    #pragma unroll
    for (int o = 16; o > 0; o >>= 1) {
        float t = __shfl_xor_sync(0xFFFFFFFFu, v, o);
        v = mx ? fmaxf(v, t) : (v + t);
    }
    if (lane == 0) sh[wid] = v;
    __syncthreads();
    if (wid == 0) {
        float r = (lane < 8) ? sh[lane] : (mx ? -1e30f : 0.f);
        #pragma unroll
        for (int o = 4; o > 0; o >>= 1) {
            float t = __shfl_xor_sync(0xFFFFFFFFu, r, o);
            r = mx ? fmaxf(r, t) : (r + t);
        }
        if (lane == 0) sh[0] = r;
    }
    __syncthreads();
    float r = sh[0];
    __syncthreads();
    return r;
}

__global__ void softmax_fuse_kernel(const float* __restrict__ logits,
                                    float* __restrict__ readw,
                                    float* __restrict__ rwprod,
                                    float* __restrict__ svec)
{
    __shared__ float sh[8];
    int b = blockIdx.x;
    int t = threadIdx.x;
    const float* r = logits + (size_t)b * 2048;
    const float* w = r + 1024;
    float vr[4], vw[4];
    float mr = -1e30f, mw = -1e30f;
    #pragma unroll
    for (int i = 0; i < 4; i++) {
        vr[i] = r[t + i * 256]; vw[i] = w[t + i * 256];
        mr = fmaxf(mr, vr[i]);  mw = fmaxf(mw, vw[i]);
    }
    mr = blk_reduce(mr, true, sh);
    mw = blk_reduce(mw, true, sh);
    float er[4], ew[4], sr = 0.f, sw = 0.f;
    #pragma unroll
    for (int i = 0; i < 4; i++) {
        er[i] = expf(vr[i] - mr); sr += er[i];
        ew[i] = expf(vw[i] - mw); sw += ew[i];
    }
    sr = blk_reduce(sr, false, sh);
    sw = blk_reduce(sw, false, sh);
    float inv_sr = 1.0f / sr, inv_sw = 1.0f / sw;
    float srw = 0.f;
    #pragma unroll
    for (int i = 0; i < 4; i++) {
        float a = er[i] * inv_sr;
        float p = a * (ew[i] * inv_sw);
        readw[(size_t)b * MEMN + t + i * 256] = rna_tf32(a);
        rwprod[(size_t)b * MEMN + t + i * 256] = rna_tf32(p);
        srw += p;
    }
    srw = blk_reduce(srw, false, sh);
    if (t == 0) svec[b] = srw;
}

// ---------------- launch ----------------------------------------------------
extern "C" void kernel_launch(void* const* d_in, const int* in_sizes, int n_in,
                              void* d_out, int out_size)
{
    const float* x       = (const float*)d_in[0];
    const float* h_prev  = (const float*)d_in[1];
    const float* c_prev  = (const float*)d_in[2];
    const float* rwp     = (const float*)d_in[3];
    const float* memory  = (const float*)d_in[4];
    const float* W_ih    = (const float*)d_in[5];
    const float* b_ih    = (const float*)d_in[6];
    const float* W_hh    = (const float*)d_in[7];
    const float* b_hh    = (const float*)d_in[8];
    const float* W_read  = (const float*)d_in[9];
    const float* b_read  = (const float*)d_in[10];
    const float* W_write = (const float*)d_in[11];
    const float* b_write = (const float*)d_in[12];
    const float* W_erase = (const float*)d_in[13];
    const float* b_erase = (const float*)d_in[14];
    const float* W_add   = (const float*)d_in[15];
    const float* b_add   = (const float*)d_in[16];
    const float* W_out   = (const float*)d_in[17];
    const float* b_out   = (const float*)d_in[18];
    float* out = (float*)d_out;

    float *acat, *wcat, *wrw, *wea, *wout, *memT, *logits, *ht32;
    float *readw, *rw, *svec, *rn, *p1, *p2, *p3;
    cudaGetSymbolAddress((void**)&acat,   g_acat);
    cudaGetSymbolAddress((void**)&wcat,   g_wcat);
    cudaGetSymbolAddress((void**)&wrw,    g_wrw);
    cudaGetSymbolAddress((void**)&wea,    g_wea);
    cudaGetSymbolAddress((void**)&wout,   g_wout);
    cudaGetSymbolAddress((void**)&memT,   g_memT);
    cudaGetSymbolAddress((void**)&logits, g_logits);
    cudaGetSymbolAddress((void**)&ht32,   g_ht32);
    cudaGetSymbolAddress((void**)&readw,  g_readw);
    cudaGetSymbolAddress((void**)&rw,     g_rw);
    cudaGetSymbolAddress((void**)&svec,   g_s);
    cudaGetSymbolAddress((void**)&rn,     g_readnew);
    cudaGetSymbolAddress((void**)&p1,     g_p1);
    cudaGetSymbolAddress((void**)&p2,     g_p2);
    cudaGetSymbolAddress((void**)&p3,     g_p3);

    cudaFuncSetAttribute(mma_gates, cudaFuncAttributeMaxDynamicSharedMemorySize,
                         SMEM_MMA);
    cudaFuncSetAttribute(mma_logits, cudaFuncAttributeMaxDynamicSharedMemorySize,
                         SMEM_MMA);
    cudaFuncSetAttribute(mma_skinny1,
                         cudaFuncAttributeMaxDynamicSharedMemorySize, 2 * SKSTG0);
    cudaFuncSetAttribute(mma_skinny_comb,
                         cudaFuncAttributeMaxDynamicSharedMemorySize, 2 * SKSTG1);

    const int rgrid = (BATCH * 16) / 256;

    // 1) all packs + memory transpose in ONE launch
    pack_all<<<N_ELEM_BLK + N_MEMT_BLK, 256>>>(
        W_ih, W_hh, W_read, W_write, W_erase, W_add, W_out,
        x, h_prev, memory,
        wcat, wrw, wea, wout, acat, memT);

    // 2) read_prev = rwp @ memT^T -> acat[:, 64:128)
    mma_skinny1<<<dim3(BATCH / 64, SPLITK), 256, 2 * SKSTG0>>>(
        rwp, MEMN, MEMN, nullptr, 0, 0, memT, MEMN, 1, p1);
    reduce_act<<<rgrid, 256>>>(p1, nullptr, 0, 1, acat, KCAT, 64);

    // 3) gates GEMM + fused LSTM -> ht32
    mma_gates<<<dim3(16, 16), 256, SMEM_MMA>>>(
        acat, wcat, KCAT, b_ih, b_hh, c_prev, ht32);

    // 4) logits = h @ [W_read;W_write]^T
    mma_logits<<<dim3(16, 16), 256, SMEM_MMA>>>(
        ht32, wrw, CTRLN, b_read, b_write, logits);

    // 5) softmaxes + row sums
    softmax_fuse_kernel<<<BATCH, 256>>>(logits, readw, rw, svec);

    // 6) combined skinny: dual (readw,rw)@memT^T + ht32@[W_erase;W_add]^T
    mma_skinny_comb<<<dim3(3 * (BATCH / 64), SPLITK), 256, 2 * SKSTG1>>>(
        readw, rw, memT, ht32, wea, p1, p2, p3);

    // 7) fused reduce -> rn
    reduce_readnew<<<rgrid, 256>>>(p1, p2, p3, b_erase, b_add, svec, rn);

    // 8) out = [h | rn] @ W_out^T + b_out
    mma_skinny1<<<dim3(BATCH / 64, SPLITK), 256, 2 * SKSTG0>>>(
        ht32, CTRLN, CTRLN, rn, VDIM, VDIM, wout, CTRLN + VDIM, 1, p1);
    reduce_act<<<rgrid, 256>>>(p1, b_out, 0, 0, out, 64, 0);
}

// round 9
// speedup vs baseline: 5.9507x; 1.5180x over previous
#include <cuda_runtime.h>
#include <cuda_fp16.h>
#include <math.h>
#include <stdint.h>

#define BATCH 2048
#define CTRLN 512
#define MEMN  1024
#define VDIM  64
#define KCAT  640
#define SPLITK 8

// ---------------- scratch (device globals: allocation-free) ----------------
__device__ __half g_acat[BATCH * KCAT];      // fp16 [x|read_prev|h_prev]
__device__ __half g_wcat[2048 * KCAT];       // fp16, gate-interleaved [W_ih|W_hh]
__device__ __half g_wrw[2048 * CTRLN];       // fp16 [W_read;W_write]
__device__ __half g_wea[128 * CTRLN];        // fp16 [W_erase;W_add]
__device__ __half g_wout[64 * (CTRLN + 64)]; // fp16 W_out
__device__ __half g_memT[64 * MEMN];         // fp16 memory^T [v][m]
__device__ __half g_rwph[BATCH * MEMN];      // fp16 read_weights_prev
__device__ float  g_logits[BATCH * 2048];
__device__ __half g_ht16[BATCH * CTRLN];     // fp16 h
__device__ __half g_readw[BATCH * MEMN];
__device__ __half g_rw[BATCH * MEMN];
__device__ float  g_s[BATCH];
__device__ __half g_readnew[BATCH * VDIM];
__device__ float  g_p1[SPLITK * BATCH * VDIM];
__device__ float  g_p2[SPLITK * BATCH * VDIM];
__device__ float  g_p3[SPLITK * BATCH * 128];

// ---------------- helpers ----------------------------------------------------
__device__ __forceinline__ uint32_t smem_u32(const void* p) {
    uint32_t a;
    asm("{ .reg .u64 t; cvta.to.shared.u64 t, %1; cvt.u32.u64 %0, t; }"
        : "=r"(a) : "l"(p));
    return a;
}
__device__ __forceinline__ uint2 h4(float4 v) {
    __half2 a = __floats2half2_rn(v.x, v.y);
    __half2 b = __floats2half2_rn(v.z, v.w);
    uint2 r;
    r.x = *(uint32_t*)&a;
    r.y = *(uint32_t*)&b;
    return r;
}

#define CP_ASYNC16(s, g) \
    asm volatile("cp.async.cg.shared.global [%0], [%1], 16;" \
                 :: "r"(s), "l"(g) : "memory")
#define CP_COMMIT() asm volatile("cp.async.commit_group;" ::: "memory")
#define CP_WAIT1()  asm volatile("cp.async.wait_group 1;" ::: "memory")
#define CP_WAIT0()  asm volatile("cp.async.wait_group 0;" ::: "memory")

#define LDMX4(r0, r1, r2, r3, a) \
    asm volatile("ldmatrix.sync.aligned.m8n8.x4.shared.b16 {%0,%1,%2,%3}, [%4];" \
                 : "=r"(r0), "=r"(r1), "=r"(r2), "=r"(r3) : "r"(a))

#define MMA16(d, a, b0, b1) \
    asm volatile("mma.sync.aligned.m16n8k16.row.col.f32.f16.f16.f32 " \
        "{%0,%1,%2,%3}, {%4,%5,%6,%7}, {%8,%9}, {%0,%1,%2,%3};" \
        : "+f"((d)[0]), "+f"((d)[1]), "+f"((d)[2]), "+f"((d)[3]) \
        : "r"((a)[0]), "r"((a)[1]), "r"((a)[2]), "r"((a)[3]), "r"(b0), "r"(b1))

// ---------------- fp16 mma.sync big GEMM core (128x128 CTA, BK=64 halves) ---
#define STAGE_SZ 32768
#define SMEM_MMA (3 * STAGE_SZ)

#define MMA_BIG_MAINLOOP(A, W, K)                                              \
    extern __shared__ char smem[];                                             \
    const int tid  = threadIdx.x;                                              \
    const int lane = tid & 31, wid = tid >> 5;                                 \
    const int wm = wid >> 2, wn = wid & 3;                                     \
    const int bm = blockIdx.y, bn = blockIdx.x;                                \
    const uint32_t sbase = smem_u32(smem);                                     \
    const int NT = (K) >> 6;                                                   \
    float acc[4][4][4] = {};                                                   \
    const int lrow = tid >> 1;                                                 \
    const int lc0  = (tid & 1) * 4;                                            \
    const __half* Ag = (A) + (size_t)(bm * 128 + lrow) * (K);                  \
    const __half* Wg = (W) + (size_t)(bn * 128 + lrow) * (K);                  \
    uint32_t sw[4];                                                            \
    _Pragma("unroll")                                                          \
    for (int i = 0; i < 4; i++)                                                \
        sw[i] = (uint32_t)lrow * 128 + (((lc0 + i) ^ (lrow & 7)) * 16);        \
    _Pragma("unroll")                                                          \
    for (int s = 0; s < 2; s++) {                                              \
        uint32_t sA = sbase + s * STAGE_SZ;                                    \
        uint32_t sB = sA + 16384;                                              \
        int k0 = s * 64;                                                       \
        _Pragma("unroll")                                                      \
        for (int i = 0; i < 4; i++) {                                          \
            CP_ASYNC16(sA + sw[i], Ag + k0 + (lc0 + i) * 8);                   \
            CP_ASYNC16(sB + sw[i], Wg + k0 + (lc0 + i) * 8);                   \
        }                                                                      \
        CP_COMMIT();                                                           \
    }                                                                          \
    const int arow = (lane & 15);                                              \
    const int acol = (lane >> 4);                                              \
    const int brow = (lane & 7) + ((lane >> 4) << 3);                          \
    const int bcol = (lane >> 3) & 1;                                          \
    for (int kt = 0; kt < NT; kt++) {                                          \
        CP_WAIT1();                                                            \
        __syncthreads();                                                       \
        if (kt + 2 < NT) {                                                     \
            int st = (kt + 2) % 3;                                             \
            uint32_t sA = sbase + st * STAGE_SZ;                               \
            uint32_t sB = sA + 16384;                                          \
            int k0 = (kt + 2) * 64;                                            \
            _Pragma("unroll")                                                  \
            for (int i = 0; i < 4; i++) {                                      \
                CP_ASYNC16(sA + sw[i], Ag + k0 + (lc0 + i) * 8);               \
                CP_ASYNC16(sB + sw[i], Wg + k0 + (lc0 + i) * 8);               \
            }                                                                  \
            CP_COMMIT();                                                       \
        }                                                                      \
        uint32_t sA = sbase + (kt % 3) * STAGE_SZ;                             \
        uint32_t sB = sA + 16384;                                              \
        _Pragma("unroll")                                                      \
        for (int ks = 0; ks < 4; ks++) {                                       \
            uint32_t af[4][4], bf[2][4];                                       \
            _Pragma("unroll")                                                  \
            for (int mi = 0; mi < 4; mi++) {                                   \
                int r = wm * 64 + mi * 16 + arow;                              \
                int c = 2 * ks + acol;                                         \
                uint32_t addr = sA + r * 128 + ((c ^ (r & 7)) * 16);           \
                LDMX4(af[mi][0], af[mi][1], af[mi][2], af[mi][3], addr);       \
            }                                                                  \
            _Pragma("unroll")                                                  \
            for (int bi = 0; bi < 2; bi++) {                                   \
                int r = wn * 32 + bi * 16 + brow;                              \
                int c = 2 * ks + bcol;                                         \
                uint32_t addr = sB + r * 128 + ((c ^ (r & 7)) * 16);           \
                LDMX4(bf[bi][0], bf[bi][1], bf[bi][2], bf[bi][3], addr);       \
            }                                                                  \
            _Pragma("unroll")                                                  \
            for (int mi = 0; mi < 4; mi++) {                                   \
                _Pragma("unroll")                                              \
                for (int j = 0; j < 4; j++)                                    \
                    MMA16(acc[mi][j], af[mi], bf[j >> 1][(j & 1) * 2],         \
                          bf[j >> 1][(j & 1) * 2 + 1]);                        \
            }                                                                  \
        }                                                                      \
    }

// ---------------- gates GEMM with fused LSTM epilogue ------------------------
__global__ __launch_bounds__(256, 2) void mma_gates(
    const __half* __restrict__ A, const __half* __restrict__ W, int K,
    const float* __restrict__ b_ih, const float* __restrict__ b_hh,
    const float* __restrict__ c_prev, __half* __restrict__ ht)
{
    MMA_BIG_MAINLOOP(A, W, K)

    const int q = lane & 3;
    const int u0 = (bn * 4 + wn) * 8 + q * 2;
    float bsum[4][2];
    #pragma unroll
    for (int j = 0; j < 4; j++)
        #pragma unroll
        for (int uu = 0; uu < 2; uu++) {
            int orig = j * 512 + u0 + uu;
            bsum[j][uu] = b_ih[orig] + b_hh[orig];
        }
    #pragma unroll
    for (int mi = 0; mi < 4; mi++) {
        int r0 = bm * 128 + wm * 64 + mi * 16 + (lane >> 2);
        #pragma unroll
        for (int rr = 0; rr < 2; rr++) {
            int r = r0 + rr * 8;
            float2 cp = *(const float2*)&c_prev[(size_t)r * 512 + u0];
            float cc[2] = {cp.x, cp.y};
            float hv[2];
            #pragma unroll
            for (int uu = 0; uu < 2; uu++) {
                int k = rr * 2 + uu;
                float gi = acc[mi][0][k] + bsum[0][uu];
                float gf = acc[mi][1][k] + bsum[1][uu];
                float gg = acc[mi][2][k] + bsum[2][uu];
                float go = acc[mi][3][k] + bsum[3][uu];
                float iv = 1.0f / (1.0f + expf(-gi));
                float fv = 1.0f / (1.0f + expf(-gf));
                float gv = tanhf(gg);
                float ov = 1.0f / (1.0f + expf(-go));
                float c = fv * cc[uu] + iv * gv;
                hv[uu] = ov * tanhf(c);
            }
            *(__half2*)&ht[(size_t)r * 512 + u0] = __floats2half2_rn(hv[0], hv[1]);
        }
    }
}

// ---------------- logits GEMM (plain epilogue, split bias) -------------------
__global__ __launch_bounds__(256, 2) void mma_logits(
    const __half* __restrict__ A, const __half* __restrict__ W, int K,
    const float* __restrict__ bias_a, const float* __restrict__ bias_b,
    float* __restrict__ C)
{
    MMA_BIG_MAINLOOP(A, W, K)

    #pragma unroll
    for (int mi = 0; mi < 4; mi++) {
        #pragma unroll
        for (int j = 0; j < 4; j++) {
            int row = bm * 128 + wm * 64 + mi * 16 + (lane >> 2);
            int col = bn * 128 + wn * 32 + j * 8 + (lane & 3) * 2;
            float bv0 = (col < 1024) ? bias_a[col] : bias_b[col - 1024];
            float bv1 = (col + 1 < 1024) ? bias_a[col + 1] : bias_b[col + 1 - 1024];
            float2 v0 = {acc[mi][j][0] + bv0, acc[mi][j][1] + bv1};
            float2 v1 = {acc[mi][j][2] + bv0, acc[mi][j][3] + bv1};
            *(float2*)&C[(size_t)row * 2048 + col] = v0;
            *(float2*)&C[(size_t)(row + 8) * 2048 + col] = v1;
        }
    }
}

// ---------------- fp16 mma skinny split-K (single/concat-A) -----------------
#define SKSTG0 16384

__global__ __launch_bounds__(256) void mma_skinny1(
    const __half* __restrict__ A1, int lda1, int K1,
    const __half* __restrict__ A2, int lda2, int K2,
    const __half* __restrict__ Bw, int ldw, int NB,
    float* __restrict__ P1)
{
    extern __shared__ char smem[];
    const uint32_t sbase = smem_u32(smem);
    const int tid  = threadIdx.x;
    const int lane = tid & 31, wid = tid >> 5;
    const int wm = wid >> 1, wn = wid & 1;
    const int bmRow = (blockIdx.x / NB) * 64;
    const int bn    = (blockIdx.x % NB) * 64;

    const int total_tiles = (K1 + K2) >> 6;
    const int per = (total_tiles + SPLITK - 1) / SPLITK;
    const int t0 = blockIdx.y * per;
    int t1 = t0 + per; if (t1 > total_tiles) t1 = total_tiles;
    const int nt1 = K1 >> 6;

    float acc[4][4] = {};
    const int lrow = tid >> 2;
    const int lc0  = (tid & 3) * 2;
    uint32_t sw[2];
    #pragma unroll
    for (int i = 0; i < 2; i++)
        sw[i] = (uint32_t)lrow * 128 + (((lc0 + i) ^ (lrow & 7)) * 16);

    auto load_tile = [&](int t, int stg) {
        const __half* Ag; int lda, kA;
        if (t < nt1) { Ag = A1; lda = lda1; kA = t << 6; }
        else         { Ag = A2; lda = lda2; kA = (t - nt1) << 6; }
        const int kB = t << 6;
        uint32_t sA = sbase + stg * SKSTG0;
        uint32_t sB = sA + 8192;
        const __half* Arow = Ag + (size_t)(bmRow + lrow) * lda + kA;
        const __half* Brow = Bw + (size_t)(bn + lrow) * ldw + kB;
        #pragma unroll
        for (int i = 0; i < 2; i++) {
            CP_ASYNC16(sA + sw[i], Arow + (lc0 + i) * 8);
            CP_ASYNC16(sB + sw[i], Brow + (lc0 + i) * 8);
        }
        CP_COMMIT();
    };

    const int arow = (lane & 15);
    const int acol = (lane >> 4);
    const int brow = (lane & 7) + ((lane >> 4) << 3);
    const int bcol = (lane >> 3) & 1;

    if (t0 < t1) {
        load_tile(t0, t0 & 1);
        for (int t = t0; t < t1; t++) {
            if (t + 1 < t1) { load_tile(t + 1, (t + 1) & 1); CP_WAIT1(); }
            else            { CP_WAIT0(); }
            __syncthreads();
            uint32_t sA = sbase + (t & 1) * SKSTG0;
            uint32_t sB = sA + 8192;
            #pragma unroll
            for (int ks = 0; ks < 4; ks++) {
                uint32_t af[4], bf[2][4];
                {
                    int r = wm * 16 + arow;
                    int c = 2 * ks + acol;
                    uint32_t addr = sA + r * 128 + ((c ^ (r & 7)) * 16);
                    LDMX4(af[0], af[1], af[2], af[3], addr);
                }
                #pragma unroll
                for (int bi = 0; bi < 2; bi++) {
                    int r = wn * 32 + bi * 16 + brow;
                    int c = 2 * ks + bcol;
                    uint32_t addr = sB + r * 128 + ((c ^ (r & 7)) * 16);
                    LDMX4(bf[bi][0], bf[bi][1], bf[bi][2], bf[bi][3], addr);
                }
                #pragma unroll
                for (int j = 0; j < 4; j++)
                    MMA16(acc[j], af, bf[j >> 1][(j & 1) * 2],
                          bf[j >> 1][(j & 1) * 2 + 1]);
            }
            __syncthreads();
        }
    }

    const int pw = NB * 64;
    #pragma unroll
    for (int j = 0; j < 4; j++) {
        int row = bmRow + wm * 16 + (lane >> 2);
        int col = bn + wn * 32 + j * 8 + (lane & 3) * 2;
        size_t base = ((size_t)blockIdx.y * BATCH + row) * pw + col;
        *(float2*)&P1[base]          = make_float2(acc[j][0], acc[j][1]);
        *(float2*)&P1[base + 8 * pw] = make_float2(acc[j][2], acc[j][3]);
    }
}

// ---------------- combined skinny: dual (readw,rw)@memT^T + ht@wea^T --------
#define SKSTG1 24576

__global__ __launch_bounds__(256) void mma_skinny_comb(
    const __half* __restrict__ readw, const __half* __restrict__ rw,
    const __half* __restrict__ memT,
    const __half* __restrict__ ht16, const __half* __restrict__ wea,
    float* __restrict__ P1, float* __restrict__ P2, float* __restrict__ P3)
{
    extern __shared__ char smem[];
    const uint32_t sbase = smem_u32(smem);
    const int tid  = threadIdx.x;
    const int lane = tid & 31, wid = tid >> 5;
    const int wm = wid >> 1, wn = wid & 1;

    const bool dualp = blockIdx.x < (BATCH / 64);
    const __half *A1, *A1d = nullptr, *Bw;
    float *Pout1, *Pout2 = nullptr;
    int lda, K, ldw, NB, bxe;
    if (dualp) {
        A1 = readw; A1d = rw; lda = MEMN; K = MEMN;
        Bw = memT; ldw = MEMN; NB = 1; bxe = blockIdx.x;
        Pout1 = P1; Pout2 = P2;
    } else {
        A1 = ht16; lda = CTRLN; K = CTRLN;
        Bw = wea; ldw = CTRLN; NB = 2; bxe = blockIdx.x - BATCH / 64;
        Pout1 = P3;
    }
    const int bmRow = (bxe / NB) * 64;
    const int bn    = (bxe % NB) * 64;

    const int total_tiles = K >> 6;
    const int per = (total_tiles + SPLITK - 1) / SPLITK;
    const int t0 = blockIdx.y * per;
    int t1 = t0 + per; if (t1 > total_tiles) t1 = total_tiles;

    float acc[4][4] = {};
    float accd[4][4] = {};
    const int lrow = tid >> 2;
    const int lc0  = (tid & 3) * 2;
    uint32_t sw[2];
    #pragma unroll
    for (int i = 0; i < 2; i++)
        sw[i] = (uint32_t)lrow * 128 + (((lc0 + i) ^ (lrow & 7)) * 16);

    auto load_tile = [&](int t, int stg) {
        int k0 = t << 6;
        uint32_t sA  = sbase + stg * SKSTG1;
        uint32_t sAd = sA + 8192;
        uint32_t sB  = sA + 16384;
        const __half* Arow = A1 + (size_t)(bmRow + lrow) * lda + k0;
        const __half* Brow = Bw + (size_t)(bn + lrow) * ldw + k0;
        #pragma unroll
        for (int i = 0; i < 2; i++) {
            CP_ASYNC16(sA + sw[i], Arow + (lc0 + i) * 8);
            CP_ASYNC16(sB + sw[i], Brow + (lc0 + i) * 8);
            if (dualp) {
                const __half* Adrow = A1d + (size_t)(bmRow + lrow) * lda + k0;
                CP_ASYNC16(sAd + sw[i], Adrow + (lc0 + i) * 8);
            }
        }
        CP_COMMIT();
    };

    const int arow = (lane & 15);
    const int acol = (lane >> 4);
    const int brow = (lane & 7) + ((lane >> 4) << 3);
    const int bcol = (lane >> 3) & 1;

    if (t0 < t1) {
        load_tile(t0, t0 & 1);
        for (int t = t0; t < t1; t++) {
            if (t + 1 < t1) { load_tile(t + 1, (t + 1) & 1); CP_WAIT1(); }
            else            { CP_WAIT0(); }
            __syncthreads();
            uint32_t sA  = sbase + (t & 1) * SKSTG1;
            uint32_t sAd = sA + 8192;
            uint32_t sB  = sA + 16384;
            #pragma unroll
            for (int ks = 0; ks < 4; ks++) {
                uint32_t af[4], afd[4], bf[2][4];
                {
                    int r = wm * 16 + arow;
                    int c = 2 * ks + acol;
                    uint32_t addr = sA + r * 128 + ((c ^ (r & 7)) * 16);
                    LDMX4(af[0], af[1], af[2], af[3], addr);
                    if (dualp) {
                        uint32_t addrd = sAd + r * 128 + ((c ^ (r & 7)) * 16);
                        LDMX4(afd[0], afd[1], afd[2], afd[3], addrd);
                    }
                }
                #pragma unroll
                for (int bi = 0; bi < 2; bi++) {
                    int r = wn * 32 + bi * 16 + brow;
                    int c = 2 * ks + bcol;
                    uint32_t addr = sB + r * 128 + ((c ^ (r & 7)) * 16);
                    LDMX4(bf[bi][0], bf[bi][1], bf[bi][2], bf[bi][3], addr);
                }
                #pragma unroll
                for (int j = 0; j < 4; j++) {
                    MMA16(acc[j], af, bf[j >> 1][(j & 1) * 2],
                          bf[j >> 1][(j & 1) * 2 + 1]);
                    if (dualp)
                        MMA16(accd[j], afd, bf[j >> 1][(j & 1) * 2],
                              bf[j >> 1][(j & 1) * 2 + 1]);
                }
            }
            __syncthreads();
        }
    }

    const int pw = NB * 64;
    #pragma unroll
    for (int j = 0; j < 4; j++) {
        int row = bmRow + wm * 16 + (lane >> 2);
        int col = bn + wn * 32 + j * 8 + (lane & 3) * 2;
        size_t base = ((size_t)blockIdx.y * BATCH + row) * pw + col;
        *(float2*)&Pout1[base]          = make_float2(acc[j][0], acc[j][1]);
        *(float2*)&Pout1[base + 8 * pw] = make_float2(acc[j][2], acc[j][3]);
        if (dualp) {
            *(float2*)&Pout2[base]          = make_float2(accd[j][0], accd[j][1]);
            *(float2*)&Pout2[base + 8 * pw] = make_float2(accd[j][2], accd[j][3]);
        }
    }
}

// ---------------- reduces ----------------------------------------------------
// mode 0: fp32 out ; mode 1: fp16 out (acat read_prev)
__global__ void reduce_act(const float* __restrict__ P,
                           const float* __restrict__ bias,
                           int mode,
                           float* __restrict__ outf, __half* __restrict__ outh,
                           int ldc, int coloff)
{
    int idx = blockIdx.x * blockDim.x + threadIdx.x;   // BATCH*16
    int r = idx >> 4, c = (idx & 15) * 4;
    float4 s = {0.f, 0.f, 0.f, 0.f};
    #pragma unroll
    for (int k = 0; k < SPLITK; k++) {
        float4 v = *(const float4*)&P[((size_t)k * BATCH + r) * 64 + c];
        s.x += v.x; s.y += v.y; s.z += v.z; s.w += v.w;
    }
    if (bias) {
        s.x += bias[c]; s.y += bias[c + 1]; s.z += bias[c + 2]; s.w += bias[c + 3];
    }
    if (mode == 0) {
        *(float4*)&outf[(size_t)r * ldc + coloff + c] = s;
    } else {
        *(uint2*)&outh[(size_t)r * ldc + coloff + c] = h4(s);
    }
}

__global__ void reduce_readnew(const float* __restrict__ PA,
                               const float* __restrict__ PB,
                               const float* __restrict__ PE,
                               const float* __restrict__ b_erase,
                               const float* __restrict__ b_add,
                               const float* __restrict__ svec,
                               __half* __restrict__ rn)
{
    int idx = blockIdx.x * blockDim.x + threadIdx.x;   // BATCH*16
    int r = idx >> 4, c = (idx & 15) * 4;
    float4 s1 = {0.f, 0.f, 0.f, 0.f}, s2 = {0.f, 0.f, 0.f, 0.f};
    float4 se = {0.f, 0.f, 0.f, 0.f}, sa = {0.f, 0.f, 0.f, 0.f};
    #pragma unroll
    for (int k = 0; k < SPLITK; k++) {
        float4 v = *(const float4*)&PA[((size_t)k * BATCH + r) * 64 + c];
        float4 u = *(const float4*)&PB[((size_t)k * BATCH + r) * 64 + c];
        float4 e = *(const float4*)&PE[((size_t)k * BATCH + r) * 128 + c];
        float4 a = *(const float4*)&PE[((size_t)k * BATCH + r) * 128 + 64 + c];
        s1.x += v.x; s1.y += v.y; s1.z += v.z; s1.w += v.w;
        s2.x += u.x; s2.y += u.y; s2.z += u.z; s2.w += u.w;
        se.x += e.x; se.y += e.y; se.z += e.z; se.w += e.w;
        sa.x += a.x; sa.y += a.y; sa.z += a.z; sa.w += a.w;
    }
    float sv = svec[r];
    float ev[4] = {se.x, se.y, se.z, se.w};
    float av[4] = {sa.x, sa.y, sa.z, sa.w};
    float v1[4] = {s1.x, s1.y, s1.z, s1.w};
    float v2[4] = {s2.x, s2.y, s2.z, s2.w};
    float4 o;
    float* op = &o.x;
    #pragma unroll
    for (int q = 0; q < 4; q++) {
        float e = 1.0f / (1.0f + expf(-(ev[q] + b_erase[c + q])));
        float a = tanhf(av[q] + b_add[c + q]);
        op[q] = v1[q] - e * v2[q] + a * sv;
    }
    *(uint2*)&rn[(size_t)r * 64 + c] = h4(o);
}

// ---------------- single merged pack kernel ----------------------------------
#define N_WCAT_F4  (2048 * 160)
#define N_WRW_F4   (2048 * 128)
#define N_WEAO_F4  25600
#define N_ACAT_F4  (BATCH * 144)
#define N_RWP_F4   (BATCH * 256)
#define N_ELEM_BLK ((N_WCAT_F4 + N_WRW_F4 + N_WEAO_F4 + N_ACAT_F4 + N_RWP_F4) / 256)
#define N_MEMT_BLK 64

__global__ void pack_all(const float* __restrict__ W_ih,
                         const float* __restrict__ W_hh,
                         const float* __restrict__ W_read,
                         const float* __restrict__ W_write,
                         const float* __restrict__ W_erase,
                         const float* __restrict__ W_add,
                         const float* __restrict__ W_out,
                         const float* __restrict__ x,
                         const float* __restrict__ h_prev,
                         const float* __restrict__ rwp,
                         const float* __restrict__ mem,
                         __half* __restrict__ wcat, __half* __restrict__ wrw,
                         __half* __restrict__ wea, __half* __restrict__ wout,
                         __half* __restrict__ acat, __half* __restrict__ rwph,
                         __half* __restrict__ memT)
{
    __shared__ float s[32][33];
    if (blockIdx.x >= N_ELEM_BLK) {     // memT transpose blocks
        int bxm = blockIdx.x - N_ELEM_BLK;
        int k0 = (bxm & 31) * 32, v0 = (bxm >> 5) * 32;
        int tx = threadIdx.x & 31, ty = threadIdx.x >> 5;   // 32 x 8
        #pragma unroll
        for (int i = 0; i < 4; i++)
            s[ty + i * 8][tx] = mem[(size_t)(k0 + ty + i * 8) * 64 + v0 + tx];
        __syncthreads();
        #pragma unroll
        for (int i = 0; i < 4; i++)
            memT[(size_t)(v0 + ty + i * 8) * MEMN + k0 + tx] =
                __float2half_rn(s[tx][ty + i * 8]);
        return;
    }
    int idx = blockIdx.x * 256 + threadIdx.x;
    if (idx < N_WCAT_F4) {
        int n = idx / 160, q = idx % 160;
        int orig = ((n >> 3) & 3) * 512 + ((n >> 5) << 3) + (n & 7);
        float4 v = (q < 32)
            ? *(const float4*)&W_ih[(size_t)orig * 128 + q * 4]
            : *(const float4*)&W_hh[(size_t)orig * 512 + (q - 32) * 4];
        *(uint2*)&wcat[(size_t)n * KCAT + q * 4] = h4(v);
        return;
    }
    idx -= N_WCAT_F4;
    if (idx < N_WRW_F4) {
        int n = idx >> 7, q = idx & 127;
        float4 v = (n < 1024)
            ? *(const float4*)&W_read[(size_t)n * 512 + q * 4]
            : *(const float4*)&W_write[(size_t)(n - 1024) * 512 + q * 4];
        *(uint2*)&wrw[(size_t)n * 512 + q * 4] = h4(v);
        return;
    }
    idx -= N_WRW_F4;
    if (idx < N_WEAO_F4) {
        if (idx < 16384) {
            int n = idx >> 7, q = idx & 127;
            float4 v = (n < 64)
                ? *(const float4*)&W_erase[(size_t)n * 512 + q * 4]
                : *(const float4*)&W_add[(size_t)(n - 64) * 512 + q * 4];
            *(uint2*)&wea[(size_t)n * 512 + q * 4] = h4(v);
        } else {
            int j = idx - 16384;    // 64*144 = 9216
            float4 v = *(const float4*)&W_out[(size_t)j * 4];
            *(uint2*)&wout[(size_t)j * 4] = h4(v);
        }
        return;
    }
    idx -= N_WEAO_F4;
    if (idx < N_ACAT_F4) {
        int b = idx / 144, q = idx % 144;
        float4 v; int col;
        if (q < 16) { v = *(const float4*)&x[(size_t)b * 64 + q * 4]; col = q * 4; }
        else { v = *(const float4*)&h_prev[(size_t)b * 512 + (q - 16) * 4];
               col = 128 + (q - 16) * 4; }
        *(uint2*)&acat[(size_t)b * KCAT + col] = h4(v);
        return;
    }
    idx -= N_ACAT_F4;
    {   // rwp -> fp16
        float4 v = *(const float4*)&rwp[(size_t)idx * 4];
        *(uint2*)&rwph[(size_t)idx * 4] = h4(v);
    }
}

// ---------------- softmax -----------------------------------------------------
__device__ __forceinline__ float blk_reduce(float v, bool mx, float* sh)
{
    int lane = threadIdx.x & 31, wid = threadIdx.x >> 5;
    #pragma unroll
    for (int o = 16; o > 0; o >>= 1) {
        float t = __shfl_xor_sync(0xFFFFFFFFu, v, o);
        v = mx ? fmaxf(v, t) : (v + t);
    }
    if (lane == 0) sh[wid] = v;
    __syncthreads();
    if (wid == 0) {
        float r = (lane < 8) ? sh[lane] : (mx ? -1e30f : 0.f);
        #pragma unroll
        for (int o = 4; o > 0; o >>= 1) {
            float t = __shfl_xor_sync(0xFFFFFFFFu, r, o);
            r = mx ? fmaxf(r, t) : (r + t);
        }
        if (lane == 0) sh[0] = r;
    }
    __syncthreads();
    float r = sh[0];
    __syncthreads();
    return r;
}

__global__ void softmax_fuse_kernel(const float* __restrict__ logits,
                                    __half* __restrict__ readw,
                                    __half* __restrict__ rwprod,
                                    float* __restrict__ svec)
{
    __shared__ float sh[8];
    int b = blockIdx.x;
    int t = threadIdx.x;
    const float* r = logits + (size_t)b * 2048;
    const float* w = r + 1024;
    float vr[4], vw[4];
    float mr = -1e30f, mw = -1e30f;
    #pragma unroll
    for (int i = 0; i < 4; i++) {
        vr[i] = r[t + i * 256]; vw[i] = w[t + i * 256];
        mr = fmaxf(mr, vr[i]);  mw = fmaxf(mw, vw[i]);
    }
    mr = blk_reduce(mr, true, sh);
    mw = blk_reduce(mw, true, sh);
    float er[4], ew[4], sr = 0.f, sw = 0.f;
    #pragma unroll
    for (int i = 0; i < 4; i++) {
        er[i] = expf(vr[i] - mr); sr += er[i];
        ew[i] = expf(vw[i] - mw); sw += ew[i];
    }
    sr = blk_reduce(sr, false, sh);
    sw = blk_reduce(sw, false, sh);
    float inv_sr = 1.0f / sr, inv_sw = 1.0f / sw;
    float srw = 0.f;
    #pragma unroll
    for (int i = 0; i < 4; i++) {
        float a = er[i] * inv_sr;
        float p = a * (ew[i] * inv_sw);
        readw[(size_t)b * MEMN + t + i * 256] = __float2half_rn(a);
        rwprod[(size_t)b * MEMN + t + i * 256] = __float2half_rn(p);
        srw += p;
    }
    srw = blk_reduce(srw, false, sh);
    if (t == 0) svec[b] = srw;
}

// ---------------- launch ----------------------------------------------------
extern "C" void kernel_launch(void* const* d_in, const int* in_sizes, int n_in,
                              void* d_out, int out_size)
{
    const float* x       = (const float*)d_in[0];
    const float* h_prev  = (const float*)d_in[1];
    const float* c_prev  = (const float*)d_in[2];
    const float* rwp     = (const float*)d_in[3];
    const float* memory  = (const float*)d_in[4];
    const float* W_ih    = (const float*)d_in[5];
    const float* b_ih    = (const float*)d_in[6];
    const float* W_hh    = (const float*)d_in[7];
    const float* b_hh    = (const float*)d_in[8];
    const float* W_read  = (const float*)d_in[9];
    const float* b_read  = (const float*)d_in[10];
    const float* W_write = (const float*)d_in[11];
    const float* b_write = (const float*)d_in[12];
    const float* W_erase = (const float*)d_in[13];
    const float* b_erase = (const float*)d_in[14];
    const float* W_add   = (const float*)d_in[15];
    const float* b_add   = (const float*)d_in[16];
    const float* W_out   = (const float*)d_in[17];
    const float* b_out   = (const float*)d_in[18];
    float* out = (float*)d_out;

    __half *acat, *wcat, *wrw, *wea, *wout, *memT, *rwph, *ht16, *readw, *rw, *rn;
    float *logits, *svec, *p1, *p2, *p3;
    cudaGetSymbolAddress((void**)&acat,   g_acat);
    cudaGetSymbolAddress((void**)&wcat,   g_wcat);
    cudaGetSymbolAddress((void**)&wrw,    g_wrw);
    cudaGetSymbolAddress((void**)&wea,    g_wea);
    cudaGetSymbolAddress((void**)&wout,   g_wout);
    cudaGetSymbolAddress((void**)&memT,   g_memT);
    cudaGetSymbolAddress((void**)&rwph,   g_rwph);
    cudaGetSymbolAddress((void**)&logits, g_logits);
    cudaGetSymbolAddress((void**)&ht16,   g_ht16);
    cudaGetSymbolAddress((void**)&readw,  g_readw);
    cudaGetSymbolAddress((void**)&rw,     g_rw);
    cudaGetSymbolAddress((void**)&svec,   g_s);
    cudaGetSymbolAddress((void**)&rn,     g_readnew);
    cudaGetSymbolAddress((void**)&p1,     g_p1);
    cudaGetSymbolAddress((void**)&p2,     g_p2);
    cudaGetSymbolAddress((void**)&p3,     g_p3);

    cudaFuncSetAttribute(mma_gates, cudaFuncAttributeMaxDynamicSharedMemorySize,
                         SMEM_MMA);
    cudaFuncSetAttribute(mma_logits, cudaFuncAttributeMaxDynamicSharedMemorySize,
                         SMEM_MMA);
    cudaFuncSetAttribute(mma_skinny1,
                         cudaFuncAttributeMaxDynamicSharedMemorySize, 2 * SKSTG0);
    cudaFuncSetAttribute(mma_skinny_comb,
                         cudaFuncAttributeMaxDynamicSharedMemorySize, 2 * SKSTG1);

    const int rgrid = (BATCH * 16) / 256;

    // 1) all packs + rwp fp16 + memory transpose in ONE launch
    pack_all<<<N_ELEM_BLK + N_MEMT_BLK, 256>>>(
        W_ih, W_hh, W_read, W_write, W_erase, W_add, W_out,
        x, h_prev, rwp, memory,
        wcat, wrw, wea, wout, acat, rwph, memT);

    // 2) read_prev = rwp @ memT^T -> acat[:, 64:128)
    mma_skinny1<<<dim3(BATCH / 64, SPLITK), 256, 2 * SKSTG0>>>(
        rwph, MEMN, MEMN, nullptr, 0, 0, memT, MEMN, 1, p1);
    reduce_act<<<rgrid, 256>>>(p1, nullptr, 1, nullptr, acat, KCAT, 64);

    // 3) gates GEMM + fused LSTM -> ht16
    mma_gates<<<dim3(16, 16), 256, SMEM_MMA>>>(
        acat, wcat, KCAT, b_ih, b_hh, c_prev, ht16);

    // 4) logits = h @ [W_read;W_write]^T
    mma_logits<<<dim3(16, 16), 256, SMEM_MMA>>>(
        ht16, wrw, CTRLN, b_read, b_write, logits);

    // 5) softmaxes + row sums
    softmax_fuse_kernel<<<BATCH, 256>>>(logits, readw, rw, svec);

    // 6) combined skinny: dual (readw,rw)@memT^T + ht@[W_erase;W_add]^T
    mma_skinny_comb<<<dim3(3 * (BATCH / 64), SPLITK), 256, 2 * SKSTG1>>>(
        readw, rw, memT, ht16, wea, p1, p2, p3);

    // 7) fused reduce -> rn (fp16)
    reduce_readnew<<<rgrid, 256>>>(p1, p2, p3, b_erase, b_add, svec, rn);

    // 8) out = [h | rn] @ W_out^T + b_out
    mma_skinny1<<<dim3(BATCH / 64, SPLITK), 256, 2 * SKSTG0>>>(
        ht16, CTRLN, CTRLN, rn, VDIM, VDIM, wout, CTRLN + VDIM, 1, p1);
    reduce_act<<<rgrid, 256>>>(p1, b_out, 0, out, nullptr, 64, 0);
}